// round 12
// baseline (speedup 1.0000x reference)
#include <cuda_runtime.h>
#include <cuda_bf16.h>
#include <math.h>
#include <float.h>

// ---------------------------------------------------------------------------
// Problem constants
// ---------------------------------------------------------------------------
#define NB       8
#define NPTS     8192
#define NC       64
#define GS       32
#define BGROUPS  512
#define GRID_PTS 36
#define FROWS    (BGROUPS*GRID_PTS)   // 18432
#define ENC_ROWS (NB*NPTS)            // 65536

typedef __nv_bfloat16 bf16;

// ---------------------------------------------------------------------------
// Scratch (device globals; no allocation anywhere)
// ---------------------------------------------------------------------------
__device__ bf16     g_h2b[ENC_ROWS*256];
__device__ bf16     g_posb[BGROUPS*1024];     // pos embedding (no feat)
__device__ bf16     g_w2t[256*128];
__device__ bf16     g_w3t[1024*256];
__device__ bf16     g_f1w1t[512*1024];
__device__ bf16     g_f2w1t[512*1024];
__device__ bf16     g_f1w2t[512*512];
__device__ bf16     g_f2w2t[512*512];

__device__ float    g_feA1[BGROUPS*512];
__device__ float    g_feA2[BGROUPS*512];
__device__ float    g_fw1a[NB*512];           // feat @ f1_w1
__device__ float    g_fw1b[NB*512];           // feat @ f2_w1
__device__ unsigned g_featkeys[NB*1024];
__device__ float    g_centers[BGROUPS*3];
__device__ float    g_neigh[BGROUPS*GS*3];
__device__ float    g_fold1[FROWS*3];
__device__ float    g_fold2[FROWS*3];
__device__ float    g_c1[NB*1024];
__device__ float    g_c2[NB*1024];
__device__ float    g_coarse[NB*192];
__device__ float    g_acc[4];

__constant__ float c_lin[6] = {-0.3f,-0.18f,-0.06f,0.06f,0.18f,0.3f};

// bf16 scratch ids
#define BID_H2     0
#define BID_POS    1
#define BID_W2T    2
#define BID_W3T    3
#define BID_F1W1T  4
#define BID_F2W1T  5
#define BID_F1W2T  6
#define BID_F2W2T  7

// f32 scratch ids
#define FID_FEA1   0
#define FID_FEA2   1
#define FID_C1     2
#define FID_C2     3
#define FID_COARSE 4
#define FID_FOLD1  5
#define FID_FOLD2  6

__device__ __forceinline__ bf16* scratch_bf16(int id) {
    switch (id) {
        case BID_H2:    return g_h2b;
        case BID_POS:   return g_posb;
        case BID_W2T:   return g_w2t;
        case BID_W3T:   return g_w3t;
        case BID_F1W1T: return g_f1w1t;
        case BID_F2W1T: return g_f2w1t;
        case BID_F1W2T: return g_f1w2t;
        default:        return g_f2w2t;
    }
}
__device__ __forceinline__ float* scratch_f32(int id) {
    switch (id) {
        case FID_FEA1:  return g_feA1;
        case FID_FEA2:  return g_feA2;
        case FID_C1:    return g_c1;
        case FID_C2:    return g_c2;
        case FID_COARSE:return g_coarse;
        case FID_FOLD1: return g_fold1;
        default:        return g_fold2;
    }
}

__device__ __forceinline__ unsigned fkey(float f) {
    unsigned u = __float_as_uint(f);
    return (u & 0x80000000u) ? ~u : (u | 0x80000000u);
}
__device__ __forceinline__ float unfkey(unsigned k) {
    return __uint_as_float((k & 0x80000000u) ? (k & 0x7fffffffu) : ~k);
}

__device__ __forceinline__ float gelu_exact(float x) {
    return 0.5f * x * (1.0f + erff(x * 0.7071067811865476f));
}

__device__ __forceinline__ void cpa16(unsigned dst, const void* src) {
    asm volatile("cp.async.cg.shared.global [%0], [%1], 16;" :: "r"(dst), "l"(src));
}

__device__ __forceinline__ void ldsm4(unsigned& r0, unsigned& r1, unsigned& r2,
                                      unsigned& r3, unsigned addr) {
    asm volatile("ldmatrix.sync.aligned.m8n8.x4.shared.b16 {%0,%1,%2,%3}, [%4];"
        : "=r"(r0), "=r"(r1), "=r"(r2), "=r"(r3) : "r"(addr));
}

__device__ __forceinline__ void mma_bf16(float* c, const unsigned* a, const unsigned* b) {
    asm volatile(
        "mma.sync.aligned.m16n8k16.row.col.f32.bf16.bf16.f32 "
        "{%0,%1,%2,%3}, {%4,%5,%6,%7}, {%8,%9}, {%0,%1,%2,%3};"
        : "+f"(c[0]), "+f"(c[1]), "+f"(c[2]), "+f"(c[3])
        : "r"(a[0]), "r"(a[1]), "r"(a[2]), "r"(a[3]), "r"(b[0]), "r"(b[1]));
}

__device__ __forceinline__ void wredmax(float& v, int& i) {
#pragma unroll
    for (int o = 16; o; o >>= 1) {
        float v2 = __shfl_xor_sync(0xffffffffu, v, o);
        int   i2 = __shfl_xor_sync(0xffffffffu, i, o);
        if (v2 > v || (v2 == v && i2 < i)) { v = v2; i = i2; }
    }
}
__device__ __forceinline__ void wredmin(float& v, int& i) {
#pragma unroll
    for (int o = 16; o; o >>= 1) {
        float v2 = __shfl_xor_sync(0xffffffffu, v, o);
        int   i2 = __shfl_xor_sync(0xffffffffu, i, o);
        if (v2 < v || (v2 == v && i2 < i)) { v = v2; i = i2; }
    }
}

// ---------------------------------------------------------------------------
// init: main (featkeys + acc) and fold accumulators (side stream)
// ---------------------------------------------------------------------------
__global__ void zero_main_kernel() {
    int i = blockIdx.x * 256 + threadIdx.x;
    if (i < NB*1024) g_featkeys[i] = 0u;
    if (i < 4)       g_acc[i] = 0.0f;
}
__global__ void zero_fold_kernel() {
    int i = blockIdx.x * 256 + threadIdx.x;
    if (i < FROWS*3) { g_fold1[i] = 0.0f; g_fold2[i] = 0.0f; }
}

// ---------------------------------------------------------------------------
// weight transposes (bf16)
// ---------------------------------------------------------------------------
__global__ void wtrans_enc(const float* __restrict__ w2, const float* __restrict__ w3) {
    const float* W; int K, N; bf16* out;
    if (blockIdx.y == 0) { W = w2; K = 128; N = 256;  out = g_w2t; }
    else                 { W = w3; K = 256; N = 1024; out = g_w3t; }
    int i = blockIdx.x * 256 + threadIdx.x;
    if (i < K * N) {
        int n = i / K, k = i - n * K;
        out[i] = __float2bfloat16(W[(size_t)k * N + n]);
    }
}

__global__ void wtrans_fold(const float* __restrict__ fw1a, const float* __restrict__ fw1b,
                            const float* __restrict__ fw2a, const float* __restrict__ fw2b)
{
    const float* W; int K, N; bf16* out;
    switch (blockIdx.y) {
        case 0: W = fw1a; K = 1024; N = 512; out = g_f1w1t; break;
        case 1: W = fw1b; K = 1024; N = 512; out = g_f2w1t; break;
        case 2: W = fw2a; K = 512;  N = 512; out = g_f1w2t; break;
        default:W = fw2b; K = 512;  N = 512; out = g_f2w2t; break;
    }
    int i = blockIdx.x * 256 + threadIdx.x;
    if (i < K * N) {
        int n = i / K, k = i - n * K;
        out[i] = __float2bfloat16(W[(size_t)k * N + n]);
    }
}

// ---------------------------------------------------------------------------
// Farthest point sampling
// ---------------------------------------------------------------------------
__global__ void __launch_bounds__(1024) fps_kernel(const float* __restrict__ pts) {
    int b = blockIdx.x, t = threadIdx.x;
    int lane = t & 31, wid = t >> 5;
    const float* P = pts + (size_t)b * NPTS * 3;
    __shared__ float sv[32];
    __shared__ int   si[32];
    __shared__ float cur[3];

    float px[8], py[8], pz[8], dd[8];
#pragma unroll
    for (int i = 0; i < 8; i++) {
        int p = (t << 3) + i;
        px[i] = P[p*3]; py[i] = P[p*3+1]; pz[i] = P[p*3+2];
    }
    if (t == 0) {
        cur[0] = P[0]; cur[1] = P[1]; cur[2] = P[2];
        g_centers[b*192+0] = P[0]; g_centers[b*192+1] = P[1]; g_centers[b*192+2] = P[2];
    }
    __syncthreads();
    float cx = cur[0], cy = cur[1], cz = cur[2];
#pragma unroll
    for (int i = 0; i < 8; i++) {
        float dx = px[i]-cx, dy = py[i]-cy, dz = pz[i]-cz;
        dd[i] = dx*dx + dy*dy + dz*dz;
    }
    for (int it = 1; it < NC; it++) {
        float bv = dd[0]; int bi = (t << 3);
#pragma unroll
        for (int i = 1; i < 8; i++)
            if (dd[i] > bv) { bv = dd[i]; bi = (t << 3) + i; }
        wredmax(bv, bi);
        if (lane == 0) { sv[wid] = bv; si[wid] = bi; }
        __syncthreads();
        if (wid == 0) {
            float v = sv[lane]; int i = si[lane];
            wredmax(v, i);
            if (lane == 0) {
                cur[0] = P[i*3]; cur[1] = P[i*3+1]; cur[2] = P[i*3+2];
                g_centers[b*192 + it*3+0] = cur[0];
                g_centers[b*192 + it*3+1] = cur[1];
                g_centers[b*192 + it*3+2] = cur[2];
            }
        }
        __syncthreads();
        cx = cur[0]; cy = cur[1]; cz = cur[2];
#pragma unroll
        for (int i = 0; i < 8; i++) {
            float dx = px[i]-cx, dy = py[i]-cy, dz = pz[i]-cz;
            dd[i] = fminf(dd[i], dx*dx + dy*dy + dz*dz);
        }
    }
}

// ---------------------------------------------------------------------------
// 32-NN grouping — incremental argmin
// ---------------------------------------------------------------------------
__global__ void __launch_bounds__(256) knn_kernel(const float* __restrict__ pts) {
    int bg = blockIdx.x, b = bg >> 6, t = threadIdx.x;
    int lane = t & 31, wid = t >> 5;
    const float* P = pts + (size_t)b * NPTS * 3;
    __shared__ float sd[NPTS];
    __shared__ float sv[8];
    __shared__ int   si[8];
    __shared__ int   swin;
    float cx = g_centers[bg*3], cy = g_centers[bg*3+1], cz = g_centers[bg*3+2];
    for (int p = t; p < NPTS; p += 256) {
        float dx = P[p*3]-cx, dy = P[p*3+1]-cy, dz = P[p*3+2]-cz;
        sd[p] = dx*dx + dy*dy + dz*dz;
    }
    __syncthreads();

    const int base = t << 5;
    float mv = FLT_MAX; int mi = base;
#pragma unroll 8
    for (int j = 0; j < 32; j++) {
        float v = sd[base + j];
        if (v < mv) { mv = v; mi = base + j; }
    }

    for (int k = 0; k < GS; k++) {
        float bv = mv; int bi = mi;
        wredmin(bv, bi);
        if (lane == 0) { sv[wid] = bv; si[wid] = bi; }
        __syncthreads();
        if (t < 32) {
            float v = (lane < 8) ? sv[lane] : FLT_MAX;
            int   i = (lane < 8) ? si[lane] : NPTS;
            wredmin(v, i);
            if (lane == 0) {
                swin = i;
                g_neigh[(bg*GS+k)*3+0] = P[i*3+0] - cx;
                g_neigh[(bg*GS+k)*3+1] = P[i*3+1] - cy;
                g_neigh[(bg*GS+k)*3+2] = P[i*3+2] - cz;
            }
        }
        __syncthreads();
        int win = swin;
        if ((win >> 5) == t) {
            sd[win] = FLT_MAX;
            mv = FLT_MAX; mi = base;
#pragma unroll 8
            for (int j = 0; j < 32; j++) {
                float v = sd[base + j];
                if (v < mv) { mv = v; mi = base + j; }
            }
        }
        __syncthreads();
    }
}

// ---------------------------------------------------------------------------
// Fused enc layer1 + layer2 GEMM
// ---------------------------------------------------------------------------
#define SA 24
#define SB 136

__global__ void __launch_bounds__(256) enc12_kernel(
    const float* __restrict__ x, const float* __restrict__ w1,
    const float* __restrict__ b1, const float* __restrict__ b2)
{
    __shared__ __align__(16) bf16 Bs[128*SB];
    __shared__ __align__(16) bf16 As[128*SA];
    __shared__ float  sx[384];
    __shared__ float4 swc[128];

    const int tid = threadIdx.x, lane = tid & 31, wid = tid >> 5;
    const int wm = wid & 3, wn = wid >> 2;
    const int br = blockIdx.y, bc = blockIdx.x;

    const bf16* B = g_w2t + (size_t)(bc * 128) * 128;
    const unsigned bBase = (unsigned)__cvta_generic_to_shared(&Bs[0]);
    const unsigned aBase = (unsigned)__cvta_generic_to_shared(&As[0]);

#pragma unroll
    for (int i = 0; i < 8; i++) {
        int chunk = i * 256 + tid;
        int row = chunk >> 4, seg = chunk & 15;
        cpa16(bBase + (row*SB + seg*8)*2, B + row*128 + seg*8);
    }
    asm volatile("cp.async.commit_group;");

    if (tid < 96) *(float4*)&sx[tid*4] = *(const float4*)(x + (size_t)br*384 + tid*4);
    if (tid < 128) {
        float4 w; w.x = w1[tid]; w.y = w1[128+tid]; w.z = w1[256+tid]; w.w = b1[tid];
        swc[tid] = w;
    }
    asm volatile("cp.async.wait_group 0;");
    __syncthreads();

    float acc[2][8][4];
#pragma unroll
    for (int mt = 0; mt < 2; mt++)
#pragma unroll
        for (int nt = 0; nt < 8; nt++)
#pragma unroll
            for (int j = 0; j < 4; j++) acc[mt][nt][j] = 0.0f;

    unsigned aoff[2], boff[4];
#pragma unroll
    for (int mt = 0; mt < 2; mt++)
        aoff[mt] = ((wm*32 + mt*16 + (lane & 15)) * SA + ((lane >> 4) << 3)) * 2;
#pragma unroll
    for (int ntp = 0; ntp < 4; ntp++)
        boff[ntp] = ((wn*64 + ntp*16 + ((lane & 16) >> 1) + (lane & 7)) * SB
                     + (lane & 8)) * 2;

    const int r = tid >> 1;
    const float x0 = sx[r*3], x1 = sx[r*3+1], x2 = sx[r*3+2];
    const int kbase = (tid & 1) * 8;

    for (int kt = 0; kt < 8; kt++) {
        int k0 = kt*16 + kbase;
#pragma unroll
        for (int i = 0; i < 4; i++) {
            float4 wa = swc[k0 + 2*i], wb = swc[k0 + 2*i + 1];
            float va = fmaxf(fmaf(x0, wa.x, fmaf(x1, wa.y, fmaf(x2, wa.z, wa.w))), 0.0f);
            float vb = fmaxf(fmaf(x0, wb.x, fmaf(x1, wb.y, fmaf(x2, wb.z, wb.w))), 0.0f);
            *(__nv_bfloat162*)&As[r*SA + kbase + 2*i] = __floats2bfloat162_rn(va, vb);
        }
        __syncthreads();
        unsigned af[2][4], bfr[8][2];
#pragma unroll
        for (int mt = 0; mt < 2; mt++)
            ldsm4(af[mt][0], af[mt][1], af[mt][2], af[mt][3], aBase + aoff[mt]);
#pragma unroll
        for (int ntp = 0; ntp < 4; ntp++) {
            unsigned r0, r1, r2, r3;
            ldsm4(r0, r1, r2, r3, bBase + boff[ntp] + kt*32);
            bfr[2*ntp][0] = r0;   bfr[2*ntp][1] = r1;
            bfr[2*ntp+1][0] = r2; bfr[2*ntp+1][1] = r3;
        }
#pragma unroll
        for (int mt = 0; mt < 2; mt++)
#pragma unroll
            for (int nt = 0; nt < 8; nt++)
                mma_bf16(acc[mt][nt], af[mt], bfr[nt]);
        __syncthreads();
    }

    const int row0 = br*128 + wm*32;
    const int col0 = bc*128 + wn*64;
#pragma unroll
    for (int mt = 0; mt < 2; mt++) {
        int rr = row0 + mt*16 + (lane >> 2);
#pragma unroll
        for (int nt = 0; nt < 8; nt++) {
            int c = col0 + nt*8 + (lane & 3)*2;
            float bb0 = b2[c], bb1 = b2[c + 1];
            __nv_bfloat162 v0 = __floats2bfloat162_rn(
                fmaxf(acc[mt][nt][0] + bb0, 0.0f), fmaxf(acc[mt][nt][1] + bb1, 0.0f));
            __nv_bfloat162 v1 = __floats2bfloat162_rn(
                fmaxf(acc[mt][nt][2] + bb0, 0.0f), fmaxf(acc[mt][nt][3] + bb1, 0.0f));
            *(__nv_bfloat162*)(g_h2b + (size_t)rr*256 + c)       = v0;
            *(__nv_bfloat162*)(g_h2b + (size_t)(rr + 8)*256 + c) = v1;
        }
    }
}

// ---------------------------------------------------------------------------
// BF16 mma GEMM. EPI: 0 = fp32 store (+optional bias); 2 = bias + batch col-max.
// ---------------------------------------------------------------------------
#define SROW 40
#define STAGE_B (128*SROW*2)

template<int EPI>
__global__ void __launch_bounds__(256) mma_gemm(
    int aid, int bid, const float* __restrict__ bias, int cid,
    int N, int K, int rows_per_batch)
{
    __shared__ __align__(16) bf16 As[2][128*SROW];
    __shared__ __align__(16) bf16 Bs[2][128*SROW];
    __shared__ unsigned cmax[128];

    const bf16* A = scratch_bf16(aid) + (size_t)(blockIdx.y * 128) * K;
    const bf16* B = scratch_bf16(bid) + (size_t)(blockIdx.x * 128) * K;

    const int tid  = threadIdx.x;
    const int lane = tid & 31, wid = tid >> 5;
    const int wm = wid & 3, wn = wid >> 2;

    float acc[2][8][4];
#pragma unroll
    for (int mt = 0; mt < 2; mt++)
#pragma unroll
        for (int nt = 0; nt < 8; nt++)
#pragma unroll
            for (int j = 0; j < 4; j++) acc[mt][nt][j] = 0.0f;

    const unsigned aBase = (unsigned)__cvta_generic_to_shared(&As[0][0]);
    const unsigned bBase = (unsigned)__cvta_generic_to_shared(&Bs[0][0]);

    unsigned aoff[2], boff[4];
#pragma unroll
    for (int mt = 0; mt < 2; mt++)
        aoff[mt] = ((wm*32 + mt*16 + (lane & 15)) * SROW + ((lane >> 4) << 3)) * 2;
#pragma unroll
    for (int ntp = 0; ntp < 4; ntp++)
        boff[ntp] = ((wn*64 + ntp*16 + ((lane & 16) >> 1) + (lane & 7)) * SROW
                     + (lane & 8)) * 2;

    auto load_tile = [&](int s, int k0) {
#pragma unroll
        for (int i = 0; i < 2; i++) {
            int c = tid + (i << 8);
            int row = c >> 2, seg = c & 3;
            unsigned d = row * SROW + seg * 8;
            cpa16(aBase + s*STAGE_B + d*2, A + (size_t)row*K + k0 + seg*8);
            cpa16(bBase + s*STAGE_B + d*2, B + (size_t)row*K + k0 + seg*8);
        }
        asm volatile("cp.async.commit_group;");
    };

    load_tile(0, 0);
    const int KT = K >> 5;
    for (int kt = 0; kt < KT; kt++) {
        if (kt + 1 < KT) {
            load_tile((kt + 1) & 1, (kt + 1) << 5);
            asm volatile("cp.async.wait_group 1;");
        } else {
            asm volatile("cp.async.wait_group 0;");
        }
        __syncthreads();
        unsigned sOff = (kt & 1) * STAGE_B;
#pragma unroll
        for (int ks = 0; ks < 2; ks++) {
            unsigned af[2][4], bfr[8][2];
#pragma unroll
            for (int mt = 0; mt < 2; mt++)
                ldsm4(af[mt][0], af[mt][1], af[mt][2], af[mt][3],
                      aBase + sOff + aoff[mt] + ks*32);
#pragma unroll
            for (int ntp = 0; ntp < 4; ntp++) {
                unsigned r0, r1, r2, r3;
                ldsm4(r0, r1, r2, r3, bBase + sOff + boff[ntp] + ks*32);
                bfr[2*ntp][0] = r0;   bfr[2*ntp][1] = r1;
                bfr[2*ntp+1][0] = r2; bfr[2*ntp+1][1] = r3;
            }
#pragma unroll
            for (int mt = 0; mt < 2; mt++)
#pragma unroll
                for (int nt = 0; nt < 8; nt++)
                    mma_bf16(acc[mt][nt], af[mt], bfr[nt]);
        }
        __syncthreads();
    }

    const int row0  = blockIdx.y * 128 + wm * 32;
    const int col0g = blockIdx.x * 128 + wn * 64;

    if (EPI == 0) {
        float* C = scratch_f32(cid);
#pragma unroll
        for (int mt = 0; mt < 2; mt++) {
            int r = row0 + mt*16 + (lane >> 2);
#pragma unroll
            for (int nt = 0; nt < 8; nt++) {
                int c = col0g + nt*8 + (lane & 3)*2;
                float bb0 = bias ? bias[c]     : 0.0f;
                float bb1 = bias ? bias[c + 1] : 0.0f;
                float2 v0 = {acc[mt][nt][0] + bb0, acc[mt][nt][1] + bb1};
                float2 v1 = {acc[mt][nt][2] + bb0, acc[mt][nt][3] + bb1};
                *(float2*)(C + (size_t)r*N + c)       = v0;
                *(float2*)(C + (size_t)(r + 8)*N + c) = v1;
            }
        }
    } else {
        if (tid < 128) cmax[tid] = 0u;
        __syncthreads();
#pragma unroll
        for (int nt = 0; nt < 8; nt++) {
            int cc = wn*64 + nt*8 + (lane & 3)*2;
            float b0 = bias[blockIdx.x*128 + cc];
            float b1 = bias[blockIdx.x*128 + cc + 1];
            float m0 = fmaxf(fmaxf(acc[0][nt][0], acc[0][nt][2]),
                             fmaxf(acc[1][nt][0], acc[1][nt][2])) + b0;
            float m1 = fmaxf(fmaxf(acc[0][nt][1], acc[0][nt][3]),
                             fmaxf(acc[1][nt][1], acc[1][nt][3])) + b1;
#pragma unroll
            for (int o = 4; o < 32; o <<= 1) {
                m0 = fmaxf(m0, __shfl_xor_sync(0xffffffffu, m0, o));
                m1 = fmaxf(m1, __shfl_xor_sync(0xffffffffu, m1, o));
            }
            if (lane < 4) {
                atomicMax(&cmax[cc],     fkey(m0));
                atomicMax(&cmax[cc + 1], fkey(m1));
            }
        }
        __syncthreads();
        if (tid < 128) {
            int batch = (blockIdx.y * 128) / rows_per_batch;
            atomicMax(&g_featkeys[(size_t)batch * N + blockIdx.x*128 + tid], cmax[tid]);
        }
    }
}

// ---------------------------------------------------------------------------
// Fused fold GEMM (foldpre in A-fill, W2 GEMM, W3 projection epilogue)
// ---------------------------------------------------------------------------
__global__ void __launch_bounds__(256) fold_gemm_fused(
    int feaid, int stage, const float* __restrict__ w1, int bidW,
    const float* __restrict__ b2, const float* __restrict__ W3,
    const float* __restrict__ b3, int outid)
{
    __shared__ __align__(16) bf16 As[2][128*SROW];
    __shared__ __align__(16) bf16 Bs[2][128*SROW];
    __shared__ bf16  w1xs[512], w1ys[512], w1zs[512];
    __shared__ float l0s[128], l1s[128], l2s[128];
    __shared__ float w3s[128*3];
    __shared__ float b2s[128];

    const int K = 512;
    const float* feA = scratch_f32(feaid);
    const bf16* B = scratch_bf16(bidW) + (size_t)(blockIdx.x * 128) * K;

    const int tid  = threadIdx.x;
    const int lane = tid & 31, wid = tid >> 5;
    const int wm = wid & 3, wn = wid >> 2;

    if (tid < 128) {
        int cg = blockIdx.x*128 + tid;
        w3s[tid*3+0] = W3[cg*3+0];
        w3s[tid*3+1] = W3[cg*3+1];
        w3s[tid*3+2] = W3[cg*3+2];
        b2s[tid] = b2[cg];
        int gr = blockIdx.y*128 + tid;
        if (stage == 1) {
            int bg = gr / 36;
            int g = gr - bg * 36;
            l0s[tid] = c_lin[g / 6];
            l1s[tid] = c_lin[g % 6];
            l2s[tid] = 0.0f;
        } else {
            l0s[tid] = g_fold1[gr*3+0];
            l1s[tid] = g_fold1[gr*3+1];
            l2s[tid] = g_fold1[gr*3+2];
        }
    }
    for (int i = tid; i < 512; i += 256) {
        w1xs[i] = __float2bfloat16(w1[1024*512 + i]);
        w1ys[i] = __float2bfloat16(w1[1025*512 + i]);
        w1zs[i] = (stage == 2) ? __float2bfloat16(w1[1026*512 + i])
                               : __float2bfloat16(0.0f);
    }

    const unsigned aBase = (unsigned)__cvta_generic_to_shared(&As[0][0]);
    const unsigned bBase = (unsigned)__cvta_generic_to_shared(&Bs[0][0]);

    const int fr  = tid >> 1;
    const int fkk = (tid & 1) << 4;
    const int fbg = (blockIdx.y*128 + fr) / 36;
    const float* faRow = feA + (size_t)fbg * 512;

    auto fillA = [&](int s, int k0) {
        float l0 = l0s[fr], l1 = l1s[fr], l2 = l2s[fr];
        const float4* fa = (const float4*)(faRow + k0 + fkk);
        unsigned pk[8];
#pragma unroll
        for (int q = 0; q < 4; q++) {
            float4 f = fa[q];
            int kb = k0 + fkk + q*4;
            float v0 = fmaf(l2, __bfloat162float(w1zs[kb+0]),
                       fmaf(l1, __bfloat162float(w1ys[kb+0]),
                       fmaf(l0, __bfloat162float(w1xs[kb+0]), f.x)));
            float v1 = fmaf(l2, __bfloat162float(w1zs[kb+1]),
                       fmaf(l1, __bfloat162float(w1ys[kb+1]),
                       fmaf(l0, __bfloat162float(w1xs[kb+1]), f.y)));
            float v2 = fmaf(l2, __bfloat162float(w1zs[kb+2]),
                       fmaf(l1, __bfloat162float(w1ys[kb+2]),
                       fmaf(l0, __bfloat162float(w1xs[kb+2]), f.z)));
            float v3 = fmaf(l2, __bfloat162float(w1zs[kb+3]),
                       fmaf(l1, __bfloat162float(w1ys[kb+3]),
                       fmaf(l0, __bfloat162float(w1xs[kb+3]), f.w)));
            __nv_bfloat162 p0 = __floats2bfloat162_rn(fmaxf(v0, 0.0f), fmaxf(v1, 0.0f));
            __nv_bfloat162 p1 = __floats2bfloat162_rn(fmaxf(v2, 0.0f), fmaxf(v3, 0.0f));
            pk[q*2+0] = *(unsigned*)&p0;
            pk[q*2+1] = *(unsigned*)&p1;
        }
        uint4* dst = (uint4*)&As[s][fr*SROW + fkk];
        dst[0] = make_uint4(pk[0], pk[1], pk[2], pk[3]);
        dst[1] = make_uint4(pk[4], pk[5], pk[6], pk[7]);
    };

    auto loadB = [&](int s, int k0) {
#pragma unroll
        for (int i = 0; i < 2; i++) {
            int c = tid + (i << 8);
            int rr = c >> 2, sg = c & 3;
            cpa16(bBase + s*STAGE_B + (rr*SROW + sg*8)*2, B + (size_t)rr*K + k0 + sg*8);
        }
        asm volatile("cp.async.commit_group;");
    };

    float acc[2][8][4];
#pragma unroll
    for (int mt = 0; mt < 2; mt++)
#pragma unroll
        for (int nt = 0; nt < 8; nt++)
#pragma unroll
            for (int j = 0; j < 4; j++) acc[mt][nt][j] = 0.0f;

    unsigned aoff[2], boff[4];
#pragma unroll
    for (int mt = 0; mt < 2; mt++)
        aoff[mt] = ((wm*32 + mt*16 + (lane & 15)) * SROW + ((lane >> 4) << 3)) * 2;
#pragma unroll
    for (int ntp = 0; ntp < 4; ntp++)
        boff[ntp] = ((wn*64 + ntp*16 + ((lane & 16) >> 1) + (lane & 7)) * SROW
                     + (lane & 8)) * 2;

    loadB(0, 0);
    __syncthreads();
    fillA(0, 0);

    const int KT = K >> 5;
    for (int kt = 0; kt < KT; kt++) {
        int s = kt & 1;
        if (kt + 1 < KT) {
            loadB(s ^ 1, (kt + 1) << 5);
            asm volatile("cp.async.wait_group 1;");
        } else {
            asm volatile("cp.async.wait_group 0;");
        }
        __syncthreads();
        if (kt + 1 < KT) fillA(s ^ 1, (kt + 1) << 5);
        unsigned sOff = s * STAGE_B;
#pragma unroll
        for (int ks = 0; ks < 2; ks++) {
            unsigned af[2][4], bfr[8][2];
#pragma unroll
            for (int mt = 0; mt < 2; mt++)
                ldsm4(af[mt][0], af[mt][1], af[mt][2], af[mt][3],
                      aBase + sOff + aoff[mt] + ks*32);
#pragma unroll
            for (int ntp = 0; ntp < 4; ntp++) {
                unsigned r0, r1, r2, r3;
                ldsm4(r0, r1, r2, r3, bBase + sOff + boff[ntp] + ks*32);
                bfr[2*ntp][0] = r0;   bfr[2*ntp][1] = r1;
                bfr[2*ntp+1][0] = r2; bfr[2*ntp+1][1] = r3;
            }
#pragma unroll
            for (int mt = 0; mt < 2; mt++)
#pragma unroll
                for (int nt = 0; nt < 8; nt++)
                    mma_bf16(acc[mt][nt], af[mt], bfr[nt]);
        }
        __syncthreads();
    }

    float* out = scratch_f32(outid);
    const int row0 = blockIdx.y * 128 + wm * 32;
    float p[4][3];
#pragma unroll
    for (int i = 0; i < 4; i++)
#pragma unroll
        for (int c = 0; c < 3; c++) p[i][c] = 0.0f;

#pragma unroll
    for (int nt = 0; nt < 8; nt++) {
        int cc0 = wn*64 + nt*8 + (lane & 3)*2;
        int cc1 = cc0 + 1;
        float bb0 = b2s[cc0], bb1 = b2s[cc1];
        float h00 = fmaxf(acc[0][nt][0] + bb0, 0.0f);
        float h01 = fmaxf(acc[0][nt][1] + bb1, 0.0f);
        float h02 = fmaxf(acc[0][nt][2] + bb0, 0.0f);
        float h03 = fmaxf(acc[0][nt][3] + bb1, 0.0f);
        float h10 = fmaxf(acc[1][nt][0] + bb0, 0.0f);
        float h11 = fmaxf(acc[1][nt][1] + bb1, 0.0f);
        float h12 = fmaxf(acc[1][nt][2] + bb0, 0.0f);
        float h13 = fmaxf(acc[1][nt][3] + bb1, 0.0f);
#pragma unroll
        for (int c = 0; c < 3; c++) {
            float w0 = w3s[cc0*3 + c], w1v = w3s[cc1*3 + c];
            p[0][c] = fmaf(h00, w0, fmaf(h01, w1v, p[0][c]));
            p[1][c] = fmaf(h02, w0, fmaf(h03, w1v, p[1][c]));
            p[2][c] = fmaf(h10, w0, fmaf(h11, w1v, p[2][c]));
            p[3][c] = fmaf(h12, w0, fmaf(h13, w1v, p[3][c]));
        }
    }
#pragma unroll
    for (int o = 1; o <= 2; o <<= 1)
#pragma unroll
        for (int i = 0; i < 4; i++)
#pragma unroll
            for (int c = 0; c < 3; c++)
                p[i][c] += __shfl_xor_sync(0xffffffffu, p[i][c], o);

    if ((lane & 3) == 0) {
        bool addb3 = (blockIdx.x == 0) && (wn == 0);
#pragma unroll
        for (int i = 0; i < 4; i++) {
            int r = row0 + (i >> 1)*16 + (lane >> 2) + (i & 1)*8;
#pragma unroll
            for (int c = 0; c < 3; c++) {
                float v = p[i][c];
                if (addb3) v += b3[c];
                atomicAdd(&out[r*3 + c], v);
            }
        }
    }
}

// ---------------------------------------------------------------------------
// Small per-row MLP (coarse chain)
// ---------------------------------------------------------------------------
__global__ void mlp_row_kernel(int xid, int xkeys, const float* __restrict__ W,
                               const float* __restrict__ bias, int yid,
                               int K, int N, int act)
{
    __shared__ float sx[1024];
    float* Y = scratch_f32(yid);
    int b = blockIdx.y;
    int col = blockIdx.x * blockDim.x + threadIdx.x;
    if (xkeys) {
        for (int k = threadIdx.x; k < K; k += blockDim.x)
            sx[k] = unfkey(g_featkeys[b*K + k]);
    } else {
        const float* X = scratch_f32(xid);
        for (int k = threadIdx.x; k < K; k += blockDim.x) sx[k] = X[b*K + k];
    }
    __syncthreads();
    float s0 = 0.0f, s1 = 0.0f, s2 = 0.0f, s3 = 0.0f;
    for (int k = 0; k < K; k += 4) {
        s0 = fmaf(sx[k+0], W[(size_t)(k+0)*N + col], s0);
        s1 = fmaf(sx[k+1], W[(size_t)(k+1)*N + col], s1);
        s2 = fmaf(sx[k+2], W[(size_t)(k+2)*N + col], s2);
        s3 = fmaf(sx[k+3], W[(size_t)(k+3)*N + col], s3);
    }
    float s = ((s0 + s1) + (s2 + s3)) + bias[col];
    if (act) s = fmaxf(s, 0.0f);
    Y[b*N + col] = s;
}

// ---------------------------------------------------------------------------
// pos only (bf16): pos[bg] = gelu(centers@pe_w1+pe_b1) @ pe_w2 + pe_b2
// ---------------------------------------------------------------------------
__global__ void pos_kernel(const float* __restrict__ w1, const float* __restrict__ b1,
                           const float* __restrict__ w2, const float* __restrict__ b2)
{
    int bg = blockIdx.x, t = threadIdx.x;
    __shared__ float h[128];
    float cx = g_centers[bg*3], cy = g_centers[bg*3+1], cz = g_centers[bg*3+2];
    float v = cx*w1[t] + cy*w1[128+t] + cz*w1[256+t] + b1[t];
    h[t] = gelu_exact(v);
    __syncthreads();
    for (int q = 0; q < 8; q++) {
        int j = (q << 7) + t;
        float s = 0.0f;
#pragma unroll 8
        for (int k = 0; k < 128; k++) s = fmaf(h[k], w2[k*1024 + j], s);
        g_posb[bg*1024 + j] = __float2bfloat16(s + b2[j]);
    }
}

// ---------------------------------------------------------------------------
// feat @ foldW1 (8 rows, fp32 exact): out[b][col] = sum_k feat[b][k]*W[k*512+col]
// grid (4, NB, 2); z selects stage
// ---------------------------------------------------------------------------
__global__ void featmlp_kernel(const float* __restrict__ w1a,
                               const float* __restrict__ w1b)
{
    __shared__ float sx[1024];
    int stage = blockIdx.z;
    const float* W = stage ? w1b : w1a;
    float* out = stage ? g_fw1b : g_fw1a;
    int b = blockIdx.y;
    int col = blockIdx.x * 128 + threadIdx.x;
    for (int k = threadIdx.x; k < 1024; k += 128)
        sx[k] = unfkey(g_featkeys[b*1024 + k]);
    __syncthreads();
    float s0 = 0.0f, s1 = 0.0f, s2 = 0.0f, s3 = 0.0f;
    for (int k = 0; k < 1024; k += 4) {
        s0 = fmaf(sx[k+0], W[(size_t)(k+0)*512 + col], s0);
        s1 = fmaf(sx[k+1], W[(size_t)(k+1)*512 + col], s1);
        s2 = fmaf(sx[k+2], W[(size_t)(k+2)*512 + col], s2);
        s3 = fmaf(sx[k+3], W[(size_t)(k+3)*512 + col], s3);
    }
    out[b*512 + col] = (s0 + s1) + (s2 + s3);
}

// feA += featW1 (broadcast per batch), both stages in one pass
__global__ void featadd_kernel() {
    int gid = blockIdx.x * 256 + threadIdx.x;   // 512*512 exactly
    int bg = gid >> 9, j = gid & 511;
    int batch = bg >> 6;
    g_feA1[gid] += g_fw1a[batch*512 + j];
    g_feA2[gid] += g_fw1b[batch*512 + j];
}

// ---------------------------------------------------------------------------
// Chamfer fine
// ---------------------------------------------------------------------------
__global__ void chamfer_fine_kernel() {
    int bg = blockIdx.x, t = threadIdx.x;  // 128 threads
    __shared__ float F[108], Nn[96], rm[36], cm[32];
    for (int i = t; i < 108; i += 128) F[i] = g_fold2[bg*108 + i];
    for (int i = t; i < 96;  i += 128) Nn[i] = g_neigh[bg*96 + i];
    __syncthreads();
    if (t < 36) {
        float fx = F[t*3], fy = F[t*3+1], fz = F[t*3+2], mn = FLT_MAX;
        for (int j = 0; j < 32; j++) {
            float dx = fx-Nn[j*3], dy = fy-Nn[j*3+1], dz = fz-Nn[j*3+2];
            mn = fminf(mn, dx*dx + dy*dy + dz*dz);
        }
        rm[t] = mn;
    } else if (t < 68) {
        int j = t - 36;
        float nx = Nn[j*3], ny = Nn[j*3+1], nz = Nn[j*3+2], mn = FLT_MAX;
        for (int i = 0; i < 36; i++) {
            float dx = F[i*3]-nx, dy = F[i*3+1]-ny, dz = F[i*3+2]-nz;
            mn = fminf(mn, dx*dx + dy*dy + dz*dz);
        }
        cm[j] = mn;
    }
    __syncthreads();
    if (t == 0) {
        float s = 0.0f;
        for (int i = 0; i < 36; i++) s += rm[i];
        atomicAdd(&g_acc[0], s);
        s = 0.0f;
        for (int j = 0; j < 32; j++) s += cm[j];
        atomicAdd(&g_acc[1], s);
    }
}

// ---------------------------------------------------------------------------
// Chamfer coarse
// ---------------------------------------------------------------------------
__global__ void __launch_bounds__(512) chamfer_coarse_kernel() {
    int t = threadIdx.x;
    __shared__ float C[1536], Ce[1536], s1[512], s2[512];
    for (int i = t; i < 1536; i += 512) { C[i] = g_coarse[i]; Ce[i] = g_centers[i]; }
    __syncthreads();
    int b = t >> 6, i = t & 63;
    const float* cb = &C[b*192];
    const float* eb = &Ce[b*192];
    float x = cb[i*3], y = cb[i*3+1], z = cb[i*3+2], mn = FLT_MAX;
    for (int j = 0; j < 64; j++) {
        float dx = x-eb[j*3], dy = y-eb[j*3+1], dz = z-eb[j*3+2];
        mn = fminf(mn, dx*dx + dy*dy + dz*dz);
    }
    s1[t] = mn;
    float x2 = eb[i*3], y2 = eb[i*3+1], z2 = eb[i*3+2];
    mn = FLT_MAX;
    for (int j = 0; j < 64; j++) {
        float dx = x2-cb[j*3], dy = y2-cb[j*3+1], dz = z2-cb[j*3+2];
        mn = fminf(mn, dx*dx + dy*dy + dz*dz);
    }
    s2[t] = mn;
    __syncthreads();
    for (int s = 256; s; s >>= 1) {
        if (t < s) { s1[t] += s1[t+s]; s2[t] += s2[t+s]; }
        __syncthreads();
    }
    if (t == 0) { g_acc[2] = s1[0]; g_acc[3] = s2[0]; }
}

__global__ void finalize_kernel(float* __restrict__ out) {
    out[0] = g_acc[0] / (float)(FROWS) + g_acc[1] / (float)(BGROUPS*GS);
    out[1] = g_acc[2] / 512.0f + g_acc[3] / 512.0f;
}

// ---------------------------------------------------------------------------
// launch — multi-stream DAG; posfe + feA GEMMs off the critical path
// ---------------------------------------------------------------------------
extern "C" void kernel_launch(void* const* d_in, const int* in_sizes, int n_in,
                              void* d_out, int out_size)
{
    (void)in_sizes; (void)n_in; (void)out_size;
    const float* corrupted = (const float*)d_in[0];
    const float* pts       = (const float*)d_in[1];
    const float* enc_w1 = (const float*)d_in[2];
    const float* enc_b1 = (const float*)d_in[3];
    const float* enc_w2 = (const float*)d_in[4];
    const float* enc_b2 = (const float*)d_in[5];
    const float* enc_w3 = (const float*)d_in[6];
    const float* enc_b3 = (const float*)d_in[7];
    const float* pe_w1  = (const float*)d_in[8];
    const float* pe_b1  = (const float*)d_in[9];
    const float* pe_w2  = (const float*)d_in[10];
    const float* pe_b2  = (const float*)d_in[11];
    const float* cp_w1  = (const float*)d_in[12];
    const float* cp_b1  = (const float*)d_in[13];
    const float* cp_w2  = (const float*)d_in[14];
    const float* cp_b2  = (const float*)d_in[15];
    const float* cp_w3  = (const float*)d_in[16];
    const float* cp_b3  = (const float*)d_in[17];
    const float* f1_w1  = (const float*)d_in[18];
    const float* f1_b1  = (const float*)d_in[19];
    const float* f1_w2  = (const float*)d_in[20];
    const float* f1_b2  = (const float*)d_in[21];
    const float* f1_w3  = (const float*)d_in[22];
    const float* f1_b3  = (const float*)d_in[23];
    const float* f2_w1  = (const float*)d_in[24];
    const float* f2_b1  = (const float*)d_in[25];
    const float* f2_w2  = (const float*)d_in[26];
    const float* f2_b2  = (const float*)d_in[27];
    const float* f2_w3  = (const float*)d_in[28];
    const float* f2_b3  = (const float*)d_in[29];
    float* out = (float*)d_out;

    // one-time host resources (no device memory involved)
    static cudaStream_t sB = nullptr, sC = nullptr;
    static cudaEvent_t eFork, eGeo, eEnc, ePosW, eCoarse, eWf;
    if (sB == nullptr) {
        cudaStreamCreateWithFlags(&sB, cudaStreamNonBlocking);
        cudaStreamCreateWithFlags(&sC, cudaStreamNonBlocking);
        cudaEventCreateWithFlags(&eFork,   cudaEventDisableTiming);
        cudaEventCreateWithFlags(&eGeo,    cudaEventDisableTiming);
        cudaEventCreateWithFlags(&eEnc,    cudaEventDisableTiming);
        cudaEventCreateWithFlags(&ePosW,   cudaEventDisableTiming);
        cudaEventCreateWithFlags(&eCoarse, cudaEventDisableTiming);
        cudaEventCreateWithFlags(&eWf,     cudaEventDisableTiming);
    }

    // main: minimal init
    zero_main_kernel<<<32, 256>>>();
    cudaEventRecord(eFork, 0);

    // stream B: geometry, then pos + both pos@W1 GEMMs (hidden behind encoder)
    cudaStreamWaitEvent(sB, eFork, 0);
    fps_kernel<<<NB, 1024, 0, sB>>>(pts);
    knn_kernel<<<BGROUPS, 256, 0, sB>>>(pts);
    cudaEventRecord(eGeo, sB);

    // stream C: fold zero + fold weight transposes, later coarse chain
    cudaStreamWaitEvent(sC, eFork, 0);
    zero_fold_kernel<<<(FROWS*3 + 255)/256, 256, 0, sC>>>();
    wtrans_fold<<<dim3(2048, 4), 256, 0, sC>>>(f1_w1, f2_w1, f1_w2, f2_w2);
    cudaEventRecord(eWf, sC);

    // stream B (cont.): pos + feA GEMMs
    pos_kernel<<<BGROUPS, 128, 0, sB>>>(pe_w1, pe_b1, pe_w2, pe_b2);
    cudaStreamWaitEvent(sB, eWf, 0);
    mma_gemm<0><<<dim3(4, 4), 256, 0, sB>>>(BID_POS, BID_F1W1T, f1_b1, FID_FEA1, 512, 1024, 0);
    mma_gemm<0><<<dim3(4, 4), 256, 0, sB>>>(BID_POS, BID_F2W1T, f2_b1, FID_FEA2, 512, 1024, 0);
    cudaEventRecord(ePosW, sB);

    // main: enc weights + encoder
    wtrans_enc<<<dim3(1024, 2), 256>>>(enc_w2, enc_w3);
    enc12_kernel<<<dim3(2, 512), 256>>>(corrupted, enc_w1, enc_b1, enc_b2);
    mma_gemm<2><<<dim3(8, 512), 256>>>(BID_H2, BID_W3T, enc_b3, 0, 1024, 256, NPTS);
    cudaEventRecord(eEnc, 0);

    // stream C: coarse MLP chain + coarse chamfer
    cudaStreamWaitEvent(sC, eEnc, 0);
    mlp_row_kernel<<<dim3(8, NB), 128, 0, sC>>>(0, 1, cp_w1, cp_b1, FID_C1, 1024, 1024, 1);
    mlp_row_kernel<<<dim3(8, NB), 128, 0, sC>>>(FID_C1, 0, cp_w2, cp_b2, FID_C2, 1024, 1024, 1);
    mlp_row_kernel<<<dim3(1, NB), 192, 0, sC>>>(FID_C2, 0, cp_w3, cp_b3, FID_COARSE, 1024, 192, 0);
    cudaStreamWaitEvent(sC, eGeo, 0);
    chamfer_coarse_kernel<<<1, 512, 0, sC>>>();
    cudaEventRecord(eCoarse, sC);

    // main: feat @ foldW1 (tiny), then add into feA (waits pos@W1 GEMMs)
    featmlp_kernel<<<dim3(4, NB, 2), 128>>>(f1_w1, f2_w1);
    cudaStreamWaitEvent(0, ePosW, 0);
    featadd_kernel<<<1024, 256>>>();

    // fold stage 1 (fused foldpre + GEMM + W3 projection)
    fold_gemm_fused<<<dim3(4, 144), 256>>>(FID_FEA1, 1, f1_w1, BID_F1W2T,
                                           f1_b2, f1_w3, f1_b3, FID_FOLD1);

    // fold stage 2
    fold_gemm_fused<<<dim3(4, 144), 256>>>(FID_FEA2, 2, f2_w1, BID_F2W2T,
                                           f2_b2, f2_w3, f2_b3, FID_FOLD2);

    // fine chamfer (needs neigh from geometry)
    cudaStreamWaitEvent(0, eGeo, 0);
    chamfer_fine_kernel<<<BGROUPS, 128>>>();

    // join coarse chain, finalize
    cudaStreamWaitEvent(0, eCoarse, 0);
    finalize_kernel<<<1, 1>>>(out);
}

// round 13
// speedup vs baseline: 1.6395x; 1.6395x over previous
#include <cuda_runtime.h>
#include <cuda_bf16.h>
#include <math.h>
#include <float.h>

// ---------------------------------------------------------------------------
// Problem constants
// ---------------------------------------------------------------------------
#define NB       8
#define NPTS     8192
#define NC       64
#define GS       32
#define BGROUPS  512
#define GRID_PTS 36
#define FROWS    (BGROUPS*GRID_PTS)   // 18432
#define ENC_ROWS (NB*NPTS)            // 65536

typedef __nv_bfloat16 bf16;

// ---------------------------------------------------------------------------
// Scratch (device globals; no allocation anywhere)
// ---------------------------------------------------------------------------
__device__ bf16     g_h2b[ENC_ROWS*256];
__device__ bf16     g_feb[BGROUPS*1024];
__device__ bf16     g_w2t[256*128];
__device__ bf16     g_w3t[1024*256];
__device__ bf16     g_f1w1t[512*1024];
__device__ bf16     g_f2w1t[512*1024];
__device__ bf16     g_f1w2t[512*512];
__device__ bf16     g_f2w2t[512*512];

__device__ float    g_feA1[BGROUPS*512];
__device__ float    g_feA2[BGROUPS*512];
__device__ unsigned g_featkeys[NB*1024];
__device__ float    g_centers[BGROUPS*3];
__device__ float    g_neigh[BGROUPS*GS*3];
__device__ float    g_fold1[FROWS*3];
__device__ float    g_fold2[FROWS*3];
__device__ float    g_c1[NB*1024];
__device__ float    g_c2[NB*1024];
__device__ float    g_coarse[NB*192];
__device__ float    g_acc[4];

__constant__ float c_lin[6] = {-0.3f,-0.18f,-0.06f,0.06f,0.18f,0.3f};

// bf16 scratch ids
#define BID_H2     0
#define BID_FE     1
#define BID_W2T    2
#define BID_W3T    3
#define BID_F1W1T  4
#define BID_F2W1T  5
#define BID_F1W2T  6
#define BID_F2W2T  7

// f32 scratch ids
#define FID_FEA1   0
#define FID_FEA2   1
#define FID_C1     2
#define FID_C2     3
#define FID_COARSE 4
#define FID_FOLD1  5
#define FID_FOLD2  6

__device__ __forceinline__ bf16* scratch_bf16(int id) {
    switch (id) {
        case BID_H2:    return g_h2b;
        case BID_FE:    return g_feb;
        case BID_W2T:   return g_w2t;
        case BID_W3T:   return g_w3t;
        case BID_F1W1T: return g_f1w1t;
        case BID_F2W1T: return g_f2w1t;
        case BID_F1W2T: return g_f1w2t;
        default:        return g_f2w2t;
    }
}
__device__ __forceinline__ float* scratch_f32(int id) {
    switch (id) {
        case FID_FEA1:  return g_feA1;
        case FID_FEA2:  return g_feA2;
        case FID_C1:    return g_c1;
        case FID_C2:    return g_c2;
        case FID_COARSE:return g_coarse;
        case FID_FOLD1: return g_fold1;
        default:        return g_fold2;
    }
}

__device__ __forceinline__ unsigned fkey(float f) {
    unsigned u = __float_as_uint(f);
    return (u & 0x80000000u) ? ~u : (u | 0x80000000u);
}
__device__ __forceinline__ float unfkey(unsigned k) {
    return __uint_as_float((k & 0x80000000u) ? (k & 0x7fffffffu) : ~k);
}

__device__ __forceinline__ float gelu_exact(float x) {
    return 0.5f * x * (1.0f + erff(x * 0.7071067811865476f));
}

__device__ __forceinline__ void cpa16(unsigned dst, const void* src) {
    asm volatile("cp.async.cg.shared.global [%0], [%1], 16;" :: "r"(dst), "l"(src));
}

__device__ __forceinline__ void ldsm4(unsigned& r0, unsigned& r1, unsigned& r2,
                                      unsigned& r3, unsigned addr) {
    asm volatile("ldmatrix.sync.aligned.m8n8.x4.shared.b16 {%0,%1,%2,%3}, [%4];"
        : "=r"(r0), "=r"(r1), "=r"(r2), "=r"(r3) : "r"(addr));
}

__device__ __forceinline__ void mma_bf16(float* c, const unsigned* a, const unsigned* b) {
    asm volatile(
        "mma.sync.aligned.m16n8k16.row.col.f32.bf16.bf16.f32 "
        "{%0,%1,%2,%3}, {%4,%5,%6,%7}, {%8,%9}, {%0,%1,%2,%3};"
        : "+f"(c[0]), "+f"(c[1]), "+f"(c[2]), "+f"(c[3])
        : "r"(a[0]), "r"(a[1]), "r"(a[2]), "r"(a[3]), "r"(b[0]), "r"(b[1]));
}

__device__ __forceinline__ void wredmax(float& v, int& i) {
#pragma unroll
    for (int o = 16; o; o >>= 1) {
        float v2 = __shfl_xor_sync(0xffffffffu, v, o);
        int   i2 = __shfl_xor_sync(0xffffffffu, i, o);
        if (v2 > v || (v2 == v && i2 < i)) { v = v2; i = i2; }
    }
}
__device__ __forceinline__ void wredmin(float& v, int& i) {
#pragma unroll
    for (int o = 16; o; o >>= 1) {
        float v2 = __shfl_xor_sync(0xffffffffu, v, o);
        int   i2 = __shfl_xor_sync(0xffffffffu, i, o);
        if (v2 < v || (v2 == v && i2 < i)) { v = v2; i = i2; }
    }
}

// ---------------------------------------------------------------------------
// init
// ---------------------------------------------------------------------------
__global__ void zero_main_kernel() {
    int i = blockIdx.x * 256 + threadIdx.x;
    if (i < NB*1024) g_featkeys[i] = 0u;
    if (i < 4)       g_acc[i] = 0.0f;
}
__global__ void zero_fold_kernel() {
    int i = blockIdx.x * 256 + threadIdx.x;
    if (i < FROWS*3) { g_fold1[i] = 0.0f; g_fold2[i] = 0.0f; }
}

// ---------------------------------------------------------------------------
// weight transpose + bf16: out[n*K+k] = bf16(W[k*N+n])
// ---------------------------------------------------------------------------
__global__ void wtrans_one(const float* __restrict__ W, int K, int N, int bid) {
    bf16* out = scratch_bf16(bid);
    int i = blockIdx.x * 256 + threadIdx.x;
    if (i < K * N) {
        int n = i / K, k = i - n * K;
        out[i] = __float2bfloat16(W[(size_t)k * N + n]);
    }
}

__global__ void wtrans_fold(const float* __restrict__ fw1a, const float* __restrict__ fw1b,
                            const float* __restrict__ fw2a, const float* __restrict__ fw2b)
{
    const float* W; int K, N; bf16* out;
    switch (blockIdx.y) {
        case 0: W = fw1a; K = 1024; N = 512; out = g_f1w1t; break;
        case 1: W = fw1b; K = 1024; N = 512; out = g_f2w1t; break;
        case 2: W = fw2a; K = 512;  N = 512; out = g_f1w2t; break;
        default:W = fw2b; K = 512;  N = 512; out = g_f2w2t; break;
    }
    int i = blockIdx.x * 256 + threadIdx.x;
    if (i < K * N) {
        int n = i / K, k = i - n * K;
        out[i] = __float2bfloat16(W[(size_t)k * N + n]);
    }
}

// ---------------------------------------------------------------------------
// Farthest point sampling
// ---------------------------------------------------------------------------
__global__ void __launch_bounds__(1024) fps_kernel(const float* __restrict__ pts) {
    int b = blockIdx.x, t = threadIdx.x;
    int lane = t & 31, wid = t >> 5;
    const float* P = pts + (size_t)b * NPTS * 3;
    __shared__ float sv[32];
    __shared__ int   si[32];
    __shared__ float cur[3];

    float px[8], py[8], pz[8], dd[8];
#pragma unroll
    for (int i = 0; i < 8; i++) {
        int p = (t << 3) + i;
        px[i] = P[p*3]; py[i] = P[p*3+1]; pz[i] = P[p*3+2];
    }
    if (t == 0) {
        cur[0] = P[0]; cur[1] = P[1]; cur[2] = P[2];
        g_centers[b*192+0] = P[0]; g_centers[b*192+1] = P[1]; g_centers[b*192+2] = P[2];
    }
    __syncthreads();
    float cx = cur[0], cy = cur[1], cz = cur[2];
#pragma unroll
    for (int i = 0; i < 8; i++) {
        float dx = px[i]-cx, dy = py[i]-cy, dz = pz[i]-cz;
        dd[i] = dx*dx + dy*dy + dz*dz;
    }
    for (int it = 1; it < NC; it++) {
        float bv = dd[0]; int bi = (t << 3);
#pragma unroll
        for (int i = 1; i < 8; i++)
            if (dd[i] > bv) { bv = dd[i]; bi = (t << 3) + i; }
        wredmax(bv, bi);
        if (lane == 0) { sv[wid] = bv; si[wid] = bi; }
        __syncthreads();
        if (wid == 0) {
            float v = sv[lane]; int i = si[lane];
            wredmax(v, i);
            if (lane == 0) {
                cur[0] = P[i*3]; cur[1] = P[i*3+1]; cur[2] = P[i*3+2];
                g_centers[b*192 + it*3+0] = cur[0];
                g_centers[b*192 + it*3+1] = cur[1];
                g_centers[b*192 + it*3+2] = cur[2];
            }
        }
        __syncthreads();
        cx = cur[0]; cy = cur[1]; cz = cur[2];
#pragma unroll
        for (int i = 0; i < 8; i++) {
            float dx = px[i]-cx, dy = py[i]-cy, dz = pz[i]-cz;
            dd[i] = fminf(dd[i], dx*dx + dy*dy + dz*dz);
        }
    }
}

// ---------------------------------------------------------------------------
// 32-NN grouping — incremental argmin
// ---------------------------------------------------------------------------
__global__ void __launch_bounds__(256) knn_kernel(const float* __restrict__ pts) {
    int bg = blockIdx.x, b = bg >> 6, t = threadIdx.x;
    int lane = t & 31, wid = t >> 5;
    const float* P = pts + (size_t)b * NPTS * 3;
    __shared__ float sd[NPTS];
    __shared__ float sv[8];
    __shared__ int   si[8];
    __shared__ int   swin;
    float cx = g_centers[bg*3], cy = g_centers[bg*3+1], cz = g_centers[bg*3+2];
    for (int p = t; p < NPTS; p += 256) {
        float dx = P[p*3]-cx, dy = P[p*3+1]-cy, dz = P[p*3+2]-cz;
        sd[p] = dx*dx + dy*dy + dz*dz;
    }
    __syncthreads();

    const int base = t << 5;
    float mv = FLT_MAX; int mi = base;
#pragma unroll 8
    for (int j = 0; j < 32; j++) {
        float v = sd[base + j];
        if (v < mv) { mv = v; mi = base + j; }
    }

    for (int k = 0; k < GS; k++) {
        float bv = mv; int bi = mi;
        wredmin(bv, bi);
        if (lane == 0) { sv[wid] = bv; si[wid] = bi; }
        __syncthreads();
        if (t < 32) {
            float v = (lane < 8) ? sv[lane] : FLT_MAX;
            int   i = (lane < 8) ? si[lane] : NPTS;
            wredmin(v, i);
            if (lane == 0) {
                swin = i;
                g_neigh[(bg*GS+k)*3+0] = P[i*3+0] - cx;
                g_neigh[(bg*GS+k)*3+1] = P[i*3+1] - cy;
                g_neigh[(bg*GS+k)*3+2] = P[i*3+2] - cz;
            }
        }
        __syncthreads();
        int win = swin;
        if ((win >> 5) == t) {
            sd[win] = FLT_MAX;
            mv = FLT_MAX; mi = base;
#pragma unroll 8
            for (int j = 0; j < 32; j++) {
                float v = sd[base + j];
                if (v < mv) { mv = v; mi = base + j; }
            }
        }
        __syncthreads();
    }
}

// ---------------------------------------------------------------------------
// Fused enc layer1 + layer2 GEMM
// ---------------------------------------------------------------------------
#define SA 24
#define SB 136

__global__ void __launch_bounds__(256) enc12_kernel(
    const float* __restrict__ x, const float* __restrict__ w1,
    const float* __restrict__ b1, const float* __restrict__ b2)
{
    __shared__ __align__(16) bf16 Bs[128*SB];
    __shared__ __align__(16) bf16 As[128*SA];
    __shared__ float  sx[384];
    __shared__ float4 swc[128];

    const int tid = threadIdx.x, lane = tid & 31, wid = tid >> 5;
    const int wm = wid & 3, wn = wid >> 2;
    const int br = blockIdx.y, bc = blockIdx.x;

    const bf16* B = g_w2t + (size_t)(bc * 128) * 128;
    const unsigned bBase = (unsigned)__cvta_generic_to_shared(&Bs[0]);
    const unsigned aBase = (unsigned)__cvta_generic_to_shared(&As[0]);

#pragma unroll
    for (int i = 0; i < 8; i++) {
        int chunk = i * 256 + tid;
        int row = chunk >> 4, seg = chunk & 15;
        cpa16(bBase + (row*SB + seg*8)*2, B + row*128 + seg*8);
    }
    asm volatile("cp.async.commit_group;");

    if (tid < 96) *(float4*)&sx[tid*4] = *(const float4*)(x + (size_t)br*384 + tid*4);
    if (tid < 128) {
        float4 w; w.x = w1[tid]; w.y = w1[128+tid]; w.z = w1[256+tid]; w.w = b1[tid];
        swc[tid] = w;
    }
    asm volatile("cp.async.wait_group 0;");
    __syncthreads();

    float acc[2][8][4];
#pragma unroll
    for (int mt = 0; mt < 2; mt++)
#pragma unroll
        for (int nt = 0; nt < 8; nt++)
#pragma unroll
            for (int j = 0; j < 4; j++) acc[mt][nt][j] = 0.0f;

    unsigned aoff[2], boff[4];
#pragma unroll
    for (int mt = 0; mt < 2; mt++)
        aoff[mt] = ((wm*32 + mt*16 + (lane & 15)) * SA + ((lane >> 4) << 3)) * 2;
#pragma unroll
    for (int ntp = 0; ntp < 4; ntp++)
        boff[ntp] = ((wn*64 + ntp*16 + ((lane & 16) >> 1) + (lane & 7)) * SB
                     + (lane & 8)) * 2;

    const int r = tid >> 1;
    const float x0 = sx[r*3], x1 = sx[r*3+1], x2 = sx[r*3+2];
    const int kbase = (tid & 1) * 8;

    for (int kt = 0; kt < 8; kt++) {
        int k0 = kt*16 + kbase;
#pragma unroll
        for (int i = 0; i < 4; i++) {
            float4 wa = swc[k0 + 2*i], wb = swc[k0 + 2*i + 1];
            float va = fmaxf(fmaf(x0, wa.x, fmaf(x1, wa.y, fmaf(x2, wa.z, wa.w))), 0.0f);
            float vb = fmaxf(fmaf(x0, wb.x, fmaf(x1, wb.y, fmaf(x2, wb.z, wb.w))), 0.0f);
            *(__nv_bfloat162*)&As[r*SA + kbase + 2*i] = __floats2bfloat162_rn(va, vb);
        }
        __syncthreads();
        unsigned af[2][4], bfr[8][2];
#pragma unroll
        for (int mt = 0; mt < 2; mt++)
            ldsm4(af[mt][0], af[mt][1], af[mt][2], af[mt][3], aBase + aoff[mt]);
#pragma unroll
        for (int ntp = 0; ntp < 4; ntp++) {
            unsigned r0, r1, r2, r3;
            ldsm4(r0, r1, r2, r3, bBase + boff[ntp] + kt*32);
            bfr[2*ntp][0] = r0;   bfr[2*ntp][1] = r1;
            bfr[2*ntp+1][0] = r2; bfr[2*ntp+1][1] = r3;
        }
#pragma unroll
        for (int mt = 0; mt < 2; mt++)
#pragma unroll
            for (int nt = 0; nt < 8; nt++)
                mma_bf16(acc[mt][nt], af[mt], bfr[nt]);
        __syncthreads();
    }

    const int row0 = br*128 + wm*32;
    const int col0 = bc*128 + wn*64;
#pragma unroll
    for (int mt = 0; mt < 2; mt++) {
        int rr = row0 + mt*16 + (lane >> 2);
#pragma unroll
        for (int nt = 0; nt < 8; nt++) {
            int c = col0 + nt*8 + (lane & 3)*2;
            float bb0 = b2[c], bb1 = b2[c + 1];
            __nv_bfloat162 v0 = __floats2bfloat162_rn(
                fmaxf(acc[mt][nt][0] + bb0, 0.0f), fmaxf(acc[mt][nt][1] + bb1, 0.0f));
            __nv_bfloat162 v1 = __floats2bfloat162_rn(
                fmaxf(acc[mt][nt][2] + bb0, 0.0f), fmaxf(acc[mt][nt][3] + bb1, 0.0f));
            *(__nv_bfloat162*)(g_h2b + (size_t)rr*256 + c)       = v0;
            *(__nv_bfloat162*)(g_h2b + (size_t)(rr + 8)*256 + c) = v1;
        }
    }
}

// ---------------------------------------------------------------------------
// BF16 mma GEMM. EPI: 0 = fp32 store (+optional bias); 2 = bias + batch col-max.
// ---------------------------------------------------------------------------
#define SROW 40
#define STAGE_B (128*SROW*2)

template<int EPI>
__global__ void __launch_bounds__(256) mma_gemm(
    int aid, int bid, const float* __restrict__ bias, int cid,
    int N, int K, int rows_per_batch)
{
    __shared__ __align__(16) bf16 As[2][128*SROW];
    __shared__ __align__(16) bf16 Bs[2][128*SROW];
    __shared__ unsigned cmax[128];

    const bf16* A = scratch_bf16(aid) + (size_t)(blockIdx.y * 128) * K;
    const bf16* B = scratch_bf16(bid) + (size_t)(blockIdx.x * 128) * K;

    const int tid  = threadIdx.x;
    const int lane = tid & 31, wid = tid >> 5;
    const int wm = wid & 3, wn = wid >> 2;

    float acc[2][8][4];
#pragma unroll
    for (int mt = 0; mt < 2; mt++)
#pragma unroll
        for (int nt = 0; nt < 8; nt++)
#pragma unroll
            for (int j = 0; j < 4; j++) acc[mt][nt][j] = 0.0f;

    const unsigned aBase = (unsigned)__cvta_generic_to_shared(&As[0][0]);
    const unsigned bBase = (unsigned)__cvta_generic_to_shared(&Bs[0][0]);

    unsigned aoff[2], boff[4];
#pragma unroll
    for (int mt = 0; mt < 2; mt++)
        aoff[mt] = ((wm*32 + mt*16 + (lane & 15)) * SROW + ((lane >> 4) << 3)) * 2;
#pragma unroll
    for (int ntp = 0; ntp < 4; ntp++)
        boff[ntp] = ((wn*64 + ntp*16 + ((lane & 16) >> 1) + (lane & 7)) * SROW
                     + (lane & 8)) * 2;

    auto load_tile = [&](int s, int k0) {
#pragma unroll
        for (int i = 0; i < 2; i++) {
            int c = tid + (i << 8);
            int row = c >> 2, seg = c & 3;
            unsigned d = row * SROW + seg * 8;
            cpa16(aBase + s*STAGE_B + d*2, A + (size_t)row*K + k0 + seg*8);
            cpa16(bBase + s*STAGE_B + d*2, B + (size_t)row*K + k0 + seg*8);
        }
        asm volatile("cp.async.commit_group;");
    };

    load_tile(0, 0);
    const int KT = K >> 5;
    for (int kt = 0; kt < KT; kt++) {
        if (kt + 1 < KT) {
            load_tile((kt + 1) & 1, (kt + 1) << 5);
            asm volatile("cp.async.wait_group 1;");
        } else {
            asm volatile("cp.async.wait_group 0;");
        }
        __syncthreads();
        unsigned sOff = (kt & 1) * STAGE_B;
#pragma unroll
        for (int ks = 0; ks < 2; ks++) {
            unsigned af[2][4], bfr[8][2];
#pragma unroll
            for (int mt = 0; mt < 2; mt++)
                ldsm4(af[mt][0], af[mt][1], af[mt][2], af[mt][3],
                      aBase + sOff + aoff[mt] + ks*32);
#pragma unroll
            for (int ntp = 0; ntp < 4; ntp++) {
                unsigned r0, r1, r2, r3;
                ldsm4(r0, r1, r2, r3, bBase + sOff + boff[ntp] + ks*32);
                bfr[2*ntp][0] = r0;   bfr[2*ntp][1] = r1;
                bfr[2*ntp+1][0] = r2; bfr[2*ntp+1][1] = r3;
            }
#pragma unroll
            for (int mt = 0; mt < 2; mt++)
#pragma unroll
                for (int nt = 0; nt < 8; nt++)
                    mma_bf16(acc[mt][nt], af[mt], bfr[nt]);
        }
        __syncthreads();
    }

    const int row0  = blockIdx.y * 128 + wm * 32;
    const int col0g = blockIdx.x * 128 + wn * 64;

    if (EPI == 0) {
        float* C = scratch_f32(cid);
#pragma unroll
        for (int mt = 0; mt < 2; mt++) {
            int r = row0 + mt*16 + (lane >> 2);
#pragma unroll
            for (int nt = 0; nt < 8; nt++) {
                int c = col0g + nt*8 + (lane & 3)*2;
                float bb0 = bias ? bias[c]     : 0.0f;
                float bb1 = bias ? bias[c + 1] : 0.0f;
                float2 v0 = {acc[mt][nt][0] + bb0, acc[mt][nt][1] + bb1};
                float2 v1 = {acc[mt][nt][2] + bb0, acc[mt][nt][3] + bb1};
                *(float2*)(C + (size_t)r*N + c)       = v0;
                *(float2*)(C + (size_t)(r + 8)*N + c) = v1;
            }
        }
    } else {
        if (tid < 128) cmax[tid] = 0u;
        __syncthreads();
#pragma unroll
        for (int nt = 0; nt < 8; nt++) {
            int cc = wn*64 + nt*8 + (lane & 3)*2;
            float b0 = bias[blockIdx.x*128 + cc];
            float b1 = bias[blockIdx.x*128 + cc + 1];
            float m0 = fmaxf(fmaxf(acc[0][nt][0], acc[0][nt][2]),
                             fmaxf(acc[1][nt][0], acc[1][nt][2])) + b0;
            float m1 = fmaxf(fmaxf(acc[0][nt][1], acc[0][nt][3]),
                             fmaxf(acc[1][nt][1], acc[1][nt][3])) + b1;
#pragma unroll
            for (int o = 4; o < 32; o <<= 1) {
                m0 = fmaxf(m0, __shfl_xor_sync(0xffffffffu, m0, o));
                m1 = fmaxf(m1, __shfl_xor_sync(0xffffffffu, m1, o));
            }
            if (lane < 4) {
                atomicMax(&cmax[cc],     fkey(m0));
                atomicMax(&cmax[cc + 1], fkey(m1));
            }
        }
        __syncthreads();
        if (tid < 128) {
            int batch = (blockIdx.y * 128) / rows_per_batch;
            atomicMax(&g_featkeys[(size_t)batch * N + blockIdx.x*128 + tid], cmax[tid]);
        }
    }
}

// ---------------------------------------------------------------------------
// Fused fold GEMM (foldpre in A-fill, W2 GEMM, W3 projection epilogue)
// ---------------------------------------------------------------------------
__global__ void __launch_bounds__(256) fold_gemm_fused(
    int feaid, int stage, const float* __restrict__ w1, int bidW,
    const float* __restrict__ b2, const float* __restrict__ W3,
    const float* __restrict__ b3, int outid)
{
    __shared__ __align__(16) bf16 As[2][128*SROW];
    __shared__ __align__(16) bf16 Bs[2][128*SROW];
    __shared__ bf16  w1xs[512], w1ys[512], w1zs[512];
    __shared__ float l0s[128], l1s[128], l2s[128];
    __shared__ float w3s[128*3];
    __shared__ float b2s[128];

    const int K = 512;
    const float* feA = scratch_f32(feaid);
    const bf16* B = scratch_bf16(bidW) + (size_t)(blockIdx.x * 128) * K;

    const int tid  = threadIdx.x;
    const int lane = tid & 31, wid = tid >> 5;
    const int wm = wid & 3, wn = wid >> 2;

    if (tid < 128) {
        int cg = blockIdx.x*128 + tid;
        w3s[tid*3+0] = W3[cg*3+0];
        w3s[tid*3+1] = W3[cg*3+1];
        w3s[tid*3+2] = W3[cg*3+2];
        b2s[tid] = b2[cg];
        int gr = blockIdx.y*128 + tid;
        if (stage == 1) {
            int bg = gr / 36;
            int g = gr - bg * 36;
            l0s[tid] = c_lin[g / 6];
            l1s[tid] = c_lin[g % 6];
            l2s[tid] = 0.0f;
        } else {
            l0s[tid] = g_fold1[gr*3+0];
            l1s[tid] = g_fold1[gr*3+1];
            l2s[tid] = g_fold1[gr*3+2];
        }
    }
    for (int i = tid; i < 512; i += 256) {
        w1xs[i] = __float2bfloat16(w1[1024*512 + i]);
        w1ys[i] = __float2bfloat16(w1[1025*512 + i]);
        w1zs[i] = (stage == 2) ? __float2bfloat16(w1[1026*512 + i])
                               : __float2bfloat16(0.0f);
    }

    const unsigned aBase = (unsigned)__cvta_generic_to_shared(&As[0][0]);
    const unsigned bBase = (unsigned)__cvta_generic_to_shared(&Bs[0][0]);

    const int fr  = tid >> 1;
    const int fkk = (tid & 1) << 4;
    const int fbg = (blockIdx.y*128 + fr) / 36;
    const float* faRow = feA + (size_t)fbg * 512;

    auto fillA = [&](int s, int k0) {
        float l0 = l0s[fr], l1 = l1s[fr], l2 = l2s[fr];
        const float4* fa = (const float4*)(faRow + k0 + fkk);
        unsigned pk[8];
#pragma unroll
        for (int q = 0; q < 4; q++) {
            float4 f = fa[q];
            int kb = k0 + fkk + q*4;
            float v0 = fmaf(l2, __bfloat162float(w1zs[kb+0]),
                       fmaf(l1, __bfloat162float(w1ys[kb+0]),
                       fmaf(l0, __bfloat162float(w1xs[kb+0]), f.x)));
            float v1 = fmaf(l2, __bfloat162float(w1zs[kb+1]),
                       fmaf(l1, __bfloat162float(w1ys[kb+1]),
                       fmaf(l0, __bfloat162float(w1xs[kb+1]), f.y)));
            float v2 = fmaf(l2, __bfloat162float(w1zs[kb+2]),
                       fmaf(l1, __bfloat162float(w1ys[kb+2]),
                       fmaf(l0, __bfloat162float(w1xs[kb+2]), f.z)));
            float v3 = fmaf(l2, __bfloat162float(w1zs[kb+3]),
                       fmaf(l1, __bfloat162float(w1ys[kb+3]),
                       fmaf(l0, __bfloat162float(w1xs[kb+3]), f.w)));
            __nv_bfloat162 p0 = __floats2bfloat162_rn(fmaxf(v0, 0.0f), fmaxf(v1, 0.0f));
            __nv_bfloat162 p1 = __floats2bfloat162_rn(fmaxf(v2, 0.0f), fmaxf(v3, 0.0f));
            pk[q*2+0] = *(unsigned*)&p0;
            pk[q*2+1] = *(unsigned*)&p1;
        }
        uint4* dst = (uint4*)&As[s][fr*SROW + fkk];
        dst[0] = make_uint4(pk[0], pk[1], pk[2], pk[3]);
        dst[1] = make_uint4(pk[4], pk[5], pk[6], pk[7]);
    };

    auto loadB = [&](int s, int k0) {
#pragma unroll
        for (int i = 0; i < 2; i++) {
            int c = tid + (i << 8);
            int rr = c >> 2, sg = c & 3;
            cpa16(bBase + s*STAGE_B + (rr*SROW + sg*8)*2, B + (size_t)rr*K + k0 + sg*8);
        }
        asm volatile("cp.async.commit_group;");
    };

    float acc[2][8][4];
#pragma unroll
    for (int mt = 0; mt < 2; mt++)
#pragma unroll
        for (int nt = 0; nt < 8; nt++)
#pragma unroll
            for (int j = 0; j < 4; j++) acc[mt][nt][j] = 0.0f;

    unsigned aoff[2], boff[4];
#pragma unroll
    for (int mt = 0; mt < 2; mt++)
        aoff[mt] = ((wm*32 + mt*16 + (lane & 15)) * SROW + ((lane >> 4) << 3)) * 2;
#pragma unroll
    for (int ntp = 0; ntp < 4; ntp++)
        boff[ntp] = ((wn*64 + ntp*16 + ((lane & 16) >> 1) + (lane & 7)) * SROW
                     + (lane & 8)) * 2;

    loadB(0, 0);
    __syncthreads();
    fillA(0, 0);

    const int KT = K >> 5;
    for (int kt = 0; kt < KT; kt++) {
        int s = kt & 1;
        if (kt + 1 < KT) {
            loadB(s ^ 1, (kt + 1) << 5);
            asm volatile("cp.async.wait_group 1;");
        } else {
            asm volatile("cp.async.wait_group 0;");
        }
        __syncthreads();
        if (kt + 1 < KT) fillA(s ^ 1, (kt + 1) << 5);
        unsigned sOff = s * STAGE_B;
#pragma unroll
        for (int ks = 0; ks < 2; ks++) {
            unsigned af[2][4], bfr[8][2];
#pragma unroll
            for (int mt = 0; mt < 2; mt++)
                ldsm4(af[mt][0], af[mt][1], af[mt][2], af[mt][3],
                      aBase + sOff + aoff[mt] + ks*32);
#pragma unroll
            for (int ntp = 0; ntp < 4; ntp++) {
                unsigned r0, r1, r2, r3;
                ldsm4(r0, r1, r2, r3, bBase + sOff + boff[ntp] + ks*32);
                bfr[2*ntp][0] = r0;   bfr[2*ntp][1] = r1;
                bfr[2*ntp+1][0] = r2; bfr[2*ntp+1][1] = r3;
            }
#pragma unroll
            for (int mt = 0; mt < 2; mt++)
#pragma unroll
                for (int nt = 0; nt < 8; nt++)
                    mma_bf16(acc[mt][nt], af[mt], bfr[nt]);
        }
        __syncthreads();
    }

    float* out = scratch_f32(outid);
    const int row0 = blockIdx.y * 128 + wm * 32;
    float p[4][3];
#pragma unroll
    for (int i = 0; i < 4; i++)
#pragma unroll
        for (int c = 0; c < 3; c++) p[i][c] = 0.0f;

#pragma unroll
    for (int nt = 0; nt < 8; nt++) {
        int cc0 = wn*64 + nt*8 + (lane & 3)*2;
        int cc1 = cc0 + 1;
        float bb0 = b2s[cc0], bb1 = b2s[cc1];
        float h00 = fmaxf(acc[0][nt][0] + bb0, 0.0f);
        float h01 = fmaxf(acc[0][nt][1] + bb1, 0.0f);
        float h02 = fmaxf(acc[0][nt][2] + bb0, 0.0f);
        float h03 = fmaxf(acc[0][nt][3] + bb1, 0.0f);
        float h10 = fmaxf(acc[1][nt][0] + bb0, 0.0f);
        float h11 = fmaxf(acc[1][nt][1] + bb1, 0.0f);
        float h12 = fmaxf(acc[1][nt][2] + bb0, 0.0f);
        float h13 = fmaxf(acc[1][nt][3] + bb1, 0.0f);
#pragma unroll
        for (int c = 0; c < 3; c++) {
            float w0 = w3s[cc0*3 + c], w1v = w3s[cc1*3 + c];
            p[0][c] = fmaf(h00, w0, fmaf(h01, w1v, p[0][c]));
            p[1][c] = fmaf(h02, w0, fmaf(h03, w1v, p[1][c]));
            p[2][c] = fmaf(h10, w0, fmaf(h11, w1v, p[2][c]));
            p[3][c] = fmaf(h12, w0, fmaf(h13, w1v, p[3][c]));
        }
    }
#pragma unroll
    for (int o = 1; o <= 2; o <<= 1)
#pragma unroll
        for (int i = 0; i < 4; i++)
#pragma unroll
            for (int c = 0; c < 3; c++)
                p[i][c] += __shfl_xor_sync(0xffffffffu, p[i][c], o);

    if ((lane & 3) == 0) {
        bool addb3 = (blockIdx.x == 0) && (wn == 0);
#pragma unroll
        for (int i = 0; i < 4; i++) {
            int r = row0 + (i >> 1)*16 + (lane >> 2) + (i & 1)*8;
#pragma unroll
            for (int c = 0; c < 3; c++) {
                float v = p[i][c];
                if (addb3) v += b3[c];
                atomicAdd(&out[r*3 + c], v);
            }
        }
    }
}

// ---------------------------------------------------------------------------
// Small per-row MLP
// ---------------------------------------------------------------------------
__global__ void mlp_row_kernel(int xid, int xkeys, const float* __restrict__ W,
                               const float* __restrict__ bias, int yid,
                               int K, int N, int act)
{
    __shared__ float sx[1024];
    float* Y = scratch_f32(yid);
    int b = blockIdx.y;
    int col = blockIdx.x * blockDim.x + threadIdx.x;
    if (xkeys) {
        for (int k = threadIdx.x; k < K; k += blockDim.x)
            sx[k] = unfkey(g_featkeys[b*K + k]);
    } else {
        const float* X = scratch_f32(xid);
        for (int k = threadIdx.x; k < K; k += blockDim.x) sx[k] = X[b*K + k];
    }
    __syncthreads();
    float s0 = 0.0f, s1 = 0.0f, s2 = 0.0f, s3 = 0.0f;
    for (int k = 0; k < K; k += 4) {
        s0 = fmaf(sx[k+0], W[(size_t)(k+0)*N + col], s0);
        s1 = fmaf(sx[k+1], W[(size_t)(k+1)*N + col], s1);
        s2 = fmaf(sx[k+2], W[(size_t)(k+2)*N + col], s2);
        s3 = fmaf(sx[k+3], W[(size_t)(k+3)*N + col], s3);
    }
    float s = ((s0 + s1) + (s2 + s3)) + bias[col];
    if (act) s = fmaxf(s, 0.0f);
    Y[b*N + col] = s;
}

// ---------------------------------------------------------------------------
// pos + fe (bf16), 256 threads: fe[bg] = feat[b] + pos(centers[bg])
// ---------------------------------------------------------------------------
__global__ void __launch_bounds__(256) posfe_kernel(
    const float* __restrict__ w1, const float* __restrict__ b1,
    const float* __restrict__ w2, const float* __restrict__ b2)
{
    int bg = blockIdx.x, t = threadIdx.x, b = bg >> 6;
    __shared__ float h[128];
    float cx = g_centers[bg*3], cy = g_centers[bg*3+1], cz = g_centers[bg*3+2];
    if (t < 128) {
        float v = cx*w1[t] + cy*w1[128+t] + cz*w1[256+t] + b1[t];
        h[t] = gelu_exact(v);
    }
    __syncthreads();
    for (int q = 0; q < 4; q++) {
        int j = (q << 8) + t;
        float s = 0.0f;
#pragma unroll 8
        for (int k = 0; k < 128; k++) s = fmaf(h[k], w2[k*1024 + j], s);
        float feat = unfkey(g_featkeys[b*1024 + j]);
        g_feb[bg*1024 + j] = __float2bfloat16(s + b2[j] + feat);
    }
}

// ---------------------------------------------------------------------------
// Chamfer fine
// ---------------------------------------------------------------------------
__global__ void chamfer_fine_kernel() {
    int bg = blockIdx.x, t = threadIdx.x;  // 128 threads
    __shared__ float F[108], Nn[96], rm[36], cm[32];
    for (int i = t; i < 108; i += 128) F[i] = g_fold2[bg*108 + i];
    for (int i = t; i < 96;  i += 128) Nn[i] = g_neigh[bg*96 + i];
    __syncthreads();
    if (t < 36) {
        float fx = F[t*3], fy = F[t*3+1], fz = F[t*3+2], mn = FLT_MAX;
        for (int j = 0; j < 32; j++) {
            float dx = fx-Nn[j*3], dy = fy-Nn[j*3+1], dz = fz-Nn[j*3+2];
            mn = fminf(mn, dx*dx + dy*dy + dz*dz);
        }
        rm[t] = mn;
    } else if (t < 68) {
        int j = t - 36;
        float nx = Nn[j*3], ny = Nn[j*3+1], nz = Nn[j*3+2], mn = FLT_MAX;
        for (int i = 0; i < 36; i++) {
            float dx = F[i*3]-nx, dy = F[i*3+1]-ny, dz = F[i*3+2]-nz;
            mn = fminf(mn, dx*dx + dy*dy + dz*dz);
        }
        cm[j] = mn;
    }
    __syncthreads();
    if (t == 0) {
        float s = 0.0f;
        for (int i = 0; i < 36; i++) s += rm[i];
        atomicAdd(&g_acc[0], s);
        s = 0.0f;
        for (int j = 0; j < 32; j++) s += cm[j];
        atomicAdd(&g_acc[1], s);
    }
}

// ---------------------------------------------------------------------------
// Chamfer coarse
// ---------------------------------------------------------------------------
__global__ void __launch_bounds__(512) chamfer_coarse_kernel() {
    int t = threadIdx.x;
    __shared__ float C[1536], Ce[1536], s1[512], s2[512];
    for (int i = t; i < 1536; i += 512) { C[i] = g_coarse[i]; Ce[i] = g_centers[i]; }
    __syncthreads();
    int b = t >> 6, i = t & 63;
    const float* cb = &C[b*192];
    const float* eb = &Ce[b*192];
    float x = cb[i*3], y = cb[i*3+1], z = cb[i*3+2], mn = FLT_MAX;
    for (int j = 0; j < 64; j++) {
        float dx = x-eb[j*3], dy = y-eb[j*3+1], dz = z-eb[j*3+2];
        mn = fminf(mn, dx*dx + dy*dy + dz*dz);
    }
    s1[t] = mn;
    float x2 = eb[i*3], y2 = eb[i*3+1], z2 = eb[i*3+2];
    mn = FLT_MAX;
    for (int j = 0; j < 64; j++) {
        float dx = x2-cb[j*3], dy = y2-cb[j*3+1], dz = z2-cb[j*3+2];
        mn = fminf(mn, dx*dx + dy*dy + dz*dz);
    }
    s2[t] = mn;
    __syncthreads();
    for (int s = 256; s; s >>= 1) {
        if (t < s) { s1[t] += s1[t+s]; s2[t] += s2[t+s]; }
        __syncthreads();
    }
    if (t == 0) { g_acc[2] = s1[0]; g_acc[3] = s2[0]; }
}

__global__ void finalize_kernel(float* __restrict__ out) {
    out[0] = g_acc[0] / (float)(FROWS) + g_acc[1] / (float)(BGROUPS*GS);
    out[1] = g_acc[2] / 512.0f + g_acc[3] / 512.0f;
}

// ---------------------------------------------------------------------------
// launch — multi-stream DAG (R9 structure; w3t + fold-zero hidden on sC)
// ---------------------------------------------------------------------------
extern "C" void kernel_launch(void* const* d_in, const int* in_sizes, int n_in,
                              void* d_out, int out_size)
{
    (void)in_sizes; (void)n_in; (void)out_size;
    const float* corrupted = (const float*)d_in[0];
    const float* pts       = (const float*)d_in[1];
    const float* enc_w1 = (const float*)d_in[2];
    const float* enc_b1 = (const float*)d_in[3];
    const float* enc_w2 = (const float*)d_in[4];
    const float* enc_b2 = (const float*)d_in[5];
    const float* enc_w3 = (const float*)d_in[6];
    const float* enc_b3 = (const float*)d_in[7];
    const float* pe_w1  = (const float*)d_in[8];
    const float* pe_b1  = (const float*)d_in[9];
    const float* pe_w2  = (const float*)d_in[10];
    const float* pe_b2  = (const float*)d_in[11];
    const float* cp_w1  = (const float*)d_in[12];
    const float* cp_b1  = (const float*)d_in[13];
    const float* cp_w2  = (const float*)d_in[14];
    const float* cp_b2  = (const float*)d_in[15];
    const float* cp_w3  = (const float*)d_in[16];
    const float* cp_b3  = (const float*)d_in[17];
    const float* f1_w1  = (const float*)d_in[18];
    const float* f1_b1  = (const float*)d_in[19];
    const float* f1_w2  = (const float*)d_in[20];
    const float* f1_b2  = (const float*)d_in[21];
    const float* f1_w3  = (const float*)d_in[22];
    const float* f1_b3  = (const float*)d_in[23];
    const float* f2_w1  = (const float*)d_in[24];
    const float* f2_b1  = (const float*)d_in[25];
    const float* f2_w2  = (const float*)d_in[26];
    const float* f2_b2  = (const float*)d_in[27];
    const float* f2_w3  = (const float*)d_in[28];
    const float* f2_b3  = (const float*)d_in[29];
    float* out = (float*)d_out;

    // one-time host resources (no device memory involved)
    static cudaStream_t sB = nullptr, sC = nullptr;
    static cudaEvent_t eFork, eGeo, eEnc, ePos, eFeA2, eCoarse, eWf, eW3;
    if (sB == nullptr) {
        cudaStreamCreateWithFlags(&sB, cudaStreamNonBlocking);
        cudaStreamCreateWithFlags(&sC, cudaStreamNonBlocking);
        cudaEventCreateWithFlags(&eFork,   cudaEventDisableTiming);
        cudaEventCreateWithFlags(&eGeo,    cudaEventDisableTiming);
        cudaEventCreateWithFlags(&eEnc,    cudaEventDisableTiming);
        cudaEventCreateWithFlags(&ePos,    cudaEventDisableTiming);
        cudaEventCreateWithFlags(&eFeA2,   cudaEventDisableTiming);
        cudaEventCreateWithFlags(&eCoarse, cudaEventDisableTiming);
        cudaEventCreateWithFlags(&eWf,     cudaEventDisableTiming);
        cudaEventCreateWithFlags(&eW3,     cudaEventDisableTiming);
    }

    // main: minimal init
    zero_main_kernel<<<32, 256>>>();
    cudaEventRecord(eFork, 0);

    // stream B: geometry
    cudaStreamWaitEvent(sB, eFork, 0);
    fps_kernel<<<NB, 1024, 0, sB>>>(pts);
    knn_kernel<<<BGROUPS, 256, 0, sB>>>(pts);
    cudaEventRecord(eGeo, sB);

    // stream C: w3 transpose (needed by encL3), fold zero + fold transposes
    cudaStreamWaitEvent(sC, eFork, 0);
    wtrans_one<<<1024, 256, 0, sC>>>(enc_w3, 256, 1024, BID_W3T);
    cudaEventRecord(eW3, sC);
    zero_fold_kernel<<<(FROWS*3 + 255)/256, 256, 0, sC>>>();
    wtrans_fold<<<dim3(2048, 4), 256, 0, sC>>>(f1_w1, f2_w1, f1_w2, f2_w2);
    cudaEventRecord(eWf, sC);

    // main: w2 transpose + encoder
    wtrans_one<<<128, 256>>>(enc_w2, 128, 256, BID_W2T);
    enc12_kernel<<<dim3(2, 512), 256>>>(corrupted, enc_w1, enc_b1, enc_b2);
    cudaStreamWaitEvent(0, eW3, 0);
    mma_gemm<2><<<dim3(8, 512), 256>>>(BID_H2, BID_W3T, enc_b3, 0, 1024, 256, NPTS);
    cudaEventRecord(eEnc, 0);

    // stream C: coarse MLP chain + coarse chamfer
    cudaStreamWaitEvent(sC, eEnc, 0);
    mlp_row_kernel<<<dim3(8, NB), 128, 0, sC>>>(0, 1, cp_w1, cp_b1, FID_C1, 1024, 1024, 1);
    mlp_row_kernel<<<dim3(8, NB), 128, 0, sC>>>(FID_C1, 0, cp_w2, cp_b2, FID_C2, 1024, 1024, 1);
    mlp_row_kernel<<<dim3(1, NB), 192, 0, sC>>>(FID_C2, 0, cp_w3, cp_b3, FID_COARSE, 1024, 192, 0);
    cudaStreamWaitEvent(sC, eGeo, 0);
    chamfer_coarse_kernel<<<1, 512, 0, sC>>>();
    cudaEventRecord(eCoarse, sC);

    // main: posfe (centers + featkeys)
    cudaStreamWaitEvent(0, eGeo, 0);
    posfe_kernel<<<BGROUPS, 256>>>(pe_w1, pe_b1, pe_w2, pe_b2);
    cudaEventRecord(ePos, 0);

    // feA1 main (needs f1w1t), feA2 on stream B (needs f2w1t + fe)
    cudaStreamWaitEvent(0, eWf, 0);
    mma_gemm<0><<<dim3(4, 4), 256>>>(BID_FE, BID_F1W1T, f1_b1, FID_FEA1, 512, 1024, 0);
    cudaStreamWaitEvent(sB, ePos, 0);
    cudaStreamWaitEvent(sB, eWf, 0);
    mma_gemm<0><<<dim3(4, 4), 256, 0, sB>>>(BID_FE, BID_F2W1T, f2_b1, FID_FEA2, 512, 1024, 0);
    cudaEventRecord(eFeA2, sB);

    // fold stage 1 (fused foldpre + GEMM + W3 projection)
    fold_gemm_fused<<<dim3(4, 144), 256>>>(FID_FEA1, 1, f1_w1, BID_F1W2T,
                                           f1_b2, f1_w3, f1_b3, FID_FOLD1);

    // fold stage 2 (needs feA2 + fold1)
    cudaStreamWaitEvent(0, eFeA2, 0);
    fold_gemm_fused<<<dim3(4, 144), 256>>>(FID_FEA2, 2, f2_w1, BID_F2W2T,
                                           f2_b2, f2_w3, f2_b3, FID_FOLD2);

    // fine chamfer
    chamfer_fine_kernel<<<BGROUPS, 128>>>();

    // join coarse chain, finalize
    cudaStreamWaitEvent(0, eCoarse, 0);
    finalize_kernel<<<1, 1>>>(out);
}

// round 14
// speedup vs baseline: 1.6658x; 1.0160x over previous
#include <cuda_runtime.h>
#include <cuda_bf16.h>
#include <math.h>
#include <float.h>

// ---------------------------------------------------------------------------
// Problem constants
// ---------------------------------------------------------------------------
#define NB       8
#define NPTS     8192
#define NC       64
#define GS       32
#define BGROUPS  512
#define GRID_PTS 36
#define FROWS    (BGROUPS*GRID_PTS)   // 18432
#define ENC_ROWS (NB*NPTS)            // 65536

typedef __nv_bfloat16 bf16;

// ---------------------------------------------------------------------------
// Scratch (device globals; no allocation anywhere)
// ---------------------------------------------------------------------------
__device__ bf16     g_h2b[ENC_ROWS*256];
__device__ bf16     g_feb[BGROUPS*1024];
__device__ bf16     g_w2t[256*128];
__device__ bf16     g_w3t[1024*256];
__device__ bf16     g_f1w1t[512*1024];
__device__ bf16     g_f2w1t[512*1024];
__device__ bf16     g_f1w2t[512*512];
__device__ bf16     g_f2w2t[512*512];

__device__ float    g_feA1[BGROUPS*512];
__device__ float    g_feA2[BGROUPS*512];
__device__ unsigned g_featkeys[NB*1024];
__device__ float    g_centers[BGROUPS*3];
__device__ float    g_neigh[BGROUPS*GS*3];
__device__ float    g_fold1[FROWS*3];
__device__ float    g_fold2[FROWS*3];
__device__ float    g_c1[NB*1024];
__device__ float    g_c2[NB*1024];
__device__ float    g_coarse[NB*192];
__device__ float    g_acc[4];

__constant__ float c_lin[6] = {-0.3f,-0.18f,-0.06f,0.06f,0.18f,0.3f};

// bf16 scratch ids
#define BID_H2     0
#define BID_FE     1
#define BID_W2T    2
#define BID_W3T    3
#define BID_F1W1T  4
#define BID_F2W1T  5
#define BID_F1W2T  6
#define BID_F2W2T  7

// f32 scratch ids
#define FID_FEA1   0
#define FID_FEA2   1
#define FID_C1     2
#define FID_C2     3
#define FID_COARSE 4
#define FID_FOLD1  5
#define FID_FOLD2  6

__device__ __forceinline__ bf16* scratch_bf16(int id) {
    switch (id) {
        case BID_H2:    return g_h2b;
        case BID_FE:    return g_feb;
        case BID_W2T:   return g_w2t;
        case BID_W3T:   return g_w3t;
        case BID_F1W1T: return g_f1w1t;
        case BID_F2W1T: return g_f2w1t;
        case BID_F1W2T: return g_f1w2t;
        default:        return g_f2w2t;
    }
}
__device__ __forceinline__ float* scratch_f32(int id) {
    switch (id) {
        case FID_FEA1:  return g_feA1;
        case FID_FEA2:  return g_feA2;
        case FID_C1:    return g_c1;
        case FID_C2:    return g_c2;
        case FID_COARSE:return g_coarse;
        case FID_FOLD1: return g_fold1;
        default:        return g_fold2;
    }
}

__device__ __forceinline__ unsigned fkey(float f) {
    unsigned u = __float_as_uint(f);
    return (u & 0x80000000u) ? ~u : (u | 0x80000000u);
}
__device__ __forceinline__ float unfkey(unsigned k) {
    return __uint_as_float((k & 0x80000000u) ? (k & 0x7fffffffu) : ~k);
}

__device__ __forceinline__ float gelu_exact(float x) {
    return 0.5f * x * (1.0f + erff(x * 0.7071067811865476f));
}

__device__ __forceinline__ void cpa16(unsigned dst, const void* src) {
    asm volatile("cp.async.cg.shared.global [%0], [%1], 16;" :: "r"(dst), "l"(src));
}

__device__ __forceinline__ void ldsm4(unsigned& r0, unsigned& r1, unsigned& r2,
                                      unsigned& r3, unsigned addr) {
    asm volatile("ldmatrix.sync.aligned.m8n8.x4.shared.b16 {%0,%1,%2,%3}, [%4];"
        : "=r"(r0), "=r"(r1), "=r"(r2), "=r"(r3) : "r"(addr));
}

__device__ __forceinline__ void mma_bf16(float* c, const unsigned* a, const unsigned* b) {
    asm volatile(
        "mma.sync.aligned.m16n8k16.row.col.f32.bf16.bf16.f32 "
        "{%0,%1,%2,%3}, {%4,%5,%6,%7}, {%8,%9}, {%0,%1,%2,%3};"
        : "+f"(c[0]), "+f"(c[1]), "+f"(c[2]), "+f"(c[3])
        : "r"(a[0]), "r"(a[1]), "r"(a[2]), "r"(a[3]), "r"(b[0]), "r"(b[1]));
}

__device__ __forceinline__ void wredmax(float& v, int& i) {
#pragma unroll
    for (int o = 16; o; o >>= 1) {
        float v2 = __shfl_xor_sync(0xffffffffu, v, o);
        int   i2 = __shfl_xor_sync(0xffffffffu, i, o);
        if (v2 > v || (v2 == v && i2 < i)) { v = v2; i = i2; }
    }
}
__device__ __forceinline__ void wredmin(float& v, int& i) {
#pragma unroll
    for (int o = 16; o; o >>= 1) {
        float v2 = __shfl_xor_sync(0xffffffffu, v, o);
        int   i2 = __shfl_xor_sync(0xffffffffu, i, o);
        if (v2 < v || (v2 == v && i2 < i)) { v = v2; i = i2; }
    }
}

// ---------------------------------------------------------------------------
// init
// ---------------------------------------------------------------------------
__global__ void zero_main_kernel() {
    int i = blockIdx.x * 256 + threadIdx.x;
    if (i < NB*1024) g_featkeys[i] = 0u;
    if (i < 4)       g_acc[i] = 0.0f;
}
__global__ void zero_fold_kernel() {
    int i = blockIdx.x * 256 + threadIdx.x;
    if (i < FROWS*3) { g_fold1[i] = 0.0f; g_fold2[i] = 0.0f; }
}

// ---------------------------------------------------------------------------
// weight transpose + bf16: out[n*K+k] = bf16(W[k*N+n])
// ---------------------------------------------------------------------------
__global__ void wtrans_one(const float* __restrict__ W, int K, int N, int bid) {
    bf16* out = scratch_bf16(bid);
    int i = blockIdx.x * 256 + threadIdx.x;
    if (i < K * N) {
        int n = i / K, k = i - n * K;
        out[i] = __float2bfloat16(W[(size_t)k * N + n]);
    }
}

__global__ void wtrans_fold(const float* __restrict__ fw1a, const float* __restrict__ fw1b,
                            const float* __restrict__ fw2a, const float* __restrict__ fw2b)
{
    const float* W; int K, N; bf16* out;
    switch (blockIdx.y) {
        case 0: W = fw1a; K = 1024; N = 512; out = g_f1w1t; break;
        case 1: W = fw1b; K = 1024; N = 512; out = g_f2w1t; break;
        case 2: W = fw2a; K = 512;  N = 512; out = g_f1w2t; break;
        default:W = fw2b; K = 512;  N = 512; out = g_f2w2t; break;
    }
    int i = blockIdx.x * 256 + threadIdx.x;
    if (i < K * N) {
        int n = i / K, k = i - n * K;
        out[i] = __float2bfloat16(W[(size_t)k * N + n]);
    }
}

// ---------------------------------------------------------------------------
// Farthest point sampling
// ---------------------------------------------------------------------------
__global__ void __launch_bounds__(1024) fps_kernel(const float* __restrict__ pts) {
    int b = blockIdx.x, t = threadIdx.x;
    int lane = t & 31, wid = t >> 5;
    const float* P = pts + (size_t)b * NPTS * 3;
    __shared__ float sv[32];
    __shared__ int   si[32];
    __shared__ float cur[3];

    float px[8], py[8], pz[8], dd[8];
#pragma unroll
    for (int i = 0; i < 8; i++) {
        int p = (t << 3) + i;
        px[i] = P[p*3]; py[i] = P[p*3+1]; pz[i] = P[p*3+2];
    }
    if (t == 0) {
        cur[0] = P[0]; cur[1] = P[1]; cur[2] = P[2];
        g_centers[b*192+0] = P[0]; g_centers[b*192+1] = P[1]; g_centers[b*192+2] = P[2];
    }
    __syncthreads();
    float cx = cur[0], cy = cur[1], cz = cur[2];
#pragma unroll
    for (int i = 0; i < 8; i++) {
        float dx = px[i]-cx, dy = py[i]-cy, dz = pz[i]-cz;
        dd[i] = dx*dx + dy*dy + dz*dz;
    }
    for (int it = 1; it < NC; it++) {
        float bv = dd[0]; int bi = (t << 3);
#pragma unroll
        for (int i = 1; i < 8; i++)
            if (dd[i] > bv) { bv = dd[i]; bi = (t << 3) + i; }
        wredmax(bv, bi);
        if (lane == 0) { sv[wid] = bv; si[wid] = bi; }
        __syncthreads();
        if (wid == 0) {
            float v = sv[lane]; int i = si[lane];
            wredmax(v, i);
            if (lane == 0) {
                cur[0] = P[i*3]; cur[1] = P[i*3+1]; cur[2] = P[i*3+2];
                g_centers[b*192 + it*3+0] = cur[0];
                g_centers[b*192 + it*3+1] = cur[1];
                g_centers[b*192 + it*3+2] = cur[2];
            }
        }
        __syncthreads();
        cx = cur[0]; cy = cur[1]; cz = cur[2];
#pragma unroll
        for (int i = 0; i < 8; i++) {
            float dx = px[i]-cx, dy = py[i]-cy, dz = pz[i]-cz;
            dd[i] = fminf(dd[i], dx*dx + dy*dy + dz*dz);
        }
    }
}

// ---------------------------------------------------------------------------
// 32-NN grouping — incremental argmin
// ---------------------------------------------------------------------------
__global__ void __launch_bounds__(256) knn_kernel(const float* __restrict__ pts) {
    int bg = blockIdx.x, b = bg >> 6, t = threadIdx.x;
    int lane = t & 31, wid = t >> 5;
    const float* P = pts + (size_t)b * NPTS * 3;
    __shared__ float sd[NPTS];
    __shared__ float sv[8];
    __shared__ int   si[8];
    __shared__ int   swin;
    float cx = g_centers[bg*3], cy = g_centers[bg*3+1], cz = g_centers[bg*3+2];
    for (int p = t; p < NPTS; p += 256) {
        float dx = P[p*3]-cx, dy = P[p*3+1]-cy, dz = P[p*3+2]-cz;
        sd[p] = dx*dx + dy*dy + dz*dz;
    }
    __syncthreads();

    const int base = t << 5;
    float mv = FLT_MAX; int mi = base;
#pragma unroll 8
    for (int j = 0; j < 32; j++) {
        float v = sd[base + j];
        if (v < mv) { mv = v; mi = base + j; }
    }

    for (int k = 0; k < GS; k++) {
        float bv = mv; int bi = mi;
        wredmin(bv, bi);
        if (lane == 0) { sv[wid] = bv; si[wid] = bi; }
        __syncthreads();
        if (t < 32) {
            float v = (lane < 8) ? sv[lane] : FLT_MAX;
            int   i = (lane < 8) ? si[lane] : NPTS;
            wredmin(v, i);
            if (lane == 0) {
                swin = i;
                g_neigh[(bg*GS+k)*3+0] = P[i*3+0] - cx;
                g_neigh[(bg*GS+k)*3+1] = P[i*3+1] - cy;
                g_neigh[(bg*GS+k)*3+2] = P[i*3+2] - cz;
            }
        }
        __syncthreads();
        int win = swin;
        if ((win >> 5) == t) {
            sd[win] = FLT_MAX;
            mv = FLT_MAX; mi = base;
#pragma unroll 8
            for (int j = 0; j < 32; j++) {
                float v = sd[base + j];
                if (v < mv) { mv = v; mi = base + j; }
            }
        }
        __syncthreads();
    }
}

// ---------------------------------------------------------------------------
// Fused enc layer1 + layer2 GEMM — full-resident A+B, single barrier.
// h2 = bf16(relu( relu(x@w1+b1) @ w2 + b2 )); dynamic smem ~70KB.
// ---------------------------------------------------------------------------
#define SR12 136
#define ENC12_SMEM (2*128*SR12*2)

__global__ void __launch_bounds__(256) enc12_kernel(
    const float* __restrict__ x, const float* __restrict__ w1,
    const float* __restrict__ b1, const float* __restrict__ b2)
{
    extern __shared__ __align__(16) bf16 dyn12[];
    bf16* As = dyn12;                 // 128 x 136
    bf16* Bs = dyn12 + 128*SR12;      // 128 x 136
    __shared__ float  sx[384];
    __shared__ float4 swc[128];

    const int tid = threadIdx.x, lane = tid & 31, wid = tid >> 5;
    const int wm = wid & 3, wn = wid >> 2;
    const int br = blockIdx.y, bc = blockIdx.x;

    const bf16* B = g_w2t + (size_t)(bc * 128) * 128;
    const unsigned bBase = (unsigned)__cvta_generic_to_shared(Bs);
    const unsigned aBase = (unsigned)__cvta_generic_to_shared(As);

#pragma unroll
    for (int i = 0; i < 8; i++) {
        int chunk = i * 256 + tid;
        int row = chunk >> 4, seg = chunk & 15;
        cpa16(bBase + (row*SR12 + seg*8)*2, B + row*128 + seg*8);
    }
    asm volatile("cp.async.commit_group;");

    if (tid < 96) *(float4*)&sx[tid*4] = *(const float4*)(x + (size_t)br*384 + tid*4);
    if (tid < 128) {
        float4 w; w.x = w1[tid]; w.y = w1[128+tid]; w.z = w1[256+tid]; w.w = b1[tid];
        swc[tid] = w;
    }
    asm volatile("cp.async.wait_group 0;");
    __syncthreads();

    // fill full A (128 x 128): thread owns row r, 64-k half
    {
        const int r = tid >> 1;
        const int kb0 = (tid & 1) * 64;
        const float x0 = sx[r*3], x1 = sx[r*3+1], x2 = sx[r*3+2];
#pragma unroll
        for (int blk = 0; blk < 8; blk++) {
            unsigned pk[4];
#pragma unroll
            for (int q = 0; q < 4; q++) {
                int k = kb0 + blk*8 + q*2;
                float4 wa = swc[k], wb = swc[k+1];
                float va = fmaxf(fmaf(x0, wa.x, fmaf(x1, wa.y, fmaf(x2, wa.z, wa.w))), 0.0f);
                float vb = fmaxf(fmaf(x0, wb.x, fmaf(x1, wb.y, fmaf(x2, wb.z, wb.w))), 0.0f);
                __nv_bfloat162 p = __floats2bfloat162_rn(va, vb);
                pk[q] = *(unsigned*)&p;
            }
            *(uint4*)&As[r*SR12 + kb0 + blk*8] = make_uint4(pk[0], pk[1], pk[2], pk[3]);
        }
    }
    __syncthreads();

    float acc[2][8][4];
#pragma unroll
    for (int mt = 0; mt < 2; mt++)
#pragma unroll
        for (int nt = 0; nt < 8; nt++)
#pragma unroll
            for (int j = 0; j < 4; j++) acc[mt][nt][j] = 0.0f;

    unsigned aoff[2], boff[4];
#pragma unroll
    for (int mt = 0; mt < 2; mt++)
        aoff[mt] = ((wm*32 + mt*16 + (lane & 15)) * SR12 + ((lane >> 4) << 3)) * 2;
#pragma unroll
    for (int ntp = 0; ntp < 4; ntp++)
        boff[ntp] = ((wn*64 + ntp*16 + ((lane & 16) >> 1) + (lane & 7)) * SR12
                     + (lane & 8)) * 2;

#pragma unroll
    for (int kt = 0; kt < 8; kt++) {
        unsigned af[2][4], bfr[8][2];
#pragma unroll
        for (int mt = 0; mt < 2; mt++)
            ldsm4(af[mt][0], af[mt][1], af[mt][2], af[mt][3], aBase + aoff[mt] + kt*32);
#pragma unroll
        for (int ntp = 0; ntp < 4; ntp++) {
            unsigned r0, r1, r2, r3;
            ldsm4(r0, r1, r2, r3, bBase + boff[ntp] + kt*32);
            bfr[2*ntp][0] = r0;   bfr[2*ntp][1] = r1;
            bfr[2*ntp+1][0] = r2; bfr[2*ntp+1][1] = r3;
        }
#pragma unroll
        for (int mt = 0; mt < 2; mt++)
#pragma unroll
            for (int nt = 0; nt < 8; nt++)
                mma_bf16(acc[mt][nt], af[mt], bfr[nt]);
    }

    const int row0 = br*128 + wm*32;
    const int col0 = bc*128 + wn*64;
#pragma unroll
    for (int mt = 0; mt < 2; mt++) {
        int rr = row0 + mt*16 + (lane >> 2);
#pragma unroll
        for (int nt = 0; nt < 8; nt++) {
            int c = col0 + nt*8 + (lane & 3)*2;
            float bb0 = b2[c], bb1 = b2[c + 1];
            __nv_bfloat162 v0 = __floats2bfloat162_rn(
                fmaxf(acc[mt][nt][0] + bb0, 0.0f), fmaxf(acc[mt][nt][1] + bb1, 0.0f));
            __nv_bfloat162 v1 = __floats2bfloat162_rn(
                fmaxf(acc[mt][nt][2] + bb0, 0.0f), fmaxf(acc[mt][nt][3] + bb1, 0.0f));
            *(__nv_bfloat162*)(g_h2b + (size_t)rr*256 + c)       = v0;
            *(__nv_bfloat162*)(g_h2b + (size_t)(rr + 8)*256 + c) = v1;
        }
    }
}

// ---------------------------------------------------------------------------
// BF16 mma GEMM. EPI: 0 = fp32 store (+optional bias); 2 = bias + batch col-max.
// ---------------------------------------------------------------------------
#define SROW 40
#define STAGE_B (128*SROW*2)

template<int EPI>
__global__ void __launch_bounds__(256) mma_gemm(
    int aid, int bid, const float* __restrict__ bias, int cid,
    int N, int K, int rows_per_batch)
{
    __shared__ __align__(16) bf16 As[2][128*SROW];
    __shared__ __align__(16) bf16 Bs[2][128*SROW];
    __shared__ unsigned cmax[128];

    const bf16* A = scratch_bf16(aid) + (size_t)(blockIdx.y * 128) * K;
    const bf16* B = scratch_bf16(bid) + (size_t)(blockIdx.x * 128) * K;

    const int tid  = threadIdx.x;
    const int lane = tid & 31, wid = tid >> 5;
    const int wm = wid & 3, wn = wid >> 2;

    float acc[2][8][4];
#pragma unroll
    for (int mt = 0; mt < 2; mt++)
#pragma unroll
        for (int nt = 0; nt < 8; nt++)
#pragma unroll
            for (int j = 0; j < 4; j++) acc[mt][nt][j] = 0.0f;

    const unsigned aBase = (unsigned)__cvta_generic_to_shared(&As[0][0]);
    const unsigned bBase = (unsigned)__cvta_generic_to_shared(&Bs[0][0]);

    unsigned aoff[2], boff[4];
#pragma unroll
    for (int mt = 0; mt < 2; mt++)
        aoff[mt] = ((wm*32 + mt*16 + (lane & 15)) * SROW + ((lane >> 4) << 3)) * 2;
#pragma unroll
    for (int ntp = 0; ntp < 4; ntp++)
        boff[ntp] = ((wn*64 + ntp*16 + ((lane & 16) >> 1) + (lane & 7)) * SROW
                     + (lane & 8)) * 2;

    auto load_tile = [&](int s, int k0) {
#pragma unroll
        for (int i = 0; i < 2; i++) {
            int c = tid + (i << 8);
            int row = c >> 2, seg = c & 3;
            unsigned d = row * SROW + seg * 8;
            cpa16(aBase + s*STAGE_B + d*2, A + (size_t)row*K + k0 + seg*8);
            cpa16(bBase + s*STAGE_B + d*2, B + (size_t)row*K + k0 + seg*8);
        }
        asm volatile("cp.async.commit_group;");
    };

    load_tile(0, 0);
    const int KT = K >> 5;
    for (int kt = 0; kt < KT; kt++) {
        if (kt + 1 < KT) {
            load_tile((kt + 1) & 1, (kt + 1) << 5);
            asm volatile("cp.async.wait_group 1;");
        } else {
            asm volatile("cp.async.wait_group 0;");
        }
        __syncthreads();
        unsigned sOff = (kt & 1) * STAGE_B;
#pragma unroll
        for (int ks = 0; ks < 2; ks++) {
            unsigned af[2][4], bfr[8][2];
#pragma unroll
            for (int mt = 0; mt < 2; mt++)
                ldsm4(af[mt][0], af[mt][1], af[mt][2], af[mt][3],
                      aBase + sOff + aoff[mt] + ks*32);
#pragma unroll
            for (int ntp = 0; ntp < 4; ntp++) {
                unsigned r0, r1, r2, r3;
                ldsm4(r0, r1, r2, r3, bBase + sOff + boff[ntp] + ks*32);
                bfr[2*ntp][0] = r0;   bfr[2*ntp][1] = r1;
                bfr[2*ntp+1][0] = r2; bfr[2*ntp+1][1] = r3;
            }
#pragma unroll
            for (int mt = 0; mt < 2; mt++)
#pragma unroll
                for (int nt = 0; nt < 8; nt++)
                    mma_bf16(acc[mt][nt], af[mt], bfr[nt]);
        }
        __syncthreads();
    }

    const int row0  = blockIdx.y * 128 + wm * 32;
    const int col0g = blockIdx.x * 128 + wn * 64;

    if (EPI == 0) {
        float* C = scratch_f32(cid);
#pragma unroll
        for (int mt = 0; mt < 2; mt++) {
            int r = row0 + mt*16 + (lane >> 2);
#pragma unroll
            for (int nt = 0; nt < 8; nt++) {
                int c = col0g + nt*8 + (lane & 3)*2;
                float bb0 = bias ? bias[c]     : 0.0f;
                float bb1 = bias ? bias[c + 1] : 0.0f;
                float2 v0 = {acc[mt][nt][0] + bb0, acc[mt][nt][1] + bb1};
                float2 v1 = {acc[mt][nt][2] + bb0, acc[mt][nt][3] + bb1};
                *(float2*)(C + (size_t)r*N + c)       = v0;
                *(float2*)(C + (size_t)(r + 8)*N + c) = v1;
            }
        }
    } else {
        if (tid < 128) cmax[tid] = 0u;
        __syncthreads();
#pragma unroll
        for (int nt = 0; nt < 8; nt++) {
            int cc = wn*64 + nt*8 + (lane & 3)*2;
            float b0 = bias[blockIdx.x*128 + cc];
            float b1 = bias[blockIdx.x*128 + cc + 1];
            float m0 = fmaxf(fmaxf(acc[0][nt][0], acc[0][nt][2]),
                             fmaxf(acc[1][nt][0], acc[1][nt][2])) + b0;
            float m1 = fmaxf(fmaxf(acc[0][nt][1], acc[0][nt][3]),
                             fmaxf(acc[1][nt][1], acc[1][nt][3])) + b1;
#pragma unroll
            for (int o = 4; o < 32; o <<= 1) {
                m0 = fmaxf(m0, __shfl_xor_sync(0xffffffffu, m0, o));
                m1 = fmaxf(m1, __shfl_xor_sync(0xffffffffu, m1, o));
            }
            if (lane < 4) {
                atomicMax(&cmax[cc],     fkey(m0));
                atomicMax(&cmax[cc + 1], fkey(m1));
            }
        }
        __syncthreads();
        if (tid < 128) {
            int batch = (blockIdx.y * 128) / rows_per_batch;
            atomicMax(&g_featkeys[(size_t)batch * N + blockIdx.x*128 + tid], cmax[tid]);
        }
    }
}

// ---------------------------------------------------------------------------
// Fused fold GEMM (foldpre in A-fill, W2 GEMM, W3 projection epilogue)
// ---------------------------------------------------------------------------
__global__ void __launch_bounds__(256) fold_gemm_fused(
    int feaid, int stage, const float* __restrict__ w1, int bidW,
    const float* __restrict__ b2, const float* __restrict__ W3,
    const float* __restrict__ b3, int outid)
{
    __shared__ __align__(16) bf16 As[2][128*SROW];
    __shared__ __align__(16) bf16 Bs[2][128*SROW];
    __shared__ bf16  w1xs[512], w1ys[512], w1zs[512];
    __shared__ float l0s[128], l1s[128], l2s[128];
    __shared__ float w3s[128*3];
    __shared__ float b2s[128];

    const int K = 512;
    const float* feA = scratch_f32(feaid);
    const bf16* B = scratch_bf16(bidW) + (size_t)(blockIdx.x * 128) * K;

    const int tid  = threadIdx.x;
    const int lane = tid & 31, wid = tid >> 5;
    const int wm = wid & 3, wn = wid >> 2;

    if (tid < 128) {
        int cg = blockIdx.x*128 + tid;
        w3s[tid*3+0] = W3[cg*3+0];
        w3s[tid*3+1] = W3[cg*3+1];
        w3s[tid*3+2] = W3[cg*3+2];
        b2s[tid] = b2[cg];
        int gr = blockIdx.y*128 + tid;
        if (stage == 1) {
            int bg = gr / 36;
            int g = gr - bg * 36;
            l0s[tid] = c_lin[g / 6];
            l1s[tid] = c_lin[g % 6];
            l2s[tid] = 0.0f;
        } else {
            l0s[tid] = g_fold1[gr*3+0];
            l1s[tid] = g_fold1[gr*3+1];
            l2s[tid] = g_fold1[gr*3+2];
        }
    }
    for (int i = tid; i < 512; i += 256) {
        w1xs[i] = __float2bfloat16(w1[1024*512 + i]);
        w1ys[i] = __float2bfloat16(w1[1025*512 + i]);
        w1zs[i] = (stage == 2) ? __float2bfloat16(w1[1026*512 + i])
                               : __float2bfloat16(0.0f);
    }

    const unsigned aBase = (unsigned)__cvta_generic_to_shared(&As[0][0]);
    const unsigned bBase = (unsigned)__cvta_generic_to_shared(&Bs[0][0]);

    const int fr  = tid >> 1;
    const int fkk = (tid & 1) << 4;
    const int fbg = (blockIdx.y*128 + fr) / 36;
    const float* faRow = feA + (size_t)fbg * 512;

    auto fillA = [&](int s, int k0) {
        float l0 = l0s[fr], l1 = l1s[fr], l2 = l2s[fr];
        const float4* fa = (const float4*)(faRow + k0 + fkk);
        unsigned pk[8];
#pragma unroll
        for (int q = 0; q < 4; q++) {
            float4 f = fa[q];
            int kb = k0 + fkk + q*4;
            float v0 = fmaf(l2, __bfloat162float(w1zs[kb+0]),
                       fmaf(l1, __bfloat162float(w1ys[kb+0]),
                       fmaf(l0, __bfloat162float(w1xs[kb+0]), f.x)));
            float v1 = fmaf(l2, __bfloat162float(w1zs[kb+1]),
                       fmaf(l1, __bfloat162float(w1ys[kb+1]),
                       fmaf(l0, __bfloat162float(w1xs[kb+1]), f.y)));
            float v2 = fmaf(l2, __bfloat162float(w1zs[kb+2]),
                       fmaf(l1, __bfloat162float(w1ys[kb+2]),
                       fmaf(l0, __bfloat162float(w1xs[kb+2]), f.z)));
            float v3 = fmaf(l2, __bfloat162float(w1zs[kb+3]),
                       fmaf(l1, __bfloat162float(w1ys[kb+3]),
                       fmaf(l0, __bfloat162float(w1xs[kb+3]), f.w)));
            __nv_bfloat162 p0 = __floats2bfloat162_rn(fmaxf(v0, 0.0f), fmaxf(v1, 0.0f));
            __nv_bfloat162 p1 = __floats2bfloat162_rn(fmaxf(v2, 0.0f), fmaxf(v3, 0.0f));
            pk[q*2+0] = *(unsigned*)&p0;
            pk[q*2+1] = *(unsigned*)&p1;
        }
        uint4* dst = (uint4*)&As[s][fr*SROW + fkk];
        dst[0] = make_uint4(pk[0], pk[1], pk[2], pk[3]);
        dst[1] = make_uint4(pk[4], pk[5], pk[6], pk[7]);
    };

    auto loadB = [&](int s, int k0) {
#pragma unroll
        for (int i = 0; i < 2; i++) {
            int c = tid + (i << 8);
            int rr = c >> 2, sg = c & 3;
            cpa16(bBase + s*STAGE_B + (rr*SROW + sg*8)*2, B + (size_t)rr*K + k0 + sg*8);
        }
        asm volatile("cp.async.commit_group;");
    };

    float acc[2][8][4];
#pragma unroll
    for (int mt = 0; mt < 2; mt++)
#pragma unroll
        for (int nt = 0; nt < 8; nt++)
#pragma unroll
            for (int j = 0; j < 4; j++) acc[mt][nt][j] = 0.0f;

    unsigned aoff[2], boff[4];
#pragma unroll
    for (int mt = 0; mt < 2; mt++)
        aoff[mt] = ((wm*32 + mt*16 + (lane & 15)) * SROW + ((lane >> 4) << 3)) * 2;
#pragma unroll
    for (int ntp = 0; ntp < 4; ntp++)
        boff[ntp] = ((wn*64 + ntp*16 + ((lane & 16) >> 1) + (lane & 7)) * SROW
                     + (lane & 8)) * 2;

    loadB(0, 0);
    __syncthreads();
    fillA(0, 0);

    const int KT = K >> 5;
    for (int kt = 0; kt < KT; kt++) {
        int s = kt & 1;
        if (kt + 1 < KT) {
            loadB(s ^ 1, (kt + 1) << 5);
            asm volatile("cp.async.wait_group 1;");
        } else {
            asm volatile("cp.async.wait_group 0;");
        }
        __syncthreads();
        if (kt + 1 < KT) fillA(s ^ 1, (kt + 1) << 5);
        unsigned sOff = s * STAGE_B;
#pragma unroll
        for (int ks = 0; ks < 2; ks++) {
            unsigned af[2][4], bfr[8][2];
#pragma unroll
            for (int mt = 0; mt < 2; mt++)
                ldsm4(af[mt][0], af[mt][1], af[mt][2], af[mt][3],
                      aBase + sOff + aoff[mt] + ks*32);
#pragma unroll
            for (int ntp = 0; ntp < 4; ntp++) {
                unsigned r0, r1, r2, r3;
                ldsm4(r0, r1, r2, r3, bBase + sOff + boff[ntp] + ks*32);
                bfr[2*ntp][0] = r0;   bfr[2*ntp][1] = r1;
                bfr[2*ntp+1][0] = r2; bfr[2*ntp+1][1] = r3;
            }
#pragma unroll
            for (int mt = 0; mt < 2; mt++)
#pragma unroll
                for (int nt = 0; nt < 8; nt++)
                    mma_bf16(acc[mt][nt], af[mt], bfr[nt]);
        }
        __syncthreads();
    }

    float* out = scratch_f32(outid);
    const int row0 = blockIdx.y * 128 + wm * 32;
    float p[4][3];
#pragma unroll
    for (int i = 0; i < 4; i++)
#pragma unroll
        for (int c = 0; c < 3; c++) p[i][c] = 0.0f;

#pragma unroll
    for (int nt = 0; nt < 8; nt++) {
        int cc0 = wn*64 + nt*8 + (lane & 3)*2;
        int cc1 = cc0 + 1;
        float bb0 = b2s[cc0], bb1 = b2s[cc1];
        float h00 = fmaxf(acc[0][nt][0] + bb0, 0.0f);
        float h01 = fmaxf(acc[0][nt][1] + bb1, 0.0f);
        float h02 = fmaxf(acc[0][nt][2] + bb0, 0.0f);
        float h03 = fmaxf(acc[0][nt][3] + bb1, 0.0f);
        float h10 = fmaxf(acc[1][nt][0] + bb0, 0.0f);
        float h11 = fmaxf(acc[1][nt][1] + bb1, 0.0f);
        float h12 = fmaxf(acc[1][nt][2] + bb0, 0.0f);
        float h13 = fmaxf(acc[1][nt][3] + bb1, 0.0f);
#pragma unroll
        for (int c = 0; c < 3; c++) {
            float w0 = w3s[cc0*3 + c], w1v = w3s[cc1*3 + c];
            p[0][c] = fmaf(h00, w0, fmaf(h01, w1v, p[0][c]));
            p[1][c] = fmaf(h02, w0, fmaf(h03, w1v, p[1][c]));
            p[2][c] = fmaf(h10, w0, fmaf(h11, w1v, p[2][c]));
            p[3][c] = fmaf(h12, w0, fmaf(h13, w1v, p[3][c]));
        }
    }
#pragma unroll
    for (int o = 1; o <= 2; o <<= 1)
#pragma unroll
        for (int i = 0; i < 4; i++)
#pragma unroll
            for (int c = 0; c < 3; c++)
                p[i][c] += __shfl_xor_sync(0xffffffffu, p[i][c], o);

    if ((lane & 3) == 0) {
        bool addb3 = (blockIdx.x == 0) && (wn == 0);
#pragma unroll
        for (int i = 0; i < 4; i++) {
            int r = row0 + (i >> 1)*16 + (lane >> 2) + (i & 1)*8;
#pragma unroll
            for (int c = 0; c < 3; c++) {
                float v = p[i][c];
                if (addb3) v += b3[c];
                atomicAdd(&out[r*3 + c], v);
            }
        }
    }
}

// ---------------------------------------------------------------------------
// Small per-row MLP
// ---------------------------------------------------------------------------
__global__ void mlp_row_kernel(int xid, int xkeys, const float* __restrict__ W,
                               const float* __restrict__ bias, int yid,
                               int K, int N, int act)
{
    __shared__ float sx[1024];
    float* Y = scratch_f32(yid);
    int b = blockIdx.y;
    int col = blockIdx.x * blockDim.x + threadIdx.x;
    if (xkeys) {
        for (int k = threadIdx.x; k < K; k += blockDim.x)
            sx[k] = unfkey(g_featkeys[b*K + k]);
    } else {
        const float* X = scratch_f32(xid);
        for (int k = threadIdx.x; k < K; k += blockDim.x) sx[k] = X[b*K + k];
    }
    __syncthreads();
    float s0 = 0.0f, s1 = 0.0f, s2 = 0.0f, s3 = 0.0f;
    for (int k = 0; k < K; k += 4) {
        s0 = fmaf(sx[k+0], W[(size_t)(k+0)*N + col], s0);
        s1 = fmaf(sx[k+1], W[(size_t)(k+1)*N + col], s1);
        s2 = fmaf(sx[k+2], W[(size_t)(k+2)*N + col], s2);
        s3 = fmaf(sx[k+3], W[(size_t)(k+3)*N + col], s3);
    }
    float s = ((s0 + s1) + (s2 + s3)) + bias[col];
    if (act) s = fmaxf(s, 0.0f);
    Y[b*N + col] = s;
}

// ---------------------------------------------------------------------------
// pos + fe (bf16), 256 threads
// ---------------------------------------------------------------------------
__global__ void __launch_bounds__(256) posfe_kernel(
    const float* __restrict__ w1, const float* __restrict__ b1,
    const float* __restrict__ w2, const float* __restrict__ b2)
{
    int bg = blockIdx.x, t = threadIdx.x, b = bg >> 6;
    __shared__ float h[128];
    float cx = g_centers[bg*3], cy = g_centers[bg*3+1], cz = g_centers[bg*3+2];
    if (t < 128) {
        float v = cx*w1[t] + cy*w1[128+t] + cz*w1[256+t] + b1[t];
        h[t] = gelu_exact(v);
    }
    __syncthreads();
    for (int q = 0; q < 4; q++) {
        int j = (q << 8) + t;
        float s = 0.0f;
#pragma unroll 8
        for (int k = 0; k < 128; k++) s = fmaf(h[k], w2[k*1024 + j], s);
        float feat = unfkey(g_featkeys[b*1024 + j]);
        g_feb[bg*1024 + j] = __float2bfloat16(s + b2[j] + feat);
    }
}

// ---------------------------------------------------------------------------
// Chamfer fine
// ---------------------------------------------------------------------------
__global__ void chamfer_fine_kernel() {
    int bg = blockIdx.x, t = threadIdx.x;  // 128 threads
    __shared__ float F[108], Nn[96], rm[36], cm[32];
    for (int i = t; i < 108; i += 128) F[i] = g_fold2[bg*108 + i];
    for (int i = t; i < 96;  i += 128) Nn[i] = g_neigh[bg*96 + i];
    __syncthreads();
    if (t < 36) {
        float fx = F[t*3], fy = F[t*3+1], fz = F[t*3+2], mn = FLT_MAX;
        for (int j = 0; j < 32; j++) {
            float dx = fx-Nn[j*3], dy = fy-Nn[j*3+1], dz = fz-Nn[j*3+2];
            mn = fminf(mn, dx*dx + dy*dy + dz*dz);
        }
        rm[t] = mn;
    } else if (t < 68) {
        int j = t - 36;
        float nx = Nn[j*3], ny = Nn[j*3+1], nz = Nn[j*3+2], mn = FLT_MAX;
        for (int i = 0; i < 36; i++) {
            float dx = F[i*3]-nx, dy = F[i*3+1]-ny, dz = F[i*3+2]-nz;
            mn = fminf(mn, dx*dx + dy*dy + dz*dz);
        }
        cm[j] = mn;
    }
    __syncthreads();
    if (t == 0) {
        float s = 0.0f;
        for (int i = 0; i < 36; i++) s += rm[i];
        atomicAdd(&g_acc[0], s);
        s = 0.0f;
        for (int j = 0; j < 32; j++) s += cm[j];
        atomicAdd(&g_acc[1], s);
    }
}

// ---------------------------------------------------------------------------
// Chamfer coarse
// ---------------------------------------------------------------------------
__global__ void __launch_bounds__(512) chamfer_coarse_kernel() {
    int t = threadIdx.x;
    __shared__ float C[1536], Ce[1536], s1[512], s2[512];
    for (int i = t; i < 1536; i += 512) { C[i] = g_coarse[i]; Ce[i] = g_centers[i]; }
    __syncthreads();
    int b = t >> 6, i = t & 63;
    const float* cb = &C[b*192];
    const float* eb = &Ce[b*192];
    float x = cb[i*3], y = cb[i*3+1], z = cb[i*3+2], mn = FLT_MAX;
    for (int j = 0; j < 64; j++) {
        float dx = x-eb[j*3], dy = y-eb[j*3+1], dz = z-eb[j*3+2];
        mn = fminf(mn, dx*dx + dy*dy + dz*dz);
    }
    s1[t] = mn;
    float x2 = eb[i*3], y2 = eb[i*3+1], z2 = eb[i*3+2];
    mn = FLT_MAX;
    for (int j = 0; j < 64; j++) {
        float dx = x2-cb[j*3], dy = y2-cb[j*3+1], dz = z2-cb[j*3+2];
        mn = fminf(mn, dx*dx + dy*dy + dz*dz);
    }
    s2[t] = mn;
    __syncthreads();
    for (int s = 256; s; s >>= 1) {
        if (t < s) { s1[t] += s1[t+s]; s2[t] += s2[t+s]; }
        __syncthreads();
    }
    if (t == 0) { g_acc[2] = s1[0]; g_acc[3] = s2[0]; }
}

__global__ void finalize_kernel(float* __restrict__ out) {
    out[0] = g_acc[0] / (float)(FROWS) + g_acc[1] / (float)(BGROUPS*GS);
    out[1] = g_acc[2] / 512.0f + g_acc[3] / 512.0f;
}

// ---------------------------------------------------------------------------
// launch — multi-stream DAG; call order arranged so encL3 is capture #5
// ---------------------------------------------------------------------------
extern "C" void kernel_launch(void* const* d_in, const int* in_sizes, int n_in,
                              void* d_out, int out_size)
{
    (void)in_sizes; (void)n_in; (void)out_size;
    const float* corrupted = (const float*)d_in[0];
    const float* pts       = (const float*)d_in[1];
    const float* enc_w1 = (const float*)d_in[2];
    const float* enc_b1 = (const float*)d_in[3];
    const float* enc_w2 = (const float*)d_in[4];
    const float* enc_b2 = (const float*)d_in[5];
    const float* enc_w3 = (const float*)d_in[6];
    const float* enc_b3 = (const float*)d_in[7];
    const float* pe_w1  = (const float*)d_in[8];
    const float* pe_b1  = (const float*)d_in[9];
    const float* pe_w2  = (const float*)d_in[10];
    const float* pe_b2  = (const float*)d_in[11];
    const float* cp_w1  = (const float*)d_in[12];
    const float* cp_b1  = (const float*)d_in[13];
    const float* cp_w2  = (const float*)d_in[14];
    const float* cp_b2  = (const float*)d_in[15];
    const float* cp_w3  = (const float*)d_in[16];
    const float* cp_b3  = (const float*)d_in[17];
    const float* f1_w1  = (const float*)d_in[18];
    const float* f1_b1  = (const float*)d_in[19];
    const float* f1_w2  = (const float*)d_in[20];
    const float* f1_b2  = (const float*)d_in[21];
    const float* f1_w3  = (const float*)d_in[22];
    const float* f1_b3  = (const float*)d_in[23];
    const float* f2_w1  = (const float*)d_in[24];
    const float* f2_b1  = (const float*)d_in[25];
    const float* f2_w2  = (const float*)d_in[26];
    const float* f2_b2  = (const float*)d_in[27];
    const float* f2_w3  = (const float*)d_in[28];
    const float* f2_b3  = (const float*)d_in[29];
    float* out = (float*)d_out;

    // one-time host resources (no device memory involved)
    static cudaStream_t sB = nullptr, sC = nullptr;
    static cudaEvent_t eFork, eGeo, eEnc, ePos, eFeA2, eCoarse, eWf, eW3;
    if (sB == nullptr) {
        cudaStreamCreateWithFlags(&sB, cudaStreamNonBlocking);
        cudaStreamCreateWithFlags(&sC, cudaStreamNonBlocking);
        cudaEventCreateWithFlags(&eFork,   cudaEventDisableTiming);
        cudaEventCreateWithFlags(&eGeo,    cudaEventDisableTiming);
        cudaEventCreateWithFlags(&eEnc,    cudaEventDisableTiming);
        cudaEventCreateWithFlags(&ePos,    cudaEventDisableTiming);
        cudaEventCreateWithFlags(&eFeA2,   cudaEventDisableTiming);
        cudaEventCreateWithFlags(&eCoarse, cudaEventDisableTiming);
        cudaEventCreateWithFlags(&eWf,     cudaEventDisableTiming);
        cudaEventCreateWithFlags(&eW3,     cudaEventDisableTiming);
        cudaFuncSetAttribute(enc12_kernel,
                             cudaFuncAttributeMaxDynamicSharedMemorySize, ENC12_SMEM);
    }

    // #0 main: minimal init
    zero_main_kernel<<<32, 256>>>();
    cudaEventRecord(eFork, 0);

    // #1 sC: w3 transpose (needed by encL3)
    cudaStreamWaitEvent(sC, eFork, 0);
    wtrans_one<<<1024, 256, 0, sC>>>(enc_w3, 256, 1024, BID_W3T);
    cudaEventRecord(eW3, sC);

    // #2 main: w2 transpose   #3 main: enc12
    wtrans_one<<<128, 256>>>(enc_w2, 128, 256, BID_W2T);
    enc12_kernel<<<dim3(2, 512), 256, ENC12_SMEM>>>(corrupted, enc_w1, enc_b1, enc_b2);

    // #4 sB: fps
    cudaStreamWaitEvent(sB, eFork, 0);
    fps_kernel<<<NB, 1024, 0, sB>>>(pts);

    // #5 main: encL3 (the launch we want profiled)
    cudaStreamWaitEvent(0, eW3, 0);
    mma_gemm<2><<<dim3(8, 512), 256>>>(BID_H2, BID_W3T, enc_b3, 0, 1024, 256, NPTS);
    cudaEventRecord(eEnc, 0);

    // #6 sB: knn
    knn_kernel<<<BGROUPS, 256, 0, sB>>>(pts);
    cudaEventRecord(eGeo, sB);

    // #7-8 sC: fold zero + fold transposes
    zero_fold_kernel<<<(FROWS*3 + 255)/256, 256, 0, sC>>>();
    wtrans_fold<<<dim3(2048, 4), 256, 0, sC>>>(f1_w1, f2_w1, f1_w2, f2_w2);
    cudaEventRecord(eWf, sC);

    // sC: coarse MLP chain + coarse chamfer
    cudaStreamWaitEvent(sC, eEnc, 0);
    mlp_row_kernel<<<dim3(8, NB), 128, 0, sC>>>(0, 1, cp_w1, cp_b1, FID_C1, 1024, 1024, 1);
    mlp_row_kernel<<<dim3(8, NB), 128, 0, sC>>>(FID_C1, 0, cp_w2, cp_b2, FID_C2, 1024, 1024, 1);
    mlp_row_kernel<<<dim3(1, NB), 192, 0, sC>>>(FID_C2, 0, cp_w3, cp_b3, FID_COARSE, 1024, 192, 0);
    cudaStreamWaitEvent(sC, eGeo, 0);
    chamfer_coarse_kernel<<<1, 512, 0, sC>>>();
    cudaEventRecord(eCoarse, sC);

    // main: posfe (centers + featkeys)
    cudaStreamWaitEvent(0, eGeo, 0);
    posfe_kernel<<<BGROUPS, 256>>>(pe_w1, pe_b1, pe_w2, pe_b2);
    cudaEventRecord(ePos, 0);

    // feA1 main (needs f1w1t), feA2 on stream B (needs f2w1t + fe)
    cudaStreamWaitEvent(0, eWf, 0);
    mma_gemm<0><<<dim3(4, 4), 256>>>(BID_FE, BID_F1W1T, f1_b1, FID_FEA1, 512, 1024, 0);
    cudaStreamWaitEvent(sB, ePos, 0);
    cudaStreamWaitEvent(sB, eWf, 0);
    mma_gemm<0><<<dim3(4, 4), 256, 0, sB>>>(BID_FE, BID_F2W1T, f2_b1, FID_FEA2, 512, 1024, 0);
    cudaEventRecord(eFeA2, sB);

    // fold stage 1 (fused foldpre + GEMM + W3 projection)
    fold_gemm_fused<<<dim3(4, 144), 256>>>(FID_FEA1, 1, f1_w1, BID_F1W2T,
                                           f1_b2, f1_w3, f1_b3, FID_FOLD1);

    // fold stage 2 (needs feA2 + fold1)
    cudaStreamWaitEvent(0, eFeA2, 0);
    fold_gemm_fused<<<dim3(4, 144), 256>>>(FID_FEA2, 2, f2_w1, BID_F2W2T,
                                           f2_b2, f2_w3, f2_b3, FID_FOLD2);

    // fine chamfer
    chamfer_fine_kernel<<<BGROUPS, 128>>>();

    // join coarse chain, finalize
    cudaStreamWaitEvent(0, eCoarse, 0);
    finalize_kernel<<<1, 1>>>(out);
}

// round 15
// speedup vs baseline: 1.8512x; 1.1113x over previous
#include <cuda_runtime.h>
#include <cuda_bf16.h>
#include <math.h>
#include <float.h>

// ---------------------------------------------------------------------------
// Problem constants
// ---------------------------------------------------------------------------
#define NB       8
#define NPTS     8192
#define NC       64
#define GS       32
#define BGROUPS  512
#define GRID_PTS 36
#define FROWS    (BGROUPS*GRID_PTS)   // 18432
#define ENC_ROWS (NB*NPTS)            // 65536

typedef __nv_bfloat16 bf16;

// ---------------------------------------------------------------------------
// Scratch (device globals; no allocation anywhere)
// ---------------------------------------------------------------------------
__device__ bf16     g_h2b[ENC_ROWS*256];
__device__ bf16     g_feb[BGROUPS*1024];
__device__ bf16     g_w2t[256*128];
__device__ bf16     g_w3t[1024*256];
__device__ bf16     g_f1w1t[512*1024];
__device__ bf16     g_f2w1t[512*1024];
__device__ bf16     g_f1w2t[512*512];
__device__ bf16     g_f2w2t[512*512];

__device__ float    g_feA1[BGROUPS*512];
__device__ float    g_feA2[BGROUPS*512];
__device__ unsigned g_featkeys[NB*1024];
__device__ float    g_centers[BGROUPS*3];
__device__ float    g_neigh[BGROUPS*GS*3];
__device__ float    g_fold1[FROWS*3];
__device__ float    g_fold2[FROWS*3];
__device__ float    g_c1[NB*1024];
__device__ float    g_c2[NB*1024];
__device__ float    g_coarse[NB*192];
__device__ float    g_acc[4];

__constant__ float c_lin[6] = {-0.3f,-0.18f,-0.06f,0.06f,0.18f,0.3f};

// bf16 scratch ids
#define BID_H2     0
#define BID_FE     1
#define BID_W2T    2
#define BID_W3T    3
#define BID_F1W1T  4
#define BID_F2W1T  5
#define BID_F1W2T  6
#define BID_F2W2T  7

// f32 scratch ids
#define FID_FEA1   0
#define FID_FEA2   1
#define FID_C1     2
#define FID_C2     3
#define FID_COARSE 4
#define FID_FOLD1  5
#define FID_FOLD2  6

__device__ __forceinline__ bf16* scratch_bf16(int id) {
    switch (id) {
        case BID_H2:    return g_h2b;
        case BID_FE:    return g_feb;
        case BID_W2T:   return g_w2t;
        case BID_W3T:   return g_w3t;
        case BID_F1W1T: return g_f1w1t;
        case BID_F2W1T: return g_f2w1t;
        case BID_F1W2T: return g_f1w2t;
        default:        return g_f2w2t;
    }
}
__device__ __forceinline__ float* scratch_f32(int id) {
    switch (id) {
        case FID_FEA1:  return g_feA1;
        case FID_FEA2:  return g_feA2;
        case FID_C1:    return g_c1;
        case FID_C2:    return g_c2;
        case FID_COARSE:return g_coarse;
        case FID_FOLD1: return g_fold1;
        default:        return g_fold2;
    }
}

__device__ __forceinline__ unsigned fkey(float f) {
    unsigned u = __float_as_uint(f);
    return (u & 0x80000000u) ? ~u : (u | 0x80000000u);
}
__device__ __forceinline__ float unfkey(unsigned k) {
    return __uint_as_float((k & 0x80000000u) ? (k & 0x7fffffffu) : ~k);
}

__device__ __forceinline__ float gelu_exact(float x) {
    return 0.5f * x * (1.0f + erff(x * 0.7071067811865476f));
}

__device__ __forceinline__ void cpa16(unsigned dst, const void* src) {
    asm volatile("cp.async.cg.shared.global [%0], [%1], 16;" :: "r"(dst), "l"(src));
}

__device__ __forceinline__ void ldsm4(unsigned& r0, unsigned& r1, unsigned& r2,
                                      unsigned& r3, unsigned addr) {
    asm volatile("ldmatrix.sync.aligned.m8n8.x4.shared.b16 {%0,%1,%2,%3}, [%4];"
        : "=r"(r0), "=r"(r1), "=r"(r2), "=r"(r3) : "r"(addr));
}

__device__ __forceinline__ void mma_bf16(float* c, const unsigned* a, const unsigned* b) {
    asm volatile(
        "mma.sync.aligned.m16n8k16.row.col.f32.bf16.bf16.f32 "
        "{%0,%1,%2,%3}, {%4,%5,%6,%7}, {%8,%9}, {%0,%1,%2,%3};"
        : "+f"(c[0]), "+f"(c[1]), "+f"(c[2]), "+f"(c[3])
        : "r"(a[0]), "r"(a[1]), "r"(a[2]), "r"(a[3]), "r"(b[0]), "r"(b[1]));
}

__device__ __forceinline__ void wredmax(float& v, int& i) {
#pragma unroll
    for (int o = 16; o; o >>= 1) {
        float v2 = __shfl_xor_sync(0xffffffffu, v, o);
        int   i2 = __shfl_xor_sync(0xffffffffu, i, o);
        if (v2 > v || (v2 == v && i2 < i)) { v = v2; i = i2; }
    }
}
__device__ __forceinline__ void wredmin(float& v, int& i) {
#pragma unroll
    for (int o = 16; o; o >>= 1) {
        float v2 = __shfl_xor_sync(0xffffffffu, v, o);
        int   i2 = __shfl_xor_sync(0xffffffffu, i, o);
        if (v2 < v || (v2 == v && i2 < i)) { v = v2; i = i2; }
    }
}

// ---------------------------------------------------------------------------
// init
// ---------------------------------------------------------------------------
__global__ void zero_main_kernel() {
    int i = blockIdx.x * 256 + threadIdx.x;
    if (i < NB*1024) g_featkeys[i] = 0u;
    if (i < 4)       g_acc[i] = 0.0f;
}
__global__ void zero_fold_kernel() {
    int i = blockIdx.x * 256 + threadIdx.x;
    if (i < FROWS*3) { g_fold1[i] = 0.0f; g_fold2[i] = 0.0f; }
}

// ---------------------------------------------------------------------------
// weight transpose + bf16: out[n*K+k] = bf16(W[k*N+n])
// ---------------------------------------------------------------------------
__global__ void wtrans_one(const float* __restrict__ W, int K, int N, int bid) {
    bf16* out = scratch_bf16(bid);
    int i = blockIdx.x * 256 + threadIdx.x;
    if (i < K * N) {
        int n = i / K, k = i - n * K;
        out[i] = __float2bfloat16(W[(size_t)k * N + n]);
    }
}

__global__ void wtrans_fold(const float* __restrict__ fw1a, const float* __restrict__ fw1b,
                            const float* __restrict__ fw2a, const float* __restrict__ fw2b)
{
    const float* W; int K, N; bf16* out;
    switch (blockIdx.y) {
        case 0: W = fw1a; K = 1024; N = 512; out = g_f1w1t; break;
        case 1: W = fw1b; K = 1024; N = 512; out = g_f2w1t; break;
        case 2: W = fw2a; K = 512;  N = 512; out = g_f1w2t; break;
        default:W = fw2b; K = 512;  N = 512; out = g_f2w2t; break;
    }
    int i = blockIdx.x * 256 + threadIdx.x;
    if (i < K * N) {
        int n = i / K, k = i - n * K;
        out[i] = __float2bfloat16(W[(size_t)k * N + n]);
    }
}

// ---------------------------------------------------------------------------
// Farthest point sampling
// ---------------------------------------------------------------------------
__global__ void __launch_bounds__(1024) fps_kernel(const float* __restrict__ pts) {
    int b = blockIdx.x, t = threadIdx.x;
    int lane = t & 31, wid = t >> 5;
    const float* P = pts + (size_t)b * NPTS * 3;
    __shared__ float sv[32];
    __shared__ int   si[32];
    __shared__ float cur[3];

    float px[8], py[8], pz[8], dd[8];
#pragma unroll
    for (int i = 0; i < 8; i++) {
        int p = (t << 3) + i;
        px[i] = P[p*3]; py[i] = P[p*3+1]; pz[i] = P[p*3+2];
    }
    if (t == 0) {
        cur[0] = P[0]; cur[1] = P[1]; cur[2] = P[2];
        g_centers[b*192+0] = P[0]; g_centers[b*192+1] = P[1]; g_centers[b*192+2] = P[2];
    }
    __syncthreads();
    float cx = cur[0], cy = cur[1], cz = cur[2];
#pragma unroll
    for (int i = 0; i < 8; i++) {
        float dx = px[i]-cx, dy = py[i]-cy, dz = pz[i]-cz;
        dd[i] = dx*dx + dy*dy + dz*dz;
    }
    for (int it = 1; it < NC; it++) {
        float bv = dd[0]; int bi = (t << 3);
#pragma unroll
        for (int i = 1; i < 8; i++)
            if (dd[i] > bv) { bv = dd[i]; bi = (t << 3) + i; }
        wredmax(bv, bi);
        if (lane == 0) { sv[wid] = bv; si[wid] = bi; }
        __syncthreads();
        if (wid == 0) {
            float v = sv[lane]; int i = si[lane];
            wredmax(v, i);
            if (lane == 0) {
                cur[0] = P[i*3]; cur[1] = P[i*3+1]; cur[2] = P[i*3+2];
                g_centers[b*192 + it*3+0] = cur[0];
                g_centers[b*192 + it*3+1] = cur[1];
                g_centers[b*192 + it*3+2] = cur[2];
            }
        }
        __syncthreads();
        cx = cur[0]; cy = cur[1]; cz = cur[2];
#pragma unroll
        for (int i = 0; i < 8; i++) {
            float dx = px[i]-cx, dy = py[i]-cy, dz = pz[i]-cz;
            dd[i] = fminf(dd[i], dx*dx + dy*dy + dz*dz);
        }
    }
}

// ---------------------------------------------------------------------------
// 32-NN grouping — incremental argmin
// ---------------------------------------------------------------------------
__global__ void __launch_bounds__(256) knn_kernel(const float* __restrict__ pts) {
    int bg = blockIdx.x, b = bg >> 6, t = threadIdx.x;
    int lane = t & 31, wid = t >> 5;
    const float* P = pts + (size_t)b * NPTS * 3;
    __shared__ float sd[NPTS];
    __shared__ float sv[8];
    __shared__ int   si[8];
    __shared__ int   swin;
    float cx = g_centers[bg*3], cy = g_centers[bg*3+1], cz = g_centers[bg*3+2];
    for (int p = t; p < NPTS; p += 256) {
        float dx = P[p*3]-cx, dy = P[p*3+1]-cy, dz = P[p*3+2]-cz;
        sd[p] = dx*dx + dy*dy + dz*dz;
    }
    __syncthreads();

    const int base = t << 5;
    float mv = FLT_MAX; int mi = base;
#pragma unroll 8
    for (int j = 0; j < 32; j++) {
        float v = sd[base + j];
        if (v < mv) { mv = v; mi = base + j; }
    }

    for (int k = 0; k < GS; k++) {
        float bv = mv; int bi = mi;
        wredmin(bv, bi);
        if (lane == 0) { sv[wid] = bv; si[wid] = bi; }
        __syncthreads();
        if (t < 32) {
            float v = (lane < 8) ? sv[lane] : FLT_MAX;
            int   i = (lane < 8) ? si[lane] : NPTS;
            wredmin(v, i);
            if (lane == 0) {
                swin = i;
                g_neigh[(bg*GS+k)*3+0] = P[i*3+0] - cx;
                g_neigh[(bg*GS+k)*3+1] = P[i*3+1] - cy;
                g_neigh[(bg*GS+k)*3+2] = P[i*3+2] - cz;
            }
        }
        __syncthreads();
        int win = swin;
        if ((win >> 5) == t) {
            sd[win] = FLT_MAX;
            mv = FLT_MAX; mi = base;
#pragma unroll 8
            for (int j = 0; j < 32; j++) {
                float v = sd[base + j];
                if (v < mv) { mv = v; mi = base + j; }
            }
        }
        __syncthreads();
    }
}

// ---------------------------------------------------------------------------
// Fused enc layer1 + layer2 GEMM — full-resident A+B, single barrier.
// ---------------------------------------------------------------------------
#define SR12 136
#define ENC12_SMEM (2*128*SR12*2)

__global__ void __launch_bounds__(256) enc12_kernel(
    const float* __restrict__ x, const float* __restrict__ w1,
    const float* __restrict__ b1, const float* __restrict__ b2)
{
    extern __shared__ __align__(16) bf16 dyn12[];
    bf16* As = dyn12;                 // 128 x 136
    bf16* Bs = dyn12 + 128*SR12;      // 128 x 136
    __shared__ float  sx[384];
    __shared__ float4 swc[128];

    const int tid = threadIdx.x, lane = tid & 31, wid = tid >> 5;
    const int wm = wid & 3, wn = wid >> 2;
    const int br = blockIdx.y, bc = blockIdx.x;

    const bf16* B = g_w2t + (size_t)(bc * 128) * 128;
    const unsigned bBase = (unsigned)__cvta_generic_to_shared(Bs);
    const unsigned aBase = (unsigned)__cvta_generic_to_shared(As);

#pragma unroll
    for (int i = 0; i < 8; i++) {
        int chunk = i * 256 + tid;
        int row = chunk >> 4, seg = chunk & 15;
        cpa16(bBase + (row*SR12 + seg*8)*2, B + row*128 + seg*8);
    }
    asm volatile("cp.async.commit_group;");

    if (tid < 96) *(float4*)&sx[tid*4] = *(const float4*)(x + (size_t)br*384 + tid*4);
    if (tid < 128) {
        float4 w; w.x = w1[tid]; w.y = w1[128+tid]; w.z = w1[256+tid]; w.w = b1[tid];
        swc[tid] = w;
    }
    asm volatile("cp.async.wait_group 0;");
    __syncthreads();

    {
        const int r = tid >> 1;
        const int kb0 = (tid & 1) * 64;
        const float x0 = sx[r*3], x1 = sx[r*3+1], x2 = sx[r*3+2];
#pragma unroll
        for (int blk = 0; blk < 8; blk++) {
            unsigned pk[4];
#pragma unroll
            for (int q = 0; q < 4; q++) {
                int k = kb0 + blk*8 + q*2;
                float4 wa = swc[k], wb = swc[k+1];
                float va = fmaxf(fmaf(x0, wa.x, fmaf(x1, wa.y, fmaf(x2, wa.z, wa.w))), 0.0f);
                float vb = fmaxf(fmaf(x0, wb.x, fmaf(x1, wb.y, fmaf(x2, wb.z, wb.w))), 0.0f);
                __nv_bfloat162 p = __floats2bfloat162_rn(va, vb);
                pk[q] = *(unsigned*)&p;
            }
            *(uint4*)&As[r*SR12 + kb0 + blk*8] = make_uint4(pk[0], pk[1], pk[2], pk[3]);
        }
    }
    __syncthreads();

    float acc[2][8][4];
#pragma unroll
    for (int mt = 0; mt < 2; mt++)
#pragma unroll
        for (int nt = 0; nt < 8; nt++)
#pragma unroll
            for (int j = 0; j < 4; j++) acc[mt][nt][j] = 0.0f;

    unsigned aoff[2], boff[4];
#pragma unroll
    for (int mt = 0; mt < 2; mt++)
        aoff[mt] = ((wm*32 + mt*16 + (lane & 15)) * SR12 + ((lane >> 4) << 3)) * 2;
#pragma unroll
    for (int ntp = 0; ntp < 4; ntp++)
        boff[ntp] = ((wn*64 + ntp*16 + ((lane & 16) >> 1) + (lane & 7)) * SR12
                     + (lane & 8)) * 2;

#pragma unroll
    for (int kt = 0; kt < 8; kt++) {
        unsigned af[2][4], bfr[8][2];
#pragma unroll
        for (int mt = 0; mt < 2; mt++)
            ldsm4(af[mt][0], af[mt][1], af[mt][2], af[mt][3], aBase + aoff[mt] + kt*32);
#pragma unroll
        for (int ntp = 0; ntp < 4; ntp++) {
            unsigned r0, r1, r2, r3;
            ldsm4(r0, r1, r2, r3, bBase + boff[ntp] + kt*32);
            bfr[2*ntp][0] = r0;   bfr[2*ntp][1] = r1;
            bfr[2*ntp+1][0] = r2; bfr[2*ntp+1][1] = r3;
        }
#pragma unroll
        for (int mt = 0; mt < 2; mt++)
#pragma unroll
            for (int nt = 0; nt < 8; nt++)
                mma_bf16(acc[mt][nt], af[mt], bfr[nt]);
    }

    const int row0 = br*128 + wm*32;
    const int col0 = bc*128 + wn*64;
#pragma unroll
    for (int mt = 0; mt < 2; mt++) {
        int rr = row0 + mt*16 + (lane >> 2);
#pragma unroll
        for (int nt = 0; nt < 8; nt++) {
            int c = col0 + nt*8 + (lane & 3)*2;
            float bb0 = b2[c], bb1 = b2[c + 1];
            __nv_bfloat162 v0 = __floats2bfloat162_rn(
                fmaxf(acc[mt][nt][0] + bb0, 0.0f), fmaxf(acc[mt][nt][1] + bb1, 0.0f));
            __nv_bfloat162 v1 = __floats2bfloat162_rn(
                fmaxf(acc[mt][nt][2] + bb0, 0.0f), fmaxf(acc[mt][nt][3] + bb1, 0.0f));
            *(__nv_bfloat162*)(g_h2b + (size_t)rr*256 + c)       = v0;
            *(__nv_bfloat162*)(g_h2b + (size_t)(rr + 8)*256 + c) = v1;
        }
    }
}

// ---------------------------------------------------------------------------
// encL3 specialized: A (128x256) resident in smem, loop over 2 N-blocks of 128
// streaming only B. grid (4, 512): bx = 256-col group, by = 128-row block.
// Epilogue per N-block: bias + per-batch column max into g_featkeys.
// ---------------------------------------------------------------------------
#define SROW 40
#define STAGE_B (128*SROW*2)
#define SRA  264
#define ENC3_SMEM (128*SRA*2 + 2*128*SROW*2)   // 67584 + 20480 = 88064

__global__ void __launch_bounds__(256) encl3_kernel(const float* __restrict__ bias)
{
    extern __shared__ __align__(16) bf16 dyn3[];
    bf16* As = dyn3;                  // 128 x 264 (K=256 resident)
    bf16* Bs = dyn3 + 128*SRA;        // 2 x 128 x 40
    __shared__ unsigned cmax[128];

    const int tid = threadIdx.x, lane = tid & 31, wid = tid >> 5;
    const int wm = wid & 3, wn = wid >> 2;
    const int bx = blockIdx.x, by = blockIdx.y;

    const bf16* A = g_h2b + (size_t)(by * 128) * 256;
    const unsigned aBase = (unsigned)__cvta_generic_to_shared(As);
    const unsigned bBase = (unsigned)__cvta_generic_to_shared(Bs);

    // A resident: 128 rows x 256 cols = 4096 16B-chunks, 16 per thread
#pragma unroll
    for (int i = 0; i < 16; i++) {
        int c = i * 256 + tid;
        int row = c >> 5, seg = c & 31;
        cpa16(aBase + (row*SRA + seg*8)*2, A + (size_t)row*256 + seg*8);
    }
    asm volatile("cp.async.commit_group;");

    unsigned aoff[2], boff[4];
#pragma unroll
    for (int mt = 0; mt < 2; mt++)
        aoff[mt] = ((wm*32 + mt*16 + (lane & 15)) * SRA + ((lane >> 4) << 3)) * 2;
#pragma unroll
    for (int ntp = 0; ntp < 4; ntp++)
        boff[ntp] = ((wn*64 + ntp*16 + ((lane & 16) >> 1) + (lane & 7)) * SROW
                     + (lane & 8)) * 2;

    const int batch = (by * 128) / NPTS;

    for (int nb = 0; nb < 2; nb++) {
        const bf16* B = g_w3t + (size_t)(bx*256 + nb*128) * 256;

        auto loadB = [&](int s, int k0) {
#pragma unroll
            for (int i = 0; i < 2; i++) {
                int c = tid + (i << 8);
                int rr = c >> 2, sg = c & 3;
                cpa16(bBase + s*STAGE_B + (rr*SROW + sg*8)*2,
                      B + (size_t)rr*256 + k0 + sg*8);
            }
            asm volatile("cp.async.commit_group;");
        };

        float acc[2][8][4];
#pragma unroll
        for (int mt = 0; mt < 2; mt++)
#pragma unroll
            for (int nt = 0; nt < 8; nt++)
#pragma unroll
                for (int j = 0; j < 4; j++) acc[mt][nt][j] = 0.0f;

        loadB(0, 0);
        for (int kt = 0; kt < 8; kt++) {
            int s = kt & 1;
            if (kt + 1 < 8) {
                loadB(s ^ 1, (kt + 1) << 5);
                asm volatile("cp.async.wait_group 1;");
            } else {
                asm volatile("cp.async.wait_group 0;");
            }
            __syncthreads();
            unsigned sOff = s * STAGE_B;
#pragma unroll
            for (int ks = 0; ks < 2; ks++) {
                unsigned af[2][4], bfr[8][2];
#pragma unroll
                for (int mt = 0; mt < 2; mt++)
                    ldsm4(af[mt][0], af[mt][1], af[mt][2], af[mt][3],
                          aBase + aoff[mt] + kt*64 + ks*32);
#pragma unroll
                for (int ntp = 0; ntp < 4; ntp++) {
                    unsigned r0, r1, r2, r3;
                    ldsm4(r0, r1, r2, r3, bBase + sOff + boff[ntp] + ks*32);
                    bfr[2*ntp][0] = r0;   bfr[2*ntp][1] = r1;
                    bfr[2*ntp+1][0] = r2; bfr[2*ntp+1][1] = r3;
                }
#pragma unroll
                for (int mt = 0; mt < 2; mt++)
#pragma unroll
                    for (int nt = 0; nt < 8; nt++)
                        mma_bf16(acc[mt][nt], af[mt], bfr[nt]);
            }
            __syncthreads();
        }

        // epilogue: bias + column max over 128 rows -> featkeys
        if (tid < 128) cmax[tid] = 0u;
        __syncthreads();
        const int colbase = bx*256 + nb*128;
#pragma unroll
        for (int nt = 0; nt < 8; nt++) {
            int cc = wn*64 + nt*8 + (lane & 3)*2;
            float b0 = bias[colbase + cc];
            float b1 = bias[colbase + cc + 1];
            float m0 = fmaxf(fmaxf(acc[0][nt][0], acc[0][nt][2]),
                             fmaxf(acc[1][nt][0], acc[1][nt][2])) + b0;
            float m1 = fmaxf(fmaxf(acc[0][nt][1], acc[0][nt][3]),
                             fmaxf(acc[1][nt][1], acc[1][nt][3])) + b1;
#pragma unroll
            for (int o = 4; o < 32; o <<= 1) {
                m0 = fmaxf(m0, __shfl_xor_sync(0xffffffffu, m0, o));
                m1 = fmaxf(m1, __shfl_xor_sync(0xffffffffu, m1, o));
            }
            if (lane < 4) {
                atomicMax(&cmax[cc],     fkey(m0));
                atomicMax(&cmax[cc + 1], fkey(m1));
            }
        }
        __syncthreads();
        if (tid < 128)
            atomicMax(&g_featkeys[(size_t)batch*1024 + colbase + tid], cmax[tid]);
        __syncthreads();
    }
}

// ---------------------------------------------------------------------------
// BF16 mma GEMM, EPI 0 = fp32 store + optional bias (feA GEMMs)
// ---------------------------------------------------------------------------
template<int EPI>
__global__ void __launch_bounds__(256) mma_gemm(
    int aid, int bid, const float* __restrict__ bias, int cid,
    int N, int K, int rows_per_batch)
{
    __shared__ __align__(16) bf16 As[2][128*SROW];
    __shared__ __align__(16) bf16 Bs[2][128*SROW];

    const bf16* A = scratch_bf16(aid) + (size_t)(blockIdx.y * 128) * K;
    const bf16* B = scratch_bf16(bid) + (size_t)(blockIdx.x * 128) * K;

    const int tid  = threadIdx.x;
    const int lane = tid & 31, wid = tid >> 5;
    const int wm = wid & 3, wn = wid >> 2;

    float acc[2][8][4];
#pragma unroll
    for (int mt = 0; mt < 2; mt++)
#pragma unroll
        for (int nt = 0; nt < 8; nt++)
#pragma unroll
            for (int j = 0; j < 4; j++) acc[mt][nt][j] = 0.0f;

    const unsigned aBase = (unsigned)__cvta_generic_to_shared(&As[0][0]);
    const unsigned bBase = (unsigned)__cvta_generic_to_shared(&Bs[0][0]);

    unsigned aoff[2], boff[4];
#pragma unroll
    for (int mt = 0; mt < 2; mt++)
        aoff[mt] = ((wm*32 + mt*16 + (lane & 15)) * SROW + ((lane >> 4) << 3)) * 2;
#pragma unroll
    for (int ntp = 0; ntp < 4; ntp++)
        boff[ntp] = ((wn*64 + ntp*16 + ((lane & 16) >> 1) + (lane & 7)) * SROW
                     + (lane & 8)) * 2;

    auto load_tile = [&](int s, int k0) {
#pragma unroll
        for (int i = 0; i < 2; i++) {
            int c = tid + (i << 8);
            int row = c >> 2, seg = c & 3;
            unsigned d = row * SROW + seg * 8;
            cpa16(aBase + s*STAGE_B + d*2, A + (size_t)row*K + k0 + seg*8);
            cpa16(bBase + s*STAGE_B + d*2, B + (size_t)row*K + k0 + seg*8);
        }
        asm volatile("cp.async.commit_group;");
    };

    load_tile(0, 0);
    const int KT = K >> 5;
    for (int kt = 0; kt < KT; kt++) {
        if (kt + 1 < KT) {
            load_tile((kt + 1) & 1, (kt + 1) << 5);
            asm volatile("cp.async.wait_group 1;");
        } else {
            asm volatile("cp.async.wait_group 0;");
        }
        __syncthreads();
        unsigned sOff = (kt & 1) * STAGE_B;
#pragma unroll
        for (int ks = 0; ks < 2; ks++) {
            unsigned af[2][4], bfr[8][2];
#pragma unroll
            for (int mt = 0; mt < 2; mt++)
                ldsm4(af[mt][0], af[mt][1], af[mt][2], af[mt][3],
                      aBase + sOff + aoff[mt] + ks*32);
#pragma unroll
            for (int ntp = 0; ntp < 4; ntp++) {
                unsigned r0, r1, r2, r3;
                ldsm4(r0, r1, r2, r3, bBase + sOff + boff[ntp] + ks*32);
                bfr[2*ntp][0] = r0;   bfr[2*ntp][1] = r1;
                bfr[2*ntp+1][0] = r2; bfr[2*ntp+1][1] = r3;
            }
#pragma unroll
            for (int mt = 0; mt < 2; mt++)
#pragma unroll
                for (int nt = 0; nt < 8; nt++)
                    mma_bf16(acc[mt][nt], af[mt], bfr[nt]);
        }
        __syncthreads();
    }

    const int row0  = blockIdx.y * 128 + wm * 32;
    const int col0g = blockIdx.x * 128 + wn * 64;

    float* C = scratch_f32(cid);
#pragma unroll
    for (int mt = 0; mt < 2; mt++) {
        int r = row0 + mt*16 + (lane >> 2);
#pragma unroll
        for (int nt = 0; nt < 8; nt++) {
            int c = col0g + nt*8 + (lane & 3)*2;
            float bb0 = bias ? bias[c]     : 0.0f;
            float bb1 = bias ? bias[c + 1] : 0.0f;
            float2 v0 = {acc[mt][nt][0] + bb0, acc[mt][nt][1] + bb1};
            float2 v1 = {acc[mt][nt][2] + bb0, acc[mt][nt][3] + bb1};
            *(float2*)(C + (size_t)r*N + c)       = v0;
            *(float2*)(C + (size_t)(r + 8)*N + c) = v1;
        }
    }
    (void)rows_per_batch;
}

// ---------------------------------------------------------------------------
// Fused fold GEMM (foldpre in A-fill, W2 GEMM, W3 projection epilogue)
// ---------------------------------------------------------------------------
__global__ void __launch_bounds__(256) fold_gemm_fused(
    int feaid, int stage, const float* __restrict__ w1, int bidW,
    const float* __restrict__ b2, const float* __restrict__ W3,
    const float* __restrict__ b3, int outid)
{
    __shared__ __align__(16) bf16 As[2][128*SROW];
    __shared__ __align__(16) bf16 Bs[2][128*SROW];
    __shared__ bf16  w1xs[512], w1ys[512], w1zs[512];
    __shared__ float l0s[128], l1s[128], l2s[128];
    __shared__ float w3s[128*3];
    __shared__ float b2s[128];

    const int K = 512;
    const float* feA = scratch_f32(feaid);
    const bf16* B = scratch_bf16(bidW) + (size_t)(blockIdx.x * 128) * K;

    const int tid  = threadIdx.x;
    const int lane = tid & 31, wid = tid >> 5;
    const int wm = wid & 3, wn = wid >> 2;

    if (tid < 128) {
        int cg = blockIdx.x*128 + tid;
        w3s[tid*3+0] = W3[cg*3+0];
        w3s[tid*3+1] = W3[cg*3+1];
        w3s[tid*3+2] = W3[cg*3+2];
        b2s[tid] = b2[cg];
        int gr = blockIdx.y*128 + tid;
        if (stage == 1) {
            int bg = gr / 36;
            int g = gr - bg * 36;
            l0s[tid] = c_lin[g / 6];
            l1s[tid] = c_lin[g % 6];
            l2s[tid] = 0.0f;
        } else {
            l0s[tid] = g_fold1[gr*3+0];
            l1s[tid] = g_fold1[gr*3+1];
            l2s[tid] = g_fold1[gr*3+2];
        }
    }
    for (int i = tid; i < 512; i += 256) {
        w1xs[i] = __float2bfloat16(w1[1024*512 + i]);
        w1ys[i] = __float2bfloat16(w1[1025*512 + i]);
        w1zs[i] = (stage == 2) ? __float2bfloat16(w1[1026*512 + i])
                               : __float2bfloat16(0.0f);
    }

    const unsigned aBase = (unsigned)__cvta_generic_to_shared(&As[0][0]);
    const unsigned bBase = (unsigned)__cvta_generic_to_shared(&Bs[0][0]);

    const int fr  = tid >> 1;
    const int fkk = (tid & 1) << 4;
    const int fbg = (blockIdx.y*128 + fr) / 36;
    const float* faRow = feA + (size_t)fbg * 512;

    auto fillA = [&](int s, int k0) {
        float l0 = l0s[fr], l1 = l1s[fr], l2 = l2s[fr];
        const float4* fa = (const float4*)(faRow + k0 + fkk);
        unsigned pk[8];
#pragma unroll
        for (int q = 0; q < 4; q++) {
            float4 f = fa[q];
            int kb = k0 + fkk + q*4;
            float v0 = fmaf(l2, __bfloat162float(w1zs[kb+0]),
                       fmaf(l1, __bfloat162float(w1ys[kb+0]),
                       fmaf(l0, __bfloat162float(w1xs[kb+0]), f.x)));
            float v1 = fmaf(l2, __bfloat162float(w1zs[kb+1]),
                       fmaf(l1, __bfloat162float(w1ys[kb+1]),
                       fmaf(l0, __bfloat162float(w1xs[kb+1]), f.y)));
            float v2 = fmaf(l2, __bfloat162float(w1zs[kb+2]),
                       fmaf(l1, __bfloat162float(w1ys[kb+2]),
                       fmaf(l0, __bfloat162float(w1xs[kb+2]), f.z)));
            float v3 = fmaf(l2, __bfloat162float(w1zs[kb+3]),
                       fmaf(l1, __bfloat162float(w1ys[kb+3]),
                       fmaf(l0, __bfloat162float(w1xs[kb+3]), f.w)));
            __nv_bfloat162 p0 = __floats2bfloat162_rn(fmaxf(v0, 0.0f), fmaxf(v1, 0.0f));
            __nv_bfloat162 p1 = __floats2bfloat162_rn(fmaxf(v2, 0.0f), fmaxf(v3, 0.0f));
            pk[q*2+0] = *(unsigned*)&p0;
            pk[q*2+1] = *(unsigned*)&p1;
        }
        uint4* dst = (uint4*)&As[s][fr*SROW + fkk];
        dst[0] = make_uint4(pk[0], pk[1], pk[2], pk[3]);
        dst[1] = make_uint4(pk[4], pk[5], pk[6], pk[7]);
    };

    auto loadB = [&](int s, int k0) {
#pragma unroll
        for (int i = 0; i < 2; i++) {
            int c = tid + (i << 8);
            int rr = c >> 2, sg = c & 3;
            cpa16(bBase + s*STAGE_B + (rr*SROW + sg*8)*2, B + (size_t)rr*K + k0 + sg*8);
        }
        asm volatile("cp.async.commit_group;");
    };

    float acc[2][8][4];
#pragma unroll
    for (int mt = 0; mt < 2; mt++)
#pragma unroll
        for (int nt = 0; nt < 8; nt++)
#pragma unroll
            for (int j = 0; j < 4; j++) acc[mt][nt][j] = 0.0f;

    unsigned aoff[2], boff[4];
#pragma unroll
    for (int mt = 0; mt < 2; mt++)
        aoff[mt] = ((wm*32 + mt*16 + (lane & 15)) * SROW + ((lane >> 4) << 3)) * 2;
#pragma unroll
    for (int ntp = 0; ntp < 4; ntp++)
        boff[ntp] = ((wn*64 + ntp*16 + ((lane & 16) >> 1) + (lane & 7)) * SROW
                     + (lane & 8)) * 2;

    loadB(0, 0);
    __syncthreads();
    fillA(0, 0);

    const int KT = K >> 5;
    for (int kt = 0; kt < KT; kt++) {
        int s = kt & 1;
        if (kt + 1 < KT) {
            loadB(s ^ 1, (kt + 1) << 5);
            asm volatile("cp.async.wait_group 1;");
        } else {
            asm volatile("cp.async.wait_group 0;");
        }
        __syncthreads();
        if (kt + 1 < KT) fillA(s ^ 1, (kt + 1) << 5);
        unsigned sOff = s * STAGE_B;
#pragma unroll
        for (int ks = 0; ks < 2; ks++) {
            unsigned af[2][4], bfr[8][2];
#pragma unroll
            for (int mt = 0; mt < 2; mt++)
                ldsm4(af[mt][0], af[mt][1], af[mt][2], af[mt][3],
                      aBase + sOff + aoff[mt] + ks*32);
#pragma unroll
            for (int ntp = 0; ntp < 4; ntp++) {
                unsigned r0, r1, r2, r3;
                ldsm4(r0, r1, r2, r3, bBase + sOff + boff[ntp] + ks*32);
                bfr[2*ntp][0] = r0;   bfr[2*ntp][1] = r1;
                bfr[2*ntp+1][0] = r2; bfr[2*ntp+1][1] = r3;
            }
#pragma unroll
            for (int mt = 0; mt < 2; mt++)
#pragma unroll
                for (int nt = 0; nt < 8; nt++)
                    mma_bf16(acc[mt][nt], af[mt], bfr[nt]);
        }
        __syncthreads();
    }

    float* out = scratch_f32(outid);
    const int row0 = blockIdx.y * 128 + wm * 32;
    float p[4][3];
#pragma unroll
    for (int i = 0; i < 4; i++)
#pragma unroll
        for (int c = 0; c < 3; c++) p[i][c] = 0.0f;

#pragma unroll
    for (int nt = 0; nt < 8; nt++) {
        int cc0 = wn*64 + nt*8 + (lane & 3)*2;
        int cc1 = cc0 + 1;
        float bb0 = b2s[cc0], bb1 = b2s[cc1];
        float h00 = fmaxf(acc[0][nt][0] + bb0, 0.0f);
        float h01 = fmaxf(acc[0][nt][1] + bb1, 0.0f);
        float h02 = fmaxf(acc[0][nt][2] + bb0, 0.0f);
        float h03 = fmaxf(acc[0][nt][3] + bb1, 0.0f);
        float h10 = fmaxf(acc[1][nt][0] + bb0, 0.0f);
        float h11 = fmaxf(acc[1][nt][1] + bb1, 0.0f);
        float h12 = fmaxf(acc[1][nt][2] + bb0, 0.0f);
        float h13 = fmaxf(acc[1][nt][3] + bb1, 0.0f);
#pragma unroll
        for (int c = 0; c < 3; c++) {
            float w0 = w3s[cc0*3 + c], w1v = w3s[cc1*3 + c];
            p[0][c] = fmaf(h00, w0, fmaf(h01, w1v, p[0][c]));
            p[1][c] = fmaf(h02, w0, fmaf(h03, w1v, p[1][c]));
            p[2][c] = fmaf(h10, w0, fmaf(h11, w1v, p[2][c]));
            p[3][c] = fmaf(h12, w0, fmaf(h13, w1v, p[3][c]));
        }
    }
#pragma unroll
    for (int o = 1; o <= 2; o <<= 1)
#pragma unroll
        for (int i = 0; i < 4; i++)
#pragma unroll
            for (int c = 0; c < 3; c++)
                p[i][c] += __shfl_xor_sync(0xffffffffu, p[i][c], o);

    if ((lane & 3) == 0) {
        bool addb3 = (blockIdx.x == 0) && (wn == 0);
#pragma unroll
        for (int i = 0; i < 4; i++) {
            int r = row0 + (i >> 1)*16 + (lane >> 2) + (i & 1)*8;
#pragma unroll
            for (int c = 0; c < 3; c++) {
                float v = p[i][c];
                if (addb3) v += b3[c];
                atomicAdd(&out[r*3 + c], v);
            }
        }
    }
}

// ---------------------------------------------------------------------------
// Small per-row MLP
// ---------------------------------------------------------------------------
__global__ void mlp_row_kernel(int xid, int xkeys, const float* __restrict__ W,
                               const float* __restrict__ bias, int yid,
                               int K, int N, int act)
{
    __shared__ float sx[1024];
    float* Y = scratch_f32(yid);
    int b = blockIdx.y;
    int col = blockIdx.x * blockDim.x + threadIdx.x;
    if (xkeys) {
        for (int k = threadIdx.x; k < K; k += blockDim.x)
            sx[k] = unfkey(g_featkeys[b*K + k]);
    } else {
        const float* X = scratch_f32(xid);
        for (int k = threadIdx.x; k < K; k += blockDim.x) sx[k] = X[b*K + k];
    }
    __syncthreads();
    float s0 = 0.0f, s1 = 0.0f, s2 = 0.0f, s3 = 0.0f;
    for (int k = 0; k < K; k += 4) {
        s0 = fmaf(sx[k+0], W[(size_t)(k+0)*N + col], s0);
        s1 = fmaf(sx[k+1], W[(size_t)(k+1)*N + col], s1);
        s2 = fmaf(sx[k+2], W[(size_t)(k+2)*N + col], s2);
        s3 = fmaf(sx[k+3], W[(size_t)(k+3)*N + col], s3);
    }
    float s = ((s0 + s1) + (s2 + s3)) + bias[col];
    if (act) s = fmaxf(s, 0.0f);
    Y[b*N + col] = s;
}

// ---------------------------------------------------------------------------
// pos + fe (bf16), 256 threads
// ---------------------------------------------------------------------------
__global__ void __launch_bounds__(256) posfe_kernel(
    const float* __restrict__ w1, const float* __restrict__ b1,
    const float* __restrict__ w2, const float* __restrict__ b2)
{
    int bg = blockIdx.x, t = threadIdx.x, b = bg >> 6;
    __shared__ float h[128];
    float cx = g_centers[bg*3], cy = g_centers[bg*3+1], cz = g_centers[bg*3+2];
    if (t < 128) {
        float v = cx*w1[t] + cy*w1[128+t] + cz*w1[256+t] + b1[t];
        h[t] = gelu_exact(v);
    }
    __syncthreads();
    for (int q = 0; q < 4; q++) {
        int j = (q << 8) + t;
        float s = 0.0f;
#pragma unroll 8
        for (int k = 0; k < 128; k++) s = fmaf(h[k], w2[k*1024 + j], s);
        float feat = unfkey(g_featkeys[b*1024 + j]);
        g_feb[bg*1024 + j] = __float2bfloat16(s + b2[j] + feat);
    }
}

// ---------------------------------------------------------------------------
// Chamfer fine
// ---------------------------------------------------------------------------
__global__ void chamfer_fine_kernel() {
    int bg = blockIdx.x, t = threadIdx.x;  // 128 threads
    __shared__ float F[108], Nn[96], rm[36], cm[32];
    for (int i = t; i < 108; i += 128) F[i] = g_fold2[bg*108 + i];
    for (int i = t; i < 96;  i += 128) Nn[i] = g_neigh[bg*96 + i];
    __syncthreads();
    if (t < 36) {
        float fx = F[t*3], fy = F[t*3+1], fz = F[t*3+2], mn = FLT_MAX;
        for (int j = 0; j < 32; j++) {
            float dx = fx-Nn[j*3], dy = fy-Nn[j*3+1], dz = fz-Nn[j*3+2];
            mn = fminf(mn, dx*dx + dy*dy + dz*dz);
        }
        rm[t] = mn;
    } else if (t < 68) {
        int j = t - 36;
        float nx = Nn[j*3], ny = Nn[j*3+1], nz = Nn[j*3+2], mn = FLT_MAX;
        for (int i = 0; i < 36; i++) {
            float dx = F[i*3]-nx, dy = F[i*3+1]-ny, dz = F[i*3+2]-nz;
            mn = fminf(mn, dx*dx + dy*dy + dz*dz);
        }
        cm[j] = mn;
    }
    __syncthreads();
    if (t == 0) {
        float s = 0.0f;
        for (int i = 0; i < 36; i++) s += rm[i];
        atomicAdd(&g_acc[0], s);
        s = 0.0f;
        for (int j = 0; j < 32; j++) s += cm[j];
        atomicAdd(&g_acc[1], s);
    }
}

// ---------------------------------------------------------------------------
// Chamfer coarse
// ---------------------------------------------------------------------------
__global__ void __launch_bounds__(512) chamfer_coarse_kernel() {
    int t = threadIdx.x;
    __shared__ float C[1536], Ce[1536], s1[512], s2[512];
    for (int i = t; i < 1536; i += 512) { C[i] = g_coarse[i]; Ce[i] = g_centers[i]; }
    __syncthreads();
    int b = t >> 6, i = t & 63;
    const float* cb = &C[b*192];
    const float* eb = &Ce[b*192];
    float x = cb[i*3], y = cb[i*3+1], z = cb[i*3+2], mn = FLT_MAX;
    for (int j = 0; j < 64; j++) {
        float dx = x-eb[j*3], dy = y-eb[j*3+1], dz = z-eb[j*3+2];
        mn = fminf(mn, dx*dx + dy*dy + dz*dz);
    }
    s1[t] = mn;
    float x2 = eb[i*3], y2 = eb[i*3+1], z2 = eb[i*3+2];
    mn = FLT_MAX;
    for (int j = 0; j < 64; j++) {
        float dx = x2-cb[j*3], dy = y2-cb[j*3+1], dz = z2-cb[j*3+2];
        mn = fminf(mn, dx*dx + dy*dy + dz*dz);
    }
    s2[t] = mn;
    __syncthreads();
    for (int s = 256; s; s >>= 1) {
        if (t < s) { s1[t] += s1[t+s]; s2[t] += s2[t+s]; }
        __syncthreads();
    }
    if (t == 0) { g_acc[2] = s1[0]; g_acc[3] = s2[0]; }
}

__global__ void finalize_kernel(float* __restrict__ out) {
    out[0] = g_acc[0] / (float)(FROWS) + g_acc[1] / (float)(BGROUPS*GS);
    out[1] = g_acc[2] / 512.0f + g_acc[3] / 512.0f;
}

// ---------------------------------------------------------------------------
// launch — multi-stream DAG; encl3 remains capture launch #5
// ---------------------------------------------------------------------------
extern "C" void kernel_launch(void* const* d_in, const int* in_sizes, int n_in,
                              void* d_out, int out_size)
{
    (void)in_sizes; (void)n_in; (void)out_size;
    const float* corrupted = (const float*)d_in[0];
    const float* pts       = (const float*)d_in[1];
    const float* enc_w1 = (const float*)d_in[2];
    const float* enc_b1 = (const float*)d_in[3];
    const float* enc_w2 = (const float*)d_in[4];
    const float* enc_b2 = (const float*)d_in[5];
    const float* enc_w3 = (const float*)d_in[6];
    const float* enc_b3 = (const float*)d_in[7];
    const float* pe_w1  = (const float*)d_in[8];
    const float* pe_b1  = (const float*)d_in[9];
    const float* pe_w2  = (const float*)d_in[10];
    const float* pe_b2  = (const float*)d_in[11];
    const float* cp_w1  = (const float*)d_in[12];
    const float* cp_b1  = (const float*)d_in[13];
    const float* cp_w2  = (const float*)d_in[14];
    const float* cp_b2  = (const float*)d_in[15];
    const float* cp_w3  = (const float*)d_in[16];
    const float* cp_b3  = (const float*)d_in[17];
    const float* f1_w1  = (const float*)d_in[18];
    const float* f1_b1  = (const float*)d_in[19];
    const float* f1_w2  = (const float*)d_in[20];
    const float* f1_b2  = (const float*)d_in[21];
    const float* f1_w3  = (const float*)d_in[22];
    const float* f1_b3  = (const float*)d_in[23];
    const float* f2_w1  = (const float*)d_in[24];
    const float* f2_b1  = (const float*)d_in[25];
    const float* f2_w2  = (const float*)d_in[26];
    const float* f2_b2  = (const float*)d_in[27];
    const float* f2_w3  = (const float*)d_in[28];
    const float* f2_b3  = (const float*)d_in[29];
    float* out = (float*)d_out;

    // one-time host resources (no device memory involved)
    static cudaStream_t sB = nullptr, sC = nullptr;
    static cudaEvent_t eFork, eGeo, eEnc, ePos, eFeA2, eCoarse, eWf, eW3;
    if (sB == nullptr) {
        cudaStreamCreateWithFlags(&sB, cudaStreamNonBlocking);
        cudaStreamCreateWithFlags(&sC, cudaStreamNonBlocking);
        cudaEventCreateWithFlags(&eFork,   cudaEventDisableTiming);
        cudaEventCreateWithFlags(&eGeo,    cudaEventDisableTiming);
        cudaEventCreateWithFlags(&eEnc,    cudaEventDisableTiming);
        cudaEventCreateWithFlags(&ePos,    cudaEventDisableTiming);
        cudaEventCreateWithFlags(&eFeA2,   cudaEventDisableTiming);
        cudaEventCreateWithFlags(&eCoarse, cudaEventDisableTiming);
        cudaEventCreateWithFlags(&eWf,     cudaEventDisableTiming);
        cudaEventCreateWithFlags(&eW3,     cudaEventDisableTiming);
        cudaFuncSetAttribute(enc12_kernel,
                             cudaFuncAttributeMaxDynamicSharedMemorySize, ENC12_SMEM);
        cudaFuncSetAttribute(encl3_kernel,
                             cudaFuncAttributeMaxDynamicSharedMemorySize, ENC3_SMEM);
    }

    // #0 main: minimal init
    zero_main_kernel<<<32, 256>>>();
    cudaEventRecord(eFork, 0);

    // #1 sC: w3 transpose (needed by encl3)
    cudaStreamWaitEvent(sC, eFork, 0);
    wtrans_one<<<1024, 256, 0, sC>>>(enc_w3, 256, 1024, BID_W3T);
    cudaEventRecord(eW3, sC);

    // #2 main: w2 transpose   #3 main: enc12
    wtrans_one<<<128, 256>>>(enc_w2, 128, 256, BID_W2T);
    enc12_kernel<<<dim3(2, 512), 256, ENC12_SMEM>>>(corrupted, enc_w1, enc_b1, enc_b2);

    // #4 sB: fps
    cudaStreamWaitEvent(sB, eFork, 0);
    fps_kernel<<<NB, 1024, 0, sB>>>(pts);

    // #5 main: encl3 (profiled launch)
    cudaStreamWaitEvent(0, eW3, 0);
    encl3_kernel<<<dim3(4, 512), 256, ENC3_SMEM>>>(enc_b3);
    cudaEventRecord(eEnc, 0);

    // #6 sB: knn
    knn_kernel<<<BGROUPS, 256, 0, sB>>>(pts);
    cudaEventRecord(eGeo, sB);

    // #7-8 sC: fold zero + fold transposes
    zero_fold_kernel<<<(FROWS*3 + 255)/256, 256, 0, sC>>>();
    wtrans_fold<<<dim3(2048, 4), 256, 0, sC>>>(f1_w1, f2_w1, f1_w2, f2_w2);
    cudaEventRecord(eWf, sC);

    // sC: coarse MLP chain + coarse chamfer
    cudaStreamWaitEvent(sC, eEnc, 0);
    mlp_row_kernel<<<dim3(8, NB), 128, 0, sC>>>(0, 1, cp_w1, cp_b1, FID_C1, 1024, 1024, 1);
    mlp_row_kernel<<<dim3(8, NB), 128, 0, sC>>>(FID_C1, 0, cp_w2, cp_b2, FID_C2, 1024, 1024, 1);
    mlp_row_kernel<<<dim3(1, NB), 192, 0, sC>>>(FID_C2, 0, cp_w3, cp_b3, FID_COARSE, 1024, 192, 0);
    cudaStreamWaitEvent(sC, eGeo, 0);
    chamfer_coarse_kernel<<<1, 512, 0, sC>>>();
    cudaEventRecord(eCoarse, sC);

    // main: posfe (centers + featkeys)
    cudaStreamWaitEvent(0, eGeo, 0);
    posfe_kernel<<<BGROUPS, 256>>>(pe_w1, pe_b1, pe_w2, pe_b2);
    cudaEventRecord(ePos, 0);

    // feA1 main (needs f1w1t), feA2 on stream B (needs f2w1t + fe)
    cudaStreamWaitEvent(0, eWf, 0);
    mma_gemm<0><<<dim3(4, 4), 256>>>(BID_FE, BID_F1W1T, f1_b1, FID_FEA1, 512, 1024, 0);
    cudaStreamWaitEvent(sB, ePos, 0);
    cudaStreamWaitEvent(sB, eWf, 0);
    mma_gemm<0><<<dim3(4, 4), 256, 0, sB>>>(BID_FE, BID_F2W1T, f2_b1, FID_FEA2, 512, 1024, 0);
    cudaEventRecord(eFeA2, sB);

    // fold stage 1 (fused foldpre + GEMM + W3 projection)
    fold_gemm_fused<<<dim3(4, 144), 256>>>(FID_FEA1, 1, f1_w1, BID_F1W2T,
                                           f1_b2, f1_w3, f1_b3, FID_FOLD1);

    // fold stage 2 (needs feA2 + fold1)
    cudaStreamWaitEvent(0, eFeA2, 0);
    fold_gemm_fused<<<dim3(4, 144), 256>>>(FID_FEA2, 2, f2_w1, BID_F2W2T,
                                           f2_b2, f2_w3, f2_b3, FID_FOLD2);

    // fine chamfer
    chamfer_fine_kernel<<<BGROUPS, 128>>>();

    // join coarse chain, finalize
    cudaStreamWaitEvent(0, eCoarse, 0);
    finalize_kernel<<<1, 1>>>(out);
}

// round 16
// speedup vs baseline: 1.8997x; 1.0262x over previous
#include <cuda_runtime.h>
#include <cuda_bf16.h>
#include <math.h>
#include <float.h>

// ---------------------------------------------------------------------------
// Problem constants
// ---------------------------------------------------------------------------
#define NB       8
#define NPTS     8192
#define NC       64
#define GS       32
#define BGROUPS  512
#define GRID_PTS 36
#define FROWS    (BGROUPS*GRID_PTS)   // 18432
#define ENC_ROWS (NB*NPTS)            // 65536

typedef __nv_bfloat16 bf16;

// ---------------------------------------------------------------------------
// Scratch (device globals; no allocation anywhere)
// ---------------------------------------------------------------------------
__device__ bf16     g_h2b[ENC_ROWS*256];
__device__ bf16     g_feb[BGROUPS*1024];
__device__ bf16     g_w2t[256*128];
__device__ bf16     g_w3t[1024*256];
__device__ bf16     g_f1w1t[512*1024];
__device__ bf16     g_f2w1t[512*1024];
__device__ bf16     g_f1w2t[512*512];
__device__ bf16     g_f2w2t[512*512];

__device__ float    g_feA1[BGROUPS*512];
__device__ float    g_feA2[BGROUPS*512];
__device__ unsigned g_featkeys[NB*1024];
__device__ float    g_centers[BGROUPS*3];
__device__ float    g_neigh[BGROUPS*GS*3];
__device__ float    g_fold1[FROWS*3];
__device__ float    g_fold2[FROWS*3];
__device__ float    g_c1[NB*1024];
__device__ float    g_c2[NB*1024];
__device__ float    g_coarse[NB*192];
__device__ float    g_acc[4];

__constant__ float c_lin[6] = {-0.3f,-0.18f,-0.06f,0.06f,0.18f,0.3f};

// bf16 scratch ids
#define BID_H2     0
#define BID_FE     1
#define BID_W2T    2
#define BID_W3T    3
#define BID_F1W1T  4
#define BID_F2W1T  5
#define BID_F1W2T  6
#define BID_F2W2T  7

// f32 scratch ids
#define FID_FEA1   0
#define FID_FEA2   1
#define FID_C1     2
#define FID_C2     3
#define FID_COARSE 4
#define FID_FOLD1  5
#define FID_FOLD2  6

__device__ __forceinline__ bf16* scratch_bf16(int id) {
    switch (id) {
        case BID_H2:    return g_h2b;
        case BID_FE:    return g_feb;
        case BID_W2T:   return g_w2t;
        case BID_W3T:   return g_w3t;
        case BID_F1W1T: return g_f1w1t;
        case BID_F2W1T: return g_f2w1t;
        case BID_F1W2T: return g_f1w2t;
        default:        return g_f2w2t;
    }
}
__device__ __forceinline__ float* scratch_f32(int id) {
    switch (id) {
        case FID_FEA1:  return g_feA1;
        case FID_FEA2:  return g_feA2;
        case FID_C1:    return g_c1;
        case FID_C2:    return g_c2;
        case FID_COARSE:return g_coarse;
        case FID_FOLD1: return g_fold1;
        default:        return g_fold2;
    }
}

__device__ __forceinline__ unsigned fkey(float f) {
    unsigned u = __float_as_uint(f);
    return (u & 0x80000000u) ? ~u : (u | 0x80000000u);
}
__device__ __forceinline__ float unfkey(unsigned k) {
    return __uint_as_float((k & 0x80000000u) ? (k & 0x7fffffffu) : ~k);
}

__device__ __forceinline__ float gelu_exact(float x) {
    return 0.5f * x * (1.0f + erff(x * 0.7071067811865476f));
}

__device__ __forceinline__ void cpa16(unsigned dst, const void* src) {
    asm volatile("cp.async.cg.shared.global [%0], [%1], 16;" :: "r"(dst), "l"(src));
}

__device__ __forceinline__ void ldsm4(unsigned& r0, unsigned& r1, unsigned& r2,
                                      unsigned& r3, unsigned addr) {
    asm volatile("ldmatrix.sync.aligned.m8n8.x4.shared.b16 {%0,%1,%2,%3}, [%4];"
        : "=r"(r0), "=r"(r1), "=r"(r2), "=r"(r3) : "r"(addr));
}

__device__ __forceinline__ void mma_bf16(float* c, const unsigned* a, const unsigned* b) {
    asm volatile(
        "mma.sync.aligned.m16n8k16.row.col.f32.bf16.bf16.f32 "
        "{%0,%1,%2,%3}, {%4,%5,%6,%7}, {%8,%9}, {%0,%1,%2,%3};"
        : "+f"(c[0]), "+f"(c[1]), "+f"(c[2]), "+f"(c[3])
        : "r"(a[0]), "r"(a[1]), "r"(a[2]), "r"(a[3]), "r"(b[0]), "r"(b[1]));
}

__device__ __forceinline__ void wredmax(float& v, int& i) {
#pragma unroll
    for (int o = 16; o; o >>= 1) {
        float v2 = __shfl_xor_sync(0xffffffffu, v, o);
        int   i2 = __shfl_xor_sync(0xffffffffu, i, o);
        if (v2 > v || (v2 == v && i2 < i)) { v = v2; i = i2; }
    }
}
__device__ __forceinline__ void wredmin(float& v, int& i) {
#pragma unroll
    for (int o = 16; o; o >>= 1) {
        float v2 = __shfl_xor_sync(0xffffffffu, v, o);
        int   i2 = __shfl_xor_sync(0xffffffffu, i, o);
        if (v2 < v || (v2 == v && i2 < i)) { v = v2; i = i2; }
    }
}

// ---------------------------------------------------------------------------
// init
// ---------------------------------------------------------------------------
__global__ void zero_main_kernel() {
    int i = blockIdx.x * 256 + threadIdx.x;
    if (i < NB*1024) g_featkeys[i] = 0u;
    if (i < 4)       g_acc[i] = 0.0f;
}
__global__ void zero_fold_kernel() {
    int i = blockIdx.x * 256 + threadIdx.x;
    if (i < FROWS*3) { g_fold1[i] = 0.0f; g_fold2[i] = 0.0f; }
}

// ---------------------------------------------------------------------------
// weight transpose + bf16: out[n*K+k] = bf16(W[k*N+n])
// ---------------------------------------------------------------------------
__global__ void wtrans_one(const float* __restrict__ W, int K, int N, int bid) {
    bf16* out = scratch_bf16(bid);
    int i = blockIdx.x * 256 + threadIdx.x;
    if (i < K * N) {
        int n = i / K, k = i - n * K;
        out[i] = __float2bfloat16(W[(size_t)k * N + n]);
    }
}

__global__ void wtrans_fold(const float* __restrict__ fw1a, const float* __restrict__ fw1b,
                            const float* __restrict__ fw2a, const float* __restrict__ fw2b)
{
    const float* W; int K, N; bf16* out;
    switch (blockIdx.y) {
        case 0: W = fw1a; K = 1024; N = 512; out = g_f1w1t; break;
        case 1: W = fw1b; K = 1024; N = 512; out = g_f2w1t; break;
        case 2: W = fw2a; K = 512;  N = 512; out = g_f1w2t; break;
        default:W = fw2b; K = 512;  N = 512; out = g_f2w2t; break;
    }
    int i = blockIdx.x * 256 + threadIdx.x;
    if (i < K * N) {
        int n = i / K, k = i - n * K;
        out[i] = __float2bfloat16(W[(size_t)k * N + n]);
    }
}

// ---------------------------------------------------------------------------
// Farthest point sampling
// ---------------------------------------------------------------------------
__global__ void __launch_bounds__(1024) fps_kernel(const float* __restrict__ pts) {
    int b = blockIdx.x, t = threadIdx.x;
    int lane = t & 31, wid = t >> 5;
    const float* P = pts + (size_t)b * NPTS * 3;
    __shared__ float sv[32];
    __shared__ int   si[32];
    __shared__ float cur[3];

    float px[8], py[8], pz[8], dd[8];
#pragma unroll
    for (int i = 0; i < 8; i++) {
        int p = (t << 3) + i;
        px[i] = P[p*3]; py[i] = P[p*3+1]; pz[i] = P[p*3+2];
    }
    if (t == 0) {
        cur[0] = P[0]; cur[1] = P[1]; cur[2] = P[2];
        g_centers[b*192+0] = P[0]; g_centers[b*192+1] = P[1]; g_centers[b*192+2] = P[2];
    }
    __syncthreads();
    float cx = cur[0], cy = cur[1], cz = cur[2];
#pragma unroll
    for (int i = 0; i < 8; i++) {
        float dx = px[i]-cx, dy = py[i]-cy, dz = pz[i]-cz;
        dd[i] = dx*dx + dy*dy + dz*dz;
    }
    for (int it = 1; it < NC; it++) {
        float bv = dd[0]; int bi = (t << 3);
#pragma unroll
        for (int i = 1; i < 8; i++)
            if (dd[i] > bv) { bv = dd[i]; bi = (t << 3) + i; }
        wredmax(bv, bi);
        if (lane == 0) { sv[wid] = bv; si[wid] = bi; }
        __syncthreads();
        if (wid == 0) {
            float v = sv[lane]; int i = si[lane];
            wredmax(v, i);
            if (lane == 0) {
                cur[0] = P[i*3]; cur[1] = P[i*3+1]; cur[2] = P[i*3+2];
                g_centers[b*192 + it*3+0] = cur[0];
                g_centers[b*192 + it*3+1] = cur[1];
                g_centers[b*192 + it*3+2] = cur[2];
            }
        }
        __syncthreads();
        cx = cur[0]; cy = cur[1]; cz = cur[2];
#pragma unroll
        for (int i = 0; i < 8; i++) {
            float dx = px[i]-cx, dy = py[i]-cy, dz = pz[i]-cz;
            dd[i] = fminf(dd[i], dx*dx + dy*dy + dz*dz);
        }
    }
}

// ---------------------------------------------------------------------------
// 32-NN grouping — incremental argmin
// ---------------------------------------------------------------------------
__global__ void __launch_bounds__(256) knn_kernel(const float* __restrict__ pts) {
    int bg = blockIdx.x, b = bg >> 6, t = threadIdx.x;
    int lane = t & 31, wid = t >> 5;
    const float* P = pts + (size_t)b * NPTS * 3;
    __shared__ float sd[NPTS];
    __shared__ float sv[8];
    __shared__ int   si[8];
    __shared__ int   swin;
    float cx = g_centers[bg*3], cy = g_centers[bg*3+1], cz = g_centers[bg*3+2];
    for (int p = t; p < NPTS; p += 256) {
        float dx = P[p*3]-cx, dy = P[p*3+1]-cy, dz = P[p*3+2]-cz;
        sd[p] = dx*dx + dy*dy + dz*dz;
    }
    __syncthreads();

    const int base = t << 5;
    float mv = FLT_MAX; int mi = base;
#pragma unroll 8
    for (int j = 0; j < 32; j++) {
        float v = sd[base + j];
        if (v < mv) { mv = v; mi = base + j; }
    }

    for (int k = 0; k < GS; k++) {
        float bv = mv; int bi = mi;
        wredmin(bv, bi);
        if (lane == 0) { sv[wid] = bv; si[wid] = bi; }
        __syncthreads();
        if (t < 32) {
            float v = (lane < 8) ? sv[lane] : FLT_MAX;
            int   i = (lane < 8) ? si[lane] : NPTS;
            wredmin(v, i);
            if (lane == 0) {
                swin = i;
                g_neigh[(bg*GS+k)*3+0] = P[i*3+0] - cx;
                g_neigh[(bg*GS+k)*3+1] = P[i*3+1] - cy;
                g_neigh[(bg*GS+k)*3+2] = P[i*3+2] - cz;
            }
        }
        __syncthreads();
        int win = swin;
        if ((win >> 5) == t) {
            sd[win] = FLT_MAX;
            mv = FLT_MAX; mi = base;
#pragma unroll 8
            for (int j = 0; j < 32; j++) {
                float v = sd[base + j];
                if (v < mv) { mv = v; mi = base + j; }
            }
        }
        __syncthreads();
    }
}

// ---------------------------------------------------------------------------
// Fused enc layer1 + layer2 — A built once, loop over both 128-col B blocks
// (double-buffered, both prefetched). grid (1, 512). smem ~105KB.
// ---------------------------------------------------------------------------
#define SR12 136
#define ENC12_SMEM (3*128*SR12*2)

__global__ void __launch_bounds__(256) enc12_kernel(
    const float* __restrict__ x, const float* __restrict__ w1,
    const float* __restrict__ b1, const float* __restrict__ b2)
{
    extern __shared__ __align__(16) bf16 dyn12[];
    bf16* As  = dyn12;                 // 128 x 136
    bf16* Bs0 = dyn12 + 128*SR12;      // 128 x 136
    bf16* Bs1 = dyn12 + 2*128*SR12;    // 128 x 136
    __shared__ float  sx[384];
    __shared__ float4 swc[128];

    const int tid = threadIdx.x, lane = tid & 31, wid = tid >> 5;
    const int wm = wid & 3, wn = wid >> 2;
    const int br = blockIdx.y;

    const unsigned aBase = (unsigned)__cvta_generic_to_shared(As);
    const unsigned bBase0 = (unsigned)__cvta_generic_to_shared(Bs0);
    const unsigned bBase1 = (unsigned)__cvta_generic_to_shared(Bs1);

    // prefetch both B blocks (w2t: 256 rows x 128 k)
#pragma unroll
    for (int i = 0; i < 8; i++) {
        int chunk = i * 256 + tid;
        int row = chunk >> 4, seg = chunk & 15;
        cpa16(bBase0 + (row*SR12 + seg*8)*2, g_w2t + (size_t)row*128 + seg*8);
    }
    asm volatile("cp.async.commit_group;");
#pragma unroll
    for (int i = 0; i < 8; i++) {
        int chunk = i * 256 + tid;
        int row = chunk >> 4, seg = chunk & 15;
        cpa16(bBase1 + (row*SR12 + seg*8)*2, g_w2t + (size_t)(128 + row)*128 + seg*8);
    }
    asm volatile("cp.async.commit_group;");

    if (tid < 96) *(float4*)&sx[tid*4] = *(const float4*)(x + (size_t)br*384 + tid*4);
    if (tid < 128) {
        float4 w; w.x = w1[tid]; w.y = w1[128+tid]; w.z = w1[256+tid]; w.w = b1[tid];
        swc[tid] = w;
    }
    __syncthreads();   // sx/swc visible

    // build full A (128 x 128) once
    {
        const int r = tid >> 1;
        const int kb0 = (tid & 1) * 64;
        const float x0 = sx[r*3], x1 = sx[r*3+1], x2 = sx[r*3+2];
#pragma unroll
        for (int blk = 0; blk < 8; blk++) {
            unsigned pk[4];
#pragma unroll
            for (int q = 0; q < 4; q++) {
                int k = kb0 + blk*8 + q*2;
                float4 wa = swc[k], wb = swc[k+1];
                float va = fmaxf(fmaf(x0, wa.x, fmaf(x1, wa.y, fmaf(x2, wa.z, wa.w))), 0.0f);
                float vb = fmaxf(fmaf(x0, wb.x, fmaf(x1, wb.y, fmaf(x2, wb.z, wb.w))), 0.0f);
                __nv_bfloat162 p = __floats2bfloat162_rn(va, vb);
                pk[q] = *(unsigned*)&p;
            }
            *(uint4*)&As[r*SR12 + kb0 + blk*8] = make_uint4(pk[0], pk[1], pk[2], pk[3]);
        }
    }

    unsigned aoff[2], boff[4];
#pragma unroll
    for (int mt = 0; mt < 2; mt++)
        aoff[mt] = ((wm*32 + mt*16 + (lane & 15)) * SR12 + ((lane >> 4) << 3)) * 2;
#pragma unroll
    for (int ntp = 0; ntp < 4; ntp++)
        boff[ntp] = ((wn*64 + ntp*16 + ((lane & 16) >> 1) + (lane & 7)) * SR12
                     + (lane & 8)) * 2;

    const int row0 = br*128 + wm*32;

    asm volatile("cp.async.wait_group 1;");
    __syncthreads();   // A + B0 ready

    for (int bc = 0; bc < 2; bc++) {
        const unsigned bB = bc ? bBase1 : bBase0;

        float acc[2][8][4];
#pragma unroll
        for (int mt = 0; mt < 2; mt++)
#pragma unroll
            for (int nt = 0; nt < 8; nt++)
#pragma unroll
                for (int j = 0; j < 4; j++) acc[mt][nt][j] = 0.0f;

#pragma unroll
        for (int kt = 0; kt < 8; kt++) {
            unsigned af[2][4], bfr[8][2];
#pragma unroll
            for (int mt = 0; mt < 2; mt++)
                ldsm4(af[mt][0], af[mt][1], af[mt][2], af[mt][3],
                      aBase + aoff[mt] + kt*32);
#pragma unroll
            for (int ntp = 0; ntp < 4; ntp++) {
                unsigned r0, r1, r2, r3;
                ldsm4(r0, r1, r2, r3, bB + boff[ntp] + kt*32);
                bfr[2*ntp][0] = r0;   bfr[2*ntp][1] = r1;
                bfr[2*ntp+1][0] = r2; bfr[2*ntp+1][1] = r3;
            }
#pragma unroll
            for (int mt = 0; mt < 2; mt++)
#pragma unroll
                for (int nt = 0; nt < 8; nt++)
                    mma_bf16(acc[mt][nt], af[mt], bfr[nt]);
        }

        const int col0 = bc*128 + wn*64;
#pragma unroll
        for (int mt = 0; mt < 2; mt++) {
            int rr = row0 + mt*16 + (lane >> 2);
#pragma unroll
            for (int nt = 0; nt < 8; nt++) {
                int c = col0 + nt*8 + (lane & 3)*2;
                float bb0 = b2[c], bb1 = b2[c + 1];
                __nv_bfloat162 v0 = __floats2bfloat162_rn(
                    fmaxf(acc[mt][nt][0] + bb0, 0.0f), fmaxf(acc[mt][nt][1] + bb1, 0.0f));
                __nv_bfloat162 v1 = __floats2bfloat162_rn(
                    fmaxf(acc[mt][nt][2] + bb0, 0.0f), fmaxf(acc[mt][nt][3] + bb1, 0.0f));
                *(__nv_bfloat162*)(g_h2b + (size_t)rr*256 + c)       = v0;
                *(__nv_bfloat162*)(g_h2b + (size_t)(rr + 8)*256 + c) = v1;
            }
        }

        if (bc == 0) {
            asm volatile("cp.async.wait_group 0;");
            __syncthreads();   // B1 ready for all warps
        }
    }
}

// ---------------------------------------------------------------------------
// encL3 specialized: A (128x256) resident in smem, loop over 2 N-blocks of 128
// ---------------------------------------------------------------------------
#define SROW 40
#define STAGE_B (128*SROW*2)
#define SRA  264
#define ENC3_SMEM (128*SRA*2 + 2*128*SROW*2)   // 88064

__global__ void __launch_bounds__(256) encl3_kernel(const float* __restrict__ bias)
{
    extern __shared__ __align__(16) bf16 dyn3[];
    bf16* As = dyn3;                  // 128 x 264 (K=256 resident)
    bf16* Bs = dyn3 + 128*SRA;        // 2 x 128 x 40
    __shared__ unsigned cmax[128];

    const int tid = threadIdx.x, lane = tid & 31, wid = tid >> 5;
    const int wm = wid & 3, wn = wid >> 2;
    const int bx = blockIdx.x, by = blockIdx.y;

    const bf16* A = g_h2b + (size_t)(by * 128) * 256;
    const unsigned aBase = (unsigned)__cvta_generic_to_shared(As);
    const unsigned bBase = (unsigned)__cvta_generic_to_shared(Bs);

#pragma unroll
    for (int i = 0; i < 16; i++) {
        int c = i * 256 + tid;
        int row = c >> 5, seg = c & 31;
        cpa16(aBase + (row*SRA + seg*8)*2, A + (size_t)row*256 + seg*8);
    }
    asm volatile("cp.async.commit_group;");

    unsigned aoff[2], boff[4];
#pragma unroll
    for (int mt = 0; mt < 2; mt++)
        aoff[mt] = ((wm*32 + mt*16 + (lane & 15)) * SRA + ((lane >> 4) << 3)) * 2;
#pragma unroll
    for (int ntp = 0; ntp < 4; ntp++)
        boff[ntp] = ((wn*64 + ntp*16 + ((lane & 16) >> 1) + (lane & 7)) * SROW
                     + (lane & 8)) * 2;

    const int batch = (by * 128) / NPTS;

    for (int nb = 0; nb < 2; nb++) {
        const bf16* B = g_w3t + (size_t)(bx*256 + nb*128) * 256;

        auto loadB = [&](int s, int k0) {
#pragma unroll
            for (int i = 0; i < 2; i++) {
                int c = tid + (i << 8);
                int rr = c >> 2, sg = c & 3;
                cpa16(bBase + s*STAGE_B + (rr*SROW + sg*8)*2,
                      B + (size_t)rr*256 + k0 + sg*8);
            }
            asm volatile("cp.async.commit_group;");
        };

        float acc[2][8][4];
#pragma unroll
        for (int mt = 0; mt < 2; mt++)
#pragma unroll
            for (int nt = 0; nt < 8; nt++)
#pragma unroll
                for (int j = 0; j < 4; j++) acc[mt][nt][j] = 0.0f;

        loadB(0, 0);
        for (int kt = 0; kt < 8; kt++) {
            int s = kt & 1;
            if (kt + 1 < 8) {
                loadB(s ^ 1, (kt + 1) << 5);
                asm volatile("cp.async.wait_group 1;");
            } else {
                asm volatile("cp.async.wait_group 0;");
            }
            __syncthreads();
            unsigned sOff = s * STAGE_B;
#pragma unroll
            for (int ks = 0; ks < 2; ks++) {
                unsigned af[2][4], bfr[8][2];
#pragma unroll
                for (int mt = 0; mt < 2; mt++)
                    ldsm4(af[mt][0], af[mt][1], af[mt][2], af[mt][3],
                          aBase + aoff[mt] + kt*64 + ks*32);
#pragma unroll
                for (int ntp = 0; ntp < 4; ntp++) {
                    unsigned r0, r1, r2, r3;
                    ldsm4(r0, r1, r2, r3, bBase + sOff + boff[ntp] + ks*32);
                    bfr[2*ntp][0] = r0;   bfr[2*ntp][1] = r1;
                    bfr[2*ntp+1][0] = r2; bfr[2*ntp+1][1] = r3;
                }
#pragma unroll
                for (int mt = 0; mt < 2; mt++)
#pragma unroll
                    for (int nt = 0; nt < 8; nt++)
                        mma_bf16(acc[mt][nt], af[mt], bfr[nt]);
            }
            __syncthreads();
        }

        if (tid < 128) cmax[tid] = 0u;
        __syncthreads();
        const int colbase = bx*256 + nb*128;
#pragma unroll
        for (int nt = 0; nt < 8; nt++) {
            int cc = wn*64 + nt*8 + (lane & 3)*2;
            float b0 = bias[colbase + cc];
            float b1 = bias[colbase + cc + 1];
            float m0 = fmaxf(fmaxf(acc[0][nt][0], acc[0][nt][2]),
                             fmaxf(acc[1][nt][0], acc[1][nt][2])) + b0;
            float m1 = fmaxf(fmaxf(acc[0][nt][1], acc[0][nt][3]),
                             fmaxf(acc[1][nt][1], acc[1][nt][3])) + b1;
#pragma unroll
            for (int o = 4; o < 32; o <<= 1) {
                m0 = fmaxf(m0, __shfl_xor_sync(0xffffffffu, m0, o));
                m1 = fmaxf(m1, __shfl_xor_sync(0xffffffffu, m1, o));
            }
            if (lane < 4) {
                atomicMax(&cmax[cc],     fkey(m0));
                atomicMax(&cmax[cc + 1], fkey(m1));
            }
        }
        __syncthreads();
        if (tid < 128)
            atomicMax(&g_featkeys[(size_t)batch*1024 + colbase + tid], cmax[tid]);
        __syncthreads();
    }
}

// ---------------------------------------------------------------------------
// BF16 mma GEMM, EPI 0 = fp32 store + optional bias (feA GEMMs)
// ---------------------------------------------------------------------------
template<int EPI>
__global__ void __launch_bounds__(256) mma_gemm(
    int aid, int bid, const float* __restrict__ bias, int cid,
    int N, int K, int rows_per_batch)
{
    __shared__ __align__(16) bf16 As[2][128*SROW];
    __shared__ __align__(16) bf16 Bs[2][128*SROW];

    const bf16* A = scratch_bf16(aid) + (size_t)(blockIdx.y * 128) * K;
    const bf16* B = scratch_bf16(bid) + (size_t)(blockIdx.x * 128) * K;

    const int tid  = threadIdx.x;
    const int lane = tid & 31, wid = tid >> 5;
    const int wm = wid & 3, wn = wid >> 2;

    float acc[2][8][4];
#pragma unroll
    for (int mt = 0; mt < 2; mt++)
#pragma unroll
        for (int nt = 0; nt < 8; nt++)
#pragma unroll
            for (int j = 0; j < 4; j++) acc[mt][nt][j] = 0.0f;

    const unsigned aBase = (unsigned)__cvta_generic_to_shared(&As[0][0]);
    const unsigned bBase = (unsigned)__cvta_generic_to_shared(&Bs[0][0]);

    unsigned aoff[2], boff[4];
#pragma unroll
    for (int mt = 0; mt < 2; mt++)
        aoff[mt] = ((wm*32 + mt*16 + (lane & 15)) * SROW + ((lane >> 4) << 3)) * 2;
#pragma unroll
    for (int ntp = 0; ntp < 4; ntp++)
        boff[ntp] = ((wn*64 + ntp*16 + ((lane & 16) >> 1) + (lane & 7)) * SROW
                     + (lane & 8)) * 2;

    auto load_tile = [&](int s, int k0) {
#pragma unroll
        for (int i = 0; i < 2; i++) {
            int c = tid + (i << 8);
            int row = c >> 2, seg = c & 3;
            unsigned d = row * SROW + seg * 8;
            cpa16(aBase + s*STAGE_B + d*2, A + (size_t)row*K + k0 + seg*8);
            cpa16(bBase + s*STAGE_B + d*2, B + (size_t)row*K + k0 + seg*8);
        }
        asm volatile("cp.async.commit_group;");
    };

    load_tile(0, 0);
    const int KT = K >> 5;
    for (int kt = 0; kt < KT; kt++) {
        if (kt + 1 < KT) {
            load_tile((kt + 1) & 1, (kt + 1) << 5);
            asm volatile("cp.async.wait_group 1;");
        } else {
            asm volatile("cp.async.wait_group 0;");
        }
        __syncthreads();
        unsigned sOff = (kt & 1) * STAGE_B;
#pragma unroll
        for (int ks = 0; ks < 2; ks++) {
            unsigned af[2][4], bfr[8][2];
#pragma unroll
            for (int mt = 0; mt < 2; mt++)
                ldsm4(af[mt][0], af[mt][1], af[mt][2], af[mt][3],
                      aBase + sOff + aoff[mt] + ks*32);
#pragma unroll
            for (int ntp = 0; ntp < 4; ntp++) {
                unsigned r0, r1, r2, r3;
                ldsm4(r0, r1, r2, r3, bBase + sOff + boff[ntp] + ks*32);
                bfr[2*ntp][0] = r0;   bfr[2*ntp][1] = r1;
                bfr[2*ntp+1][0] = r2; bfr[2*ntp+1][1] = r3;
            }
#pragma unroll
            for (int mt = 0; mt < 2; mt++)
#pragma unroll
                for (int nt = 0; nt < 8; nt++)
                    mma_bf16(acc[mt][nt], af[mt], bfr[nt]);
        }
        __syncthreads();
    }

    const int row0  = blockIdx.y * 128 + wm * 32;
    const int col0g = blockIdx.x * 128 + wn * 64;

    float* C = scratch_f32(cid);
#pragma unroll
    for (int mt = 0; mt < 2; mt++) {
        int r = row0 + mt*16 + (lane >> 2);
#pragma unroll
        for (int nt = 0; nt < 8; nt++) {
            int c = col0g + nt*8 + (lane & 3)*2;
            float bb0 = bias ? bias[c]     : 0.0f;
            float bb1 = bias ? bias[c + 1] : 0.0f;
            float2 v0 = {acc[mt][nt][0] + bb0, acc[mt][nt][1] + bb1};
            float2 v1 = {acc[mt][nt][2] + bb0, acc[mt][nt][3] + bb1};
            *(float2*)(C + (size_t)r*N + c)       = v0;
            *(float2*)(C + (size_t)(r + 8)*N + c) = v1;
        }
    }
    (void)rows_per_batch;
}

// ---------------------------------------------------------------------------
// Fused fold GEMM (foldpre in A-fill, W2 GEMM, W3 projection epilogue)
// ---------------------------------------------------------------------------
__global__ void __launch_bounds__(256) fold_gemm_fused(
    int feaid, int stage, const float* __restrict__ w1, int bidW,
    const float* __restrict__ b2, const float* __restrict__ W3,
    const float* __restrict__ b3, int outid)
{
    __shared__ __align__(16) bf16 As[2][128*SROW];
    __shared__ __align__(16) bf16 Bs[2][128*SROW];
    __shared__ bf16  w1xs[512], w1ys[512], w1zs[512];
    __shared__ float l0s[128], l1s[128], l2s[128];
    __shared__ float w3s[128*3];
    __shared__ float b2s[128];

    const int K = 512;
    const float* feA = scratch_f32(feaid);
    const bf16* B = scratch_bf16(bidW) + (size_t)(blockIdx.x * 128) * K;

    const int tid  = threadIdx.x;
    const int lane = tid & 31, wid = tid >> 5;
    const int wm = wid & 3, wn = wid >> 2;

    if (tid < 128) {
        int cg = blockIdx.x*128 + tid;
        w3s[tid*3+0] = W3[cg*3+0];
        w3s[tid*3+1] = W3[cg*3+1];
        w3s[tid*3+2] = W3[cg*3+2];
        b2s[tid] = b2[cg];
        int gr = blockIdx.y*128 + tid;
        if (stage == 1) {
            int bg = gr / 36;
            int g = gr - bg * 36;
            l0s[tid] = c_lin[g / 6];
            l1s[tid] = c_lin[g % 6];
            l2s[tid] = 0.0f;
        } else {
            l0s[tid] = g_fold1[gr*3+0];
            l1s[tid] = g_fold1[gr*3+1];
            l2s[tid] = g_fold1[gr*3+2];
        }
    }
    for (int i = tid; i < 512; i += 256) {
        w1xs[i] = __float2bfloat16(w1[1024*512 + i]);
        w1ys[i] = __float2bfloat16(w1[1025*512 + i]);
        w1zs[i] = (stage == 2) ? __float2bfloat16(w1[1026*512 + i])
                               : __float2bfloat16(0.0f);
    }

    const unsigned aBase = (unsigned)__cvta_generic_to_shared(&As[0][0]);
    const unsigned bBase = (unsigned)__cvta_generic_to_shared(&Bs[0][0]);

    const int fr  = tid >> 1;
    const int fkk = (tid & 1) << 4;
    const int fbg = (blockIdx.y*128 + fr) / 36;
    const float* faRow = feA + (size_t)fbg * 512;

    auto fillA = [&](int s, int k0) {
        float l0 = l0s[fr], l1 = l1s[fr], l2 = l2s[fr];
        const float4* fa = (const float4*)(faRow + k0 + fkk);
        unsigned pk[8];
#pragma unroll
        for (int q = 0; q < 4; q++) {
            float4 f = fa[q];
            int kb = k0 + fkk + q*4;
            float v0 = fmaf(l2, __bfloat162float(w1zs[kb+0]),
                       fmaf(l1, __bfloat162float(w1ys[kb+0]),
                       fmaf(l0, __bfloat162float(w1xs[kb+0]), f.x)));
            float v1 = fmaf(l2, __bfloat162float(w1zs[kb+1]),
                       fmaf(l1, __bfloat162float(w1ys[kb+1]),
                       fmaf(l0, __bfloat162float(w1xs[kb+1]), f.y)));
            float v2 = fmaf(l2, __bfloat162float(w1zs[kb+2]),
                       fmaf(l1, __bfloat162float(w1ys[kb+2]),
                       fmaf(l0, __bfloat162float(w1xs[kb+2]), f.z)));
            float v3 = fmaf(l2, __bfloat162float(w1zs[kb+3]),
                       fmaf(l1, __bfloat162float(w1ys[kb+3]),
                       fmaf(l0, __bfloat162float(w1xs[kb+3]), f.w)));
            __nv_bfloat162 p0 = __floats2bfloat162_rn(fmaxf(v0, 0.0f), fmaxf(v1, 0.0f));
            __nv_bfloat162 p1 = __floats2bfloat162_rn(fmaxf(v2, 0.0f), fmaxf(v3, 0.0f));
            pk[q*2+0] = *(unsigned*)&p0;
            pk[q*2+1] = *(unsigned*)&p1;
        }
        uint4* dst = (uint4*)&As[s][fr*SROW + fkk];
        dst[0] = make_uint4(pk[0], pk[1], pk[2], pk[3]);
        dst[1] = make_uint4(pk[4], pk[5], pk[6], pk[7]);
    };

    auto loadB = [&](int s, int k0) {
#pragma unroll
        for (int i = 0; i < 2; i++) {
            int c = tid + (i << 8);
            int rr = c >> 2, sg = c & 3;
            cpa16(bBase + s*STAGE_B + (rr*SROW + sg*8)*2, B + (size_t)rr*K + k0 + sg*8);
        }
        asm volatile("cp.async.commit_group;");
    };

    float acc[2][8][4];
#pragma unroll
    for (int mt = 0; mt < 2; mt++)
#pragma unroll
        for (int nt = 0; nt < 8; nt++)
#pragma unroll
            for (int j = 0; j < 4; j++) acc[mt][nt][j] = 0.0f;

    unsigned aoff[2], boff[4];
#pragma unroll
    for (int mt = 0; mt < 2; mt++)
        aoff[mt] = ((wm*32 + mt*16 + (lane & 15)) * SROW + ((lane >> 4) << 3)) * 2;
#pragma unroll
    for (int ntp = 0; ntp < 4; ntp++)
        boff[ntp] = ((wn*64 + ntp*16 + ((lane & 16) >> 1) + (lane & 7)) * SROW
                     + (lane & 8)) * 2;

    loadB(0, 0);
    __syncthreads();
    fillA(0, 0);

    const int KT = K >> 5;
    for (int kt = 0; kt < KT; kt++) {
        int s = kt & 1;
        if (kt + 1 < KT) {
            loadB(s ^ 1, (kt + 1) << 5);
            asm volatile("cp.async.wait_group 1;");
        } else {
            asm volatile("cp.async.wait_group 0;");
        }
        __syncthreads();
        if (kt + 1 < KT) fillA(s ^ 1, (kt + 1) << 5);
        unsigned sOff = s * STAGE_B;
#pragma unroll
        for (int ks = 0; ks < 2; ks++) {
            unsigned af[2][4], bfr[8][2];
#pragma unroll
            for (int mt = 0; mt < 2; mt++)
                ldsm4(af[mt][0], af[mt][1], af[mt][2], af[mt][3],
                      aBase + sOff + aoff[mt] + ks*32);
#pragma unroll
            for (int ntp = 0; ntp < 4; ntp++) {
                unsigned r0, r1, r2, r3;
                ldsm4(r0, r1, r2, r3, bBase + sOff + boff[ntp] + ks*32);
                bfr[2*ntp][0] = r0;   bfr[2*ntp][1] = r1;
                bfr[2*ntp+1][0] = r2; bfr[2*ntp+1][1] = r3;
            }
#pragma unroll
            for (int mt = 0; mt < 2; mt++)
#pragma unroll
                for (int nt = 0; nt < 8; nt++)
                    mma_bf16(acc[mt][nt], af[mt], bfr[nt]);
        }
        __syncthreads();
    }

    float* out = scratch_f32(outid);
    const int row0 = blockIdx.y * 128 + wm * 32;
    float p[4][3];
#pragma unroll
    for (int i = 0; i < 4; i++)
#pragma unroll
        for (int c = 0; c < 3; c++) p[i][c] = 0.0f;

#pragma unroll
    for (int nt = 0; nt < 8; nt++) {
        int cc0 = wn*64 + nt*8 + (lane & 3)*2;
        int cc1 = cc0 + 1;
        float bb0 = b2s[cc0], bb1 = b2s[cc1];
        float h00 = fmaxf(acc[0][nt][0] + bb0, 0.0f);
        float h01 = fmaxf(acc[0][nt][1] + bb1, 0.0f);
        float h02 = fmaxf(acc[0][nt][2] + bb0, 0.0f);
        float h03 = fmaxf(acc[0][nt][3] + bb1, 0.0f);
        float h10 = fmaxf(acc[1][nt][0] + bb0, 0.0f);
        float h11 = fmaxf(acc[1][nt][1] + bb1, 0.0f);
        float h12 = fmaxf(acc[1][nt][2] + bb0, 0.0f);
        float h13 = fmaxf(acc[1][nt][3] + bb1, 0.0f);
#pragma unroll
        for (int c = 0; c < 3; c++) {
            float w0 = w3s[cc0*3 + c], w1v = w3s[cc1*3 + c];
            p[0][c] = fmaf(h00, w0, fmaf(h01, w1v, p[0][c]));
            p[1][c] = fmaf(h02, w0, fmaf(h03, w1v, p[1][c]));
            p[2][c] = fmaf(h10, w0, fmaf(h11, w1v, p[2][c]));
            p[3][c] = fmaf(h12, w0, fmaf(h13, w1v, p[3][c]));
        }
    }
#pragma unroll
    for (int o = 1; o <= 2; o <<= 1)
#pragma unroll
        for (int i = 0; i < 4; i++)
#pragma unroll
            for (int c = 0; c < 3; c++)
                p[i][c] += __shfl_xor_sync(0xffffffffu, p[i][c], o);

    if ((lane & 3) == 0) {
        bool addb3 = (blockIdx.x == 0) && (wn == 0);
#pragma unroll
        for (int i = 0; i < 4; i++) {
            int r = row0 + (i >> 1)*16 + (lane >> 2) + (i & 1)*8;
#pragma unroll
            for (int c = 0; c < 3; c++) {
                float v = p[i][c];
                if (addb3) v += b3[c];
                atomicAdd(&out[r*3 + c], v);
            }
        }
    }
}

// ---------------------------------------------------------------------------
// Small per-row MLP
// ---------------------------------------------------------------------------
__global__ void mlp_row_kernel(int xid, int xkeys, const float* __restrict__ W,
                               const float* __restrict__ bias, int yid,
                               int K, int N, int act)
{
    __shared__ float sx[1024];
    float* Y = scratch_f32(yid);
    int b = blockIdx.y;
    int col = blockIdx.x * blockDim.x + threadIdx.x;
    if (xkeys) {
        for (int k = threadIdx.x; k < K; k += blockDim.x)
            sx[k] = unfkey(g_featkeys[b*K + k]);
    } else {
        const float* X = scratch_f32(xid);
        for (int k = threadIdx.x; k < K; k += blockDim.x) sx[k] = X[b*K + k];
    }
    __syncthreads();
    float s0 = 0.0f, s1 = 0.0f, s2 = 0.0f, s3 = 0.0f;
    for (int k = 0; k < K; k += 4) {
        s0 = fmaf(sx[k+0], W[(size_t)(k+0)*N + col], s0);
        s1 = fmaf(sx[k+1], W[(size_t)(k+1)*N + col], s1);
        s2 = fmaf(sx[k+2], W[(size_t)(k+2)*N + col], s2);
        s3 = fmaf(sx[k+3], W[(size_t)(k+3)*N + col], s3);
    }
    float s = ((s0 + s1) + (s2 + s3)) + bias[col];
    if (act) s = fmaxf(s, 0.0f);
    Y[b*N + col] = s;
}

// ---------------------------------------------------------------------------
// pos + fe (bf16), 512 threads: 2 columns per thread
// ---------------------------------------------------------------------------
__global__ void __launch_bounds__(512) posfe_kernel(
    const float* __restrict__ w1, const float* __restrict__ b1,
    const float* __restrict__ w2, const float* __restrict__ b2)
{
    int bg = blockIdx.x, t = threadIdx.x, b = bg >> 6;
    __shared__ float h[128];
    float cx = g_centers[bg*3], cy = g_centers[bg*3+1], cz = g_centers[bg*3+2];
    if (t < 128) {
        float v = cx*w1[t] + cy*w1[128+t] + cz*w1[256+t] + b1[t];
        h[t] = gelu_exact(v);
    }
    __syncthreads();
    for (int q = 0; q < 2; q++) {
        int j = (q << 9) + t;
        float s = 0.0f;
#pragma unroll 8
        for (int k = 0; k < 128; k++) s = fmaf(h[k], w2[k*1024 + j], s);
        float feat = unfkey(g_featkeys[b*1024 + j]);
        g_feb[bg*1024 + j] = __float2bfloat16(s + b2[j] + feat);
    }
}

// ---------------------------------------------------------------------------
// Chamfer fine
// ---------------------------------------------------------------------------
__global__ void chamfer_fine_kernel() {
    int bg = blockIdx.x, t = threadIdx.x;  // 128 threads
    __shared__ float F[108], Nn[96], rm[36], cm[32];
    for (int i = t; i < 108; i += 128) F[i] = g_fold2[bg*108 + i];
    for (int i = t; i < 96;  i += 128) Nn[i] = g_neigh[bg*96 + i];
    __syncthreads();
    if (t < 36) {
        float fx = F[t*3], fy = F[t*3+1], fz = F[t*3+2], mn = FLT_MAX;
        for (int j = 0; j < 32; j++) {
            float dx = fx-Nn[j*3], dy = fy-Nn[j*3+1], dz = fz-Nn[j*3+2];
            mn = fminf(mn, dx*dx + dy*dy + dz*dz);
        }
        rm[t] = mn;
    } else if (t < 68) {
        int j = t - 36;
        float nx = Nn[j*3], ny = Nn[j*3+1], nz = Nn[j*3+2], mn = FLT_MAX;
        for (int i = 0; i < 36; i++) {
            float dx = F[i*3]-nx, dy = F[i*3+1]-ny, dz = F[i*3+2]-nz;
            mn = fminf(mn, dx*dx + dy*dy + dz*dz);
        }
        cm[j] = mn;
    }
    __syncthreads();
    if (t == 0) {
        float s = 0.0f;
        for (int i = 0; i < 36; i++) s += rm[i];
        atomicAdd(&g_acc[0], s);
        s = 0.0f;
        for (int j = 0; j < 32; j++) s += cm[j];
        atomicAdd(&g_acc[1], s);
    }
}

// ---------------------------------------------------------------------------
// Chamfer coarse
// ---------------------------------------------------------------------------
__global__ void __launch_bounds__(512) chamfer_coarse_kernel() {
    int t = threadIdx.x;
    __shared__ float C[1536], Ce[1536], s1[512], s2[512];
    for (int i = t; i < 1536; i += 512) { C[i] = g_coarse[i]; Ce[i] = g_centers[i]; }
    __syncthreads();
    int b = t >> 6, i = t & 63;
    const float* cb = &C[b*192];
    const float* eb = &Ce[b*192];
    float x = cb[i*3], y = cb[i*3+1], z = cb[i*3+2], mn = FLT_MAX;
    for (int j = 0; j < 64; j++) {
        float dx = x-eb[j*3], dy = y-eb[j*3+1], dz = z-eb[j*3+2];
        mn = fminf(mn, dx*dx + dy*dy + dz*dz);
    }
    s1[t] = mn;
    float x2 = eb[i*3], y2 = eb[i*3+1], z2 = eb[i*3+2];
    mn = FLT_MAX;
    for (int j = 0; j < 64; j++) {
        float dx = x2-cb[j*3], dy = y2-cb[j*3+1], dz = z2-cb[j*3+2];
        mn = fminf(mn, dx*dx + dy*dy + dz*dz);
    }
    s2[t] = mn;
    __syncthreads();
    for (int s = 256; s; s >>= 1) {
        if (t < s) { s1[t] += s1[t+s]; s2[t] += s2[t+s]; }
        __syncthreads();
    }
    if (t == 0) { g_acc[2] = s1[0]; g_acc[3] = s2[0]; }
}

__global__ void finalize_kernel(float* __restrict__ out) {
    out[0] = g_acc[0] / (float)(FROWS) + g_acc[1] / (float)(BGROUPS*GS);
    out[1] = g_acc[2] / 512.0f + g_acc[3] / 512.0f;
}

// ---------------------------------------------------------------------------
// launch — multi-stream DAG
// ---------------------------------------------------------------------------
extern "C" void kernel_launch(void* const* d_in, const int* in_sizes, int n_in,
                              void* d_out, int out_size)
{
    (void)in_sizes; (void)n_in; (void)out_size;
    const float* corrupted = (const float*)d_in[0];
    const float* pts       = (const float*)d_in[1];
    const float* enc_w1 = (const float*)d_in[2];
    const float* enc_b1 = (const float*)d_in[3];
    const float* enc_w2 = (const float*)d_in[4];
    const float* enc_b2 = (const float*)d_in[5];
    const float* enc_w3 = (const float*)d_in[6];
    const float* enc_b3 = (const float*)d_in[7];
    const float* pe_w1  = (const float*)d_in[8];
    const float* pe_b1  = (const float*)d_in[9];
    const float* pe_w2  = (const float*)d_in[10];
    const float* pe_b2  = (const float*)d_in[11];
    const float* cp_w1  = (const float*)d_in[12];
    const float* cp_b1  = (const float*)d_in[13];
    const float* cp_w2  = (const float*)d_in[14];
    const float* cp_b2  = (const float*)d_in[15];
    const float* cp_w3  = (const float*)d_in[16];
    const float* cp_b3  = (const float*)d_in[17];
    const float* f1_w1  = (const float*)d_in[18];
    const float* f1_b1  = (const float*)d_in[19];
    const float* f1_w2  = (const float*)d_in[20];
    const float* f1_b2  = (const float*)d_in[21];
    const float* f1_w3  = (const float*)d_in[22];
    const float* f1_b3  = (const float*)d_in[23];
    const float* f2_w1  = (const float*)d_in[24];
    const float* f2_b1  = (const float*)d_in[25];
    const float* f2_w2  = (const float*)d_in[26];
    const float* f2_b2  = (const float*)d_in[27];
    const float* f2_w3  = (const float*)d_in[28];
    const float* f2_b3  = (const float*)d_in[29];
    float* out = (float*)d_out;

    // one-time host resources (no device memory involved)
    static cudaStream_t sB = nullptr, sC = nullptr;
    static cudaEvent_t eFork, eGeo, eEnc, ePos, eFeA2, eCoarse, eWf, eW3;
    if (sB == nullptr) {
        cudaStreamCreateWithFlags(&sB, cudaStreamNonBlocking);
        cudaStreamCreateWithFlags(&sC, cudaStreamNonBlocking);
        cudaEventCreateWithFlags(&eFork,   cudaEventDisableTiming);
        cudaEventCreateWithFlags(&eGeo,    cudaEventDisableTiming);
        cudaEventCreateWithFlags(&eEnc,    cudaEventDisableTiming);
        cudaEventCreateWithFlags(&ePos,    cudaEventDisableTiming);
        cudaEventCreateWithFlags(&eFeA2,   cudaEventDisableTiming);
        cudaEventCreateWithFlags(&eCoarse, cudaEventDisableTiming);
        cudaEventCreateWithFlags(&eWf,     cudaEventDisableTiming);
        cudaEventCreateWithFlags(&eW3,     cudaEventDisableTiming);
        cudaFuncSetAttribute(enc12_kernel,
                             cudaFuncAttributeMaxDynamicSharedMemorySize, ENC12_SMEM);
        cudaFuncSetAttribute(encl3_kernel,
                             cudaFuncAttributeMaxDynamicSharedMemorySize, ENC3_SMEM);
    }

    // #0 main: minimal init
    zero_main_kernel<<<32, 256>>>();
    cudaEventRecord(eFork, 0);

    // #1 sC: w3 transpose (needed by encl3)
    cudaStreamWaitEvent(sC, eFork, 0);
    wtrans_one<<<1024, 256, 0, sC>>>(enc_w3, 256, 1024, BID_W3T);
    cudaEventRecord(eW3, sC);

    // #2 main: w2 transpose   #3 main: enc12
    wtrans_one<<<128, 256>>>(enc_w2, 128, 256, BID_W2T);
    enc12_kernel<<<dim3(1, 512), 256, ENC12_SMEM>>>(corrupted, enc_w1, enc_b1, enc_b2);

    // #4 sB: fps
    cudaStreamWaitEvent(sB, eFork, 0);
    fps_kernel<<<NB, 1024, 0, sB>>>(pts);

    // #5 main: encl3
    cudaStreamWaitEvent(0, eW3, 0);
    encl3_kernel<<<dim3(4, 512), 256, ENC3_SMEM>>>(enc_b3);
    cudaEventRecord(eEnc, 0);

    // #6 sB: knn
    knn_kernel<<<BGROUPS, 256, 0, sB>>>(pts);
    cudaEventRecord(eGeo, sB);

    // #7-8 sC: fold zero + fold transposes
    zero_fold_kernel<<<(FROWS*3 + 255)/256, 256, 0, sC>>>();
    wtrans_fold<<<dim3(2048, 4), 256, 0, sC>>>(f1_w1, f2_w1, f1_w2, f2_w2);
    cudaEventRecord(eWf, sC);

    // sC: coarse MLP chain + coarse chamfer
    cudaStreamWaitEvent(sC, eEnc, 0);
    mlp_row_kernel<<<dim3(8, NB), 128, 0, sC>>>(0, 1, cp_w1, cp_b1, FID_C1, 1024, 1024, 1);
    mlp_row_kernel<<<dim3(8, NB), 128, 0, sC>>>(FID_C1, 0, cp_w2, cp_b2, FID_C2, 1024, 1024, 1);
    mlp_row_kernel<<<dim3(1, NB), 192, 0, sC>>>(FID_C2, 0, cp_w3, cp_b3, FID_COARSE, 1024, 192, 0);
    cudaStreamWaitEvent(sC, eGeo, 0);
    chamfer_coarse_kernel<<<1, 512, 0, sC>>>();
    cudaEventRecord(eCoarse, sC);

    // main: posfe (centers + featkeys)
    cudaStreamWaitEvent(0, eGeo, 0);
    posfe_kernel<<<BGROUPS, 512>>>(pe_w1, pe_b1, pe_w2, pe_b2);
    cudaEventRecord(ePos, 0);

    // feA1 main (needs f1w1t), feA2 on stream B (needs f2w1t + fe)
    cudaStreamWaitEvent(0, eWf, 0);
    mma_gemm<0><<<dim3(4, 4), 256>>>(BID_FE, BID_F1W1T, f1_b1, FID_FEA1, 512, 1024, 0);
    cudaStreamWaitEvent(sB, ePos, 0);
    cudaStreamWaitEvent(sB, eWf, 0);
    mma_gemm<0><<<dim3(4, 4), 256, 0, sB>>>(BID_FE, BID_F2W1T, f2_b1, FID_FEA2, 512, 1024, 0);
    cudaEventRecord(eFeA2, sB);

    // fold stage 1 (fused foldpre + GEMM + W3 projection)
    fold_gemm_fused<<<dim3(4, 144), 256>>>(FID_FEA1, 1, f1_w1, BID_F1W2T,
                                           f1_b2, f1_w3, f1_b3, FID_FOLD1);

    // fold stage 2 (needs feA2 + fold1)
    cudaStreamWaitEvent(0, eFeA2, 0);
    fold_gemm_fused<<<dim3(4, 144), 256>>>(FID_FEA2, 2, f2_w1, BID_F2W2T,
                                           f2_b2, f2_w3, f2_b3, FID_FOLD2);

    // fine chamfer
    chamfer_fine_kernel<<<BGROUPS, 128>>>();

    // join coarse chain, finalize
    cudaStreamWaitEvent(0, eCoarse, 0);
    finalize_kernel<<<1, 1>>>(out);
}